// round 2
// baseline (speedup 1.0000x reference)
#include <cuda_runtime.h>
#include <math.h>

// Problem constants
#define NL 4
#define DM 512
#define NH 8
#define DH 64
#define FFD 2048
#define NB 256
#define NF 30
#define NS 32
#define NROWS (NB*NS)      // 8192
#define NFR   (NB*NF)      // 7680

// ------------------------- scratch (device globals, no allocs) -------------
__device__ float g_x[NROWS*DM];        // activations (residual stream)
__device__ float g_qkv[NROWS*3*DM];    // qkv projection
__device__ float g_attn[NROWS*DM];     // attention output (heads merged)
__device__ float g_proj[NROWS*DM];     // o-proj / ff2 output
__device__ float g_ff[NROWS*FFD];      // ff1 output
__device__ float g_tn[NB*DM];          // normalized text
__device__ float g_fn[NFR*DM];         // normalized frames
__device__ float g_vn[NROWS*DM];       // normalized video tokens
__device__ float g_cf[NB*NFR];         // text x frames dots  [256, 7680]
__device__ float g_cv[NB*NROWS];       // text x video dots   [256, 8192]

// ------------------------- build x = [frames; expansion] -------------------
__global__ void build_x_kernel(const float* __restrict__ fr,
                               const float* __restrict__ ex,
                               float* __restrict__ x) {
    int idx = blockIdx.x * 256 + threadIdx.x;       // over 8192*512
    int c = idx & (DM - 1);
    int row = idx >> 9;                              // /512
    int b = row >> 5;
    int s = row & 31;
    x[idx] = (s < NF) ? fr[(b*NF + s)*DM + c] : ex[(s - NF)*DM + c];
}

// ------------------------- SGEMM: C[M,N] = A[M,K] * B[N,K]^T (+bias)(relu) -
// 128x128 tile, BK=8, 256 threads, 8x8 per thread. M,N %128==0, K %8==0.
__global__ __launch_bounds__(256) void sgemm_nt(
    const float* __restrict__ A, const float* __restrict__ Bm,
    const float* __restrict__ bias, float* __restrict__ C,
    int M, int N, int K, int relu)
{
    __shared__ float As[8][128];
    __shared__ float Bs[8][128];
    const int bn = blockIdx.x * 128;
    const int bm = blockIdx.y * 128;
    const int tid = threadIdx.x;
    const int tr = tid >> 4;          // 0..15
    const int tc = tid & 15;          // 0..15
    const int ldRow = tid >> 1;       // 0..127
    const int ldCol = (tid & 1) << 2; // 0 or 4

    float acc[8][8];
#pragma unroll
    for (int i = 0; i < 8; i++)
#pragma unroll
        for (int j = 0; j < 8; j++) acc[i][j] = 0.f;

    const float* Aptr = A + (size_t)(bm + ldRow) * K + ldCol;
    const float* Bptr = Bm + (size_t)(bn + ldRow) * K + ldCol;

    for (int k0 = 0; k0 < K; k0 += 8) {
        float4 a4 = *reinterpret_cast<const float4*>(Aptr + k0);
        float4 b4 = *reinterpret_cast<const float4*>(Bptr + k0);
        As[ldCol + 0][ldRow] = a4.x;
        As[ldCol + 1][ldRow] = a4.y;
        As[ldCol + 2][ldRow] = a4.z;
        As[ldCol + 3][ldRow] = a4.w;
        Bs[ldCol + 0][ldRow] = b4.x;
        Bs[ldCol + 1][ldRow] = b4.y;
        Bs[ldCol + 2][ldRow] = b4.z;
        Bs[ldCol + 3][ldRow] = b4.w;
        __syncthreads();
#pragma unroll
        for (int k = 0; k < 8; k++) {
            float4 ra0 = *reinterpret_cast<const float4*>(&As[k][tr * 8]);
            float4 ra1 = *reinterpret_cast<const float4*>(&As[k][tr * 8 + 4]);
            float4 rb0 = *reinterpret_cast<const float4*>(&Bs[k][tc * 8]);
            float4 rb1 = *reinterpret_cast<const float4*>(&Bs[k][tc * 8 + 4]);
            float ra[8] = {ra0.x, ra0.y, ra0.z, ra0.w, ra1.x, ra1.y, ra1.z, ra1.w};
            float rb[8] = {rb0.x, rb0.y, rb0.z, rb0.w, rb1.x, rb1.y, rb1.z, rb1.w};
#pragma unroll
            for (int i = 0; i < 8; i++)
#pragma unroll
                for (int j = 0; j < 8; j++)
                    acc[i][j] += ra[i] * rb[j];
        }
        __syncthreads();
    }

#pragma unroll
    for (int i = 0; i < 8; i++) {
        int row = bm + tr * 8 + i;
        float* crow = C + (size_t)row * N + bn + tc * 8;
#pragma unroll
        for (int j = 0; j < 8; j += 4) {
            float4 v;
            v.x = acc[i][j + 0]; v.y = acc[i][j + 1];
            v.z = acc[i][j + 2]; v.w = acc[i][j + 3];
            if (bias) {
                int col = bn + tc * 8 + j;
                v.x += bias[col + 0]; v.y += bias[col + 1];
                v.z += bias[col + 2]; v.w += bias[col + 3];
            }
            if (relu) {
                v.x = fmaxf(v.x, 0.f); v.y = fmaxf(v.y, 0.f);
                v.z = fmaxf(v.z, 0.f); v.w = fmaxf(v.w, 0.f);
            }
            *reinterpret_cast<float4*>(crow + j) = v;
        }
    }
}

// ------------------------- attention: per (batch, head), S=32, dh=64 -------
__global__ __launch_bounds__(1024) void attn_kernel(const float* __restrict__ qkv,
                                                    float* __restrict__ outp) {
    const int b = blockIdx.x;
    const int h = blockIdx.y;
    __shared__ float sq[32][65];
    __shared__ float sk[32][65];
    __shared__ float sv[32][65];
    __shared__ float sp[32][33];
    const int tx = threadIdx.x;   // 0..31
    const int ty = threadIdx.y;   // 0..31  (one warp per ty row)

    const float* base = qkv + (size_t)(b * NS + ty) * (3 * DM) + h * DH;
    sq[ty][tx]      = base[tx];
    sq[ty][tx + 32] = base[tx + 32];
    sk[ty][tx]      = base[DM + tx];
    sk[ty][tx + 32] = base[DM + tx + 32];
    sv[ty][tx]      = base[2 * DM + tx];
    sv[ty][tx + 32] = base[2 * DM + tx + 32];
    __syncthreads();

    float acc = 0.f;
#pragma unroll
    for (int d = 0; d < DH; d++) acc += sq[ty][d] * sk[tx][d];
    acc *= 0.125f; // 1/sqrt(64)

    // softmax over tx (row ty = one warp)
    float m = acc;
#pragma unroll
    for (int o = 16; o; o >>= 1) m = fmaxf(m, __shfl_xor_sync(0xffffffffu, m, o));
    float e = __expf(acc - m);
    float s = e;
#pragma unroll
    for (int o = 16; o; o >>= 1) s += __shfl_xor_sync(0xffffffffu, s, o);
    sp[ty][tx] = e / s;
    __syncthreads();

    float o0 = 0.f, o1 = 0.f;
#pragma unroll
    for (int k = 0; k < NS; k++) {
        float p = sp[ty][k];
        o0 += p * sv[k][tx];
        o1 += p * sv[k][tx + 32];
    }
    float* ob = outp + (size_t)(b * NS + ty) * DM + h * DH;
    ob[tx] = o0;
    ob[tx + 32] = o1;
}

// ------------------------- block reduce (256 threads) ----------------------
__device__ __forceinline__ float block_reduce_256(float v, float* sh) {
    __syncthreads();  // protect sh reuse across consecutive calls
    int lane = threadIdx.x & 31, wid = threadIdx.x >> 5;
#pragma unroll
    for (int o = 16; o; o >>= 1) v += __shfl_xor_sync(0xffffffffu, v, o);
    if (lane == 0) sh[wid] = v;
    __syncthreads();
    if (threadIdx.x == 0) {
        float t = 0.f;
#pragma unroll
        for (int w = 0; w < 8; w++) t += sh[w];
        sh[8] = t;
    }
    __syncthreads();
    return sh[8];
}

// ------------------------- x = LayerNorm(x + o) * g + b --------------------
__global__ __launch_bounds__(256) void add_ln_kernel(float* __restrict__ x,
                                                     const float* __restrict__ o,
                                                     const float* __restrict__ g,
                                                     const float* __restrict__ bt) {
    __shared__ float red[16];
    const int row = blockIdx.x;
    const int t = threadIdx.x;
    float v0 = x[(size_t)row * DM + t]       + o[(size_t)row * DM + t];
    float v1 = x[(size_t)row * DM + 256 + t] + o[(size_t)row * DM + 256 + t];
    float mean = block_reduce_256(v0 + v1, red) * (1.f / DM);
    float d0 = v0 - mean, d1 = v1 - mean;
    float var = block_reduce_256(d0 * d0 + d1 * d1, red) * (1.f / DM);
    float r = rsqrtf(var + 1e-5f);
    x[(size_t)row * DM + t]       = d0 * r * g[t]       + bt[t];
    x[(size_t)row * DM + 256 + t] = d1 * r * g[256 + t] + bt[256 + t];
}

// ------------------------- row l2 normalize (rows of 512) ------------------
__global__ __launch_bounds__(256) void l2norm_kernel(const float* __restrict__ in,
                                                     float* __restrict__ out) {
    __shared__ float red[16];
    const int row = blockIdx.x;
    const int t = threadIdx.x;
    float v0 = in[(size_t)row * DM + t];
    float v1 = in[(size_t)row * DM + 256 + t];
    float ss = block_reduce_256(v0 * v0 + v1 * v1, red);
    float inv = 1.f / fmaxf(sqrtf(ss), 1e-12f);
    out[(size_t)row * DM + t]       = v0 * inv;
    out[(size_t)row * DM + 256 + t] = v1 * inv;
}

// ------------------------- MaxSim reduce + output --------------------------
__global__ void sim_out_kernel(const float* __restrict__ cf,
                               const float* __restrict__ cv,
                               float* __restrict__ out) {
    int p = blockIdx.x * 256 + threadIdx.x;  // 65536 pairs
    int i = p >> 8;     // query index
    int j = p & 255;    // video index
    const float* pf = cf + (size_t)i * NFR + j * NF;
    float mf = -1e30f;
#pragma unroll
    for (int f = 0; f < NF; f++) mf = fmaxf(mf, pf[f]);
    const float* pv = cv + (size_t)i * NROWS + j * NS;
    float mv = -1e30f;
#pragma unroll
    for (int v = 0; v < NS; v++) mv = fmaxf(mv, pv[v]);
    out[p]                 = mf + mv;
    out[NB * NB + p]       = mf;
    out[2 * NB * NB + p]   = mv;
}

// ------------------------- launcher ----------------------------------------
extern "C" void kernel_launch(void* const* d_in, const int* in_sizes, int n_in,
                              void* d_out, int out_size) {
    const float* text  = (const float*)d_in[0];
    const float* fr    = (const float*)d_in[1];
    const float* ex    = (const float*)d_in[2];
    const float* Wqkv  = (const float*)d_in[3];
    const float* bqkv  = (const float*)d_in[4];
    const float* Wo    = (const float*)d_in[5];
    const float* bo    = (const float*)d_in[6];
    const float* ln1w  = (const float*)d_in[7];
    const float* ln1b  = (const float*)d_in[8];
    const float* W1    = (const float*)d_in[9];
    const float* b1    = (const float*)d_in[10];
    const float* W2    = (const float*)d_in[11];
    const float* b2    = (const float*)d_in[12];
    const float* ln2w  = (const float*)d_in[13];
    const float* ln2b  = (const float*)d_in[14];
    float* out = (float*)d_out;

    float *px, *pqkv, *pattn, *pproj, *pff, *ptn, *pfn, *pvn, *pcf, *pcv;
    cudaGetSymbolAddress((void**)&px,    g_x);
    cudaGetSymbolAddress((void**)&pqkv,  g_qkv);
    cudaGetSymbolAddress((void**)&pattn, g_attn);
    cudaGetSymbolAddress((void**)&pproj, g_proj);
    cudaGetSymbolAddress((void**)&pff,   g_ff);
    cudaGetSymbolAddress((void**)&ptn,   g_tn);
    cudaGetSymbolAddress((void**)&pfn,   g_fn);
    cudaGetSymbolAddress((void**)&pvn,   g_vn);
    cudaGetSymbolAddress((void**)&pcf,   g_cf);
    cudaGetSymbolAddress((void**)&pcv,   g_cv);

    build_x_kernel<<<(NROWS * DM) / 256, 256>>>(fr, ex, px);

    for (int l = 0; l < NL; l++) {
        // QKV: [8192,512] x [1536,512]^T
        sgemm_nt<<<dim3(3 * DM / 128, NROWS / 128), 256>>>(
            px, Wqkv + (size_t)l * 3 * DM * DM, bqkv + (size_t)l * 3 * DM,
            pqkv, NROWS, 3 * DM, DM, 0);
        // attention per (batch, head)
        attn_kernel<<<dim3(NB, NH), dim3(32, 32)>>>(pqkv, pattn);
        // O projection
        sgemm_nt<<<dim3(DM / 128, NROWS / 128), 256>>>(
            pattn, Wo + (size_t)l * DM * DM, bo + (size_t)l * DM,
            pproj, NROWS, DM, DM, 0);
        add_ln_kernel<<<NROWS, 256>>>(px, pproj, ln1w + (size_t)l * DM, ln1b + (size_t)l * DM);
        // FF1 (+ReLU)
        sgemm_nt<<<dim3(FFD / 128, NROWS / 128), 256>>>(
            px, W1 + (size_t)l * FFD * DM, b1 + (size_t)l * FFD,
            pff, NROWS, FFD, DM, 1);
        // FF2
        sgemm_nt<<<dim3(DM / 128, NROWS / 128), 256>>>(
            pff, W2 + (size_t)l * DM * FFD, b2 + (size_t)l * DM,
            pproj, NROWS, DM, FFD, 0);
        add_ln_kernel<<<NROWS, 256>>>(px, pproj, ln2w + (size_t)l * DM, ln2b + (size_t)l * DM);
    }

    // normalizations
    l2norm_kernel<<<NB, 256>>>(text, ptn);
    l2norm_kernel<<<NFR, 256>>>(fr, pfn);
    l2norm_kernel<<<NROWS, 256>>>(px, pvn);

    // similarity dot-product GEMMs
    sgemm_nt<<<dim3(NFR / 128, NB / 128), 256>>>(ptn, pfn, nullptr, pcf, NB, NFR, DM, 0);
    sgemm_nt<<<dim3(NROWS / 128, NB / 128), 256>>>(ptn, pvn, nullptr, pcv, NB, NROWS, DM, 0);

    // MaxSim + write three output matrices
    sim_out_kernel<<<(NB * NB) / 256, 256>>>(pcf, pcv, out);
}

// round 4
// speedup vs baseline: 1.4508x; 1.4508x over previous
#include <cuda_runtime.h>
#include <math.h>

// Problem constants
#define NL 4
#define DM 512
#define NH 8
#define DH 64
#define FFD 2048
#define NB 256
#define NF 30
#define NS 32
#define NROWS (NB*NS)      // 8192
#define NFR   (NB*NF)      // 7680

// ------------------------- scratch (device globals, no allocs) -------------
__device__ float g_x[NROWS*DM];        // activations (residual stream)
__device__ float g_qkv[NROWS*3*DM];    // qkv projection
__device__ float g_attn[NROWS*DM];     // attention output (heads merged)
__device__ float g_proj[NROWS*DM];     // o-proj / ff2 output
__device__ float g_ff[NROWS*FFD];      // ff1 output
__device__ float g_tn[NB*DM];          // normalized text
__device__ float g_fn[NFR*DM];         // normalized frames
__device__ float g_vn[NROWS*DM];       // normalized video tokens
__device__ float g_cf[NB*NFR];         // text x frames dots  [256, 7680]
__device__ float g_cv[NB*NROWS];       // text x video dots   [256, 8192]

// ------------------------- build x = [frames; expansion] -------------------
__global__ void build_x_kernel(const float* __restrict__ fr,
                               const float* __restrict__ ex,
                               float* __restrict__ x) {
    int idx = blockIdx.x * 256 + threadIdx.x;       // over 8192*512
    int c = idx & (DM - 1);
    int row = idx >> 9;                              // /512
    int b = row >> 5;
    int s = row & 31;
    x[idx] = (s < NF) ? fr[(b*NF + s)*DM + c] : ex[(s - NF)*DM + c];
}

// ------------------------- 3xTF32 tensor-core GEMM -------------------------
// C[M,N] = A[M,K] * B[N,K]^T (+bias)(relu), fp32 in/out, near-fp32 accuracy
// via hi/lo tf32 split (hi*hi + hi*lo + lo*hi).
// Block tile 128x64, BK=32, 256 threads = 8 warps (4x2), warp tile 32x32.
// mma.sync.aligned.m16n8k8.row.col.f32.tf32.tf32.f32
#define BM 128
#define BN 64
#define BK 32
#define SPAD 36

__device__ __forceinline__ void split_tf32(float x, unsigned &hi, unsigned &lo) {
    asm("cvt.rna.tf32.f32 %0, %1;" : "=r"(hi) : "f"(x));
    float r = x - __uint_as_float(hi);
    asm("cvt.rna.tf32.f32 %0, %1;" : "=r"(lo) : "f"(r));
}

#define MMA_TF32(d, a, b) \
    asm volatile("mma.sync.aligned.m16n8k8.row.col.f32.tf32.tf32.f32 " \
                 "{%0,%1,%2,%3}, {%4,%5,%6,%7}, {%8,%9}, {%0,%1,%2,%3};" \
                 : "+f"(d[0]), "+f"(d[1]), "+f"(d[2]), "+f"(d[3]) \
                 : "r"(a[0]), "r"(a[1]), "r"(a[2]), "r"(a[3]), \
                   "r"(b[0]), "r"(b[1]))

__global__ __launch_bounds__(256, 2) void mma_nt(
    const float* __restrict__ A, const float* __restrict__ Bm,
    const float* __restrict__ bias, float* __restrict__ C,
    int M, int N, int K, int relu)
{
    __shared__ float As[BM * SPAD];
    __shared__ float Bs[BN * SPAD];
    const int bn = blockIdx.x * BN;
    const int bm = blockIdx.y * BM;
    const int tid = threadIdx.x;
    const int warp = tid >> 5;
    const int lane = tid & 31;
    const int g = lane >> 2;      // 0..7
    const int t = lane & 3;       // 0..3
    const int wm = (warp & 3) * 32;
    const int wn = (warp >> 2) * 32;

    const int lrow = tid >> 3;        // 0..31
    const int lk = (tid & 7) * 4;     // 0..28

    float acc[2][4][4];
#pragma unroll
    for (int mt = 0; mt < 2; mt++)
#pragma unroll
        for (int nt = 0; nt < 4; nt++)
#pragma unroll
            for (int i = 0; i < 4; i++) acc[mt][nt][i] = 0.f;

    float4 pa[4], pb[2];

    // load first tile
#pragma unroll
    for (int i = 0; i < 4; i++)
        pa[i] = *reinterpret_cast<const float4*>(A + (size_t)(bm + lrow + 32 * i) * K + lk);
#pragma unroll
    for (int i = 0; i < 2; i++)
        pb[i] = *reinterpret_cast<const float4*>(Bm + (size_t)(bn + lrow + 32 * i) * K + lk);
#pragma unroll
    for (int i = 0; i < 4; i++)
        *reinterpret_cast<float4*>(&As[(lrow + 32 * i) * SPAD + lk]) = pa[i];
#pragma unroll
    for (int i = 0; i < 2; i++)
        *reinterpret_cast<float4*>(&Bs[(lrow + 32 * i) * SPAD + lk]) = pb[i];
    __syncthreads();

    for (int k0 = 0; k0 < K; k0 += BK) {
        const bool more = (k0 + BK) < K;
        if (more) {
            const int kn = k0 + BK;
#pragma unroll
            for (int i = 0; i < 4; i++)
                pa[i] = *reinterpret_cast<const float4*>(A + (size_t)(bm + lrow + 32 * i) * K + kn + lk);
#pragma unroll
            for (int i = 0; i < 2; i++)
                pb[i] = *reinterpret_cast<const float4*>(Bm + (size_t)(bn + lrow + 32 * i) * K + kn + lk);
        }

#pragma unroll
        for (int kk = 0; kk < BK; kk += 8) {
            unsigned ahi[2][4], alo[2][4], bhi[4][2], blo[4][2];
#pragma unroll
            for (int mt = 0; mt < 2; mt++) {
                const int mrow = wm + mt * 16 + g;
                const float f0 = As[mrow * SPAD + kk + t];
                const float f1 = As[(mrow + 8) * SPAD + kk + t];
                const float f2 = As[mrow * SPAD + kk + t + 4];
                const float f3 = As[(mrow + 8) * SPAD + kk + t + 4];
                split_tf32(f0, ahi[mt][0], alo[mt][0]);
                split_tf32(f1, ahi[mt][1], alo[mt][1]);
                split_tf32(f2, ahi[mt][2], alo[mt][2]);
                split_tf32(f3, ahi[mt][3], alo[mt][3]);
            }
#pragma unroll
            for (int nt = 0; nt < 4; nt++) {
                const int nrow = wn + nt * 8 + g;
                const float f0 = Bs[nrow * SPAD + kk + t];
                const float f1 = Bs[nrow * SPAD + kk + t + 4];
                split_tf32(f0, bhi[nt][0], blo[nt][0]);
                split_tf32(f1, bhi[nt][1], blo[nt][1]);
            }
#pragma unroll
            for (int mt = 0; mt < 2; mt++)
#pragma unroll
                for (int nt = 0; nt < 4; nt++) {
                    MMA_TF32(acc[mt][nt], ahi[mt], bhi[nt]);
                    MMA_TF32(acc[mt][nt], alo[mt], bhi[nt]);
                    MMA_TF32(acc[mt][nt], ahi[mt], blo[nt]);
                }
        }

        if (more) {
            __syncthreads();
#pragma unroll
            for (int i = 0; i < 4; i++)
                *reinterpret_cast<float4*>(&As[(lrow + 32 * i) * SPAD + lk]) = pa[i];
#pragma unroll
            for (int i = 0; i < 2; i++)
                *reinterpret_cast<float4*>(&Bs[(lrow + 32 * i) * SPAD + lk]) = pb[i];
            __syncthreads();
        }
    }

    // epilogue
#pragma unroll
    for (int mt = 0; mt < 2; mt++) {
        const int r0 = bm + wm + mt * 16 + g;
#pragma unroll
        for (int nt = 0; nt < 4; nt++) {
            const int c = bn + wn + nt * 8 + 2 * t;
            float b0 = 0.f, b1 = 0.f;
            if (bias) { b0 = __ldg(bias + c); b1 = __ldg(bias + c + 1); }
            float v00 = acc[mt][nt][0] + b0;
            float v01 = acc[mt][nt][1] + b1;
            float v10 = acc[mt][nt][2] + b0;
            float v11 = acc[mt][nt][3] + b1;
            if (relu) {
                v00 = fmaxf(v00, 0.f); v01 = fmaxf(v01, 0.f);
                v10 = fmaxf(v10, 0.f); v11 = fmaxf(v11, 0.f);
            }
            float2 s0 = make_float2(v00, v01);
            float2 s1 = make_float2(v10, v11);
            *reinterpret_cast<float2*>(C + (size_t)r0 * N + c) = s0;
            *reinterpret_cast<float2*>(C + (size_t)(r0 + 8) * N + c) = s1;
        }
    }
}

// ------------------------- attention: per (batch, head), S=32, dh=64 -------
__global__ __launch_bounds__(1024) void attn_kernel(const float* __restrict__ qkv,
                                                    float* __restrict__ outp) {
    const int b = blockIdx.x;
    const int h = blockIdx.y;
    __shared__ float sq[32][65];
    __shared__ float sk[32][65];
    __shared__ float sv[32][65];
    __shared__ float sp[32][33];
    const int tx = threadIdx.x;   // 0..31
    const int ty = threadIdx.y;   // 0..31  (one warp per ty row)

    const float* base = qkv + (size_t)(b * NS + ty) * (3 * DM) + h * DH;
    sq[ty][tx]      = base[tx];
    sq[ty][tx + 32] = base[tx + 32];
    sk[ty][tx]      = base[DM + tx];
    sk[ty][tx + 32] = base[DM + tx + 32];
    sv[ty][tx]      = base[2 * DM + tx];
    sv[ty][tx + 32] = base[2 * DM + tx + 32];
    __syncthreads();

    float acc = 0.f;
#pragma unroll
    for (int d = 0; d < DH; d++) acc += sq[ty][d] * sk[tx][d];
    acc *= 0.125f; // 1/sqrt(64)

    // softmax over tx (row ty = one warp)
    float m = acc;
#pragma unroll
    for (int o = 16; o; o >>= 1) m = fmaxf(m, __shfl_xor_sync(0xffffffffu, m, o));
    float e = __expf(acc - m);
    float s = e;
#pragma unroll
    for (int o = 16; o; o >>= 1) s += __shfl_xor_sync(0xffffffffu, s, o);
    sp[ty][tx] = e / s;
    __syncthreads();

    float o0 = 0.f, o1 = 0.f;
#pragma unroll
    for (int k = 0; k < NS; k++) {
        float p = sp[ty][k];
        o0 += p * sv[k][tx];
        o1 += p * sv[k][tx + 32];
    }
    float* ob = outp + (size_t)(b * NS + ty) * DM + h * DH;
    ob[tx] = o0;
    ob[tx + 32] = o1;
}

// ------------------------- block reduce (256 threads) ----------------------
__device__ __forceinline__ float block_reduce_256(float v, float* sh) {
    __syncthreads();  // protect sh reuse across consecutive calls
    int lane = threadIdx.x & 31, wid = threadIdx.x >> 5;
#pragma unroll
    for (int o = 16; o; o >>= 1) v += __shfl_xor_sync(0xffffffffu, v, o);
    if (lane == 0) sh[wid] = v;
    __syncthreads();
    if (threadIdx.x == 0) {
        float t = 0.f;
#pragma unroll
        for (int w = 0; w < 8; w++) t += sh[w];
        sh[8] = t;
    }
    __syncthreads();
    return sh[8];
}

// ------------------------- x = LayerNorm(x + o) * g + b --------------------
__global__ __launch_bounds__(256) void add_ln_kernel(float* __restrict__ x,
                                                     const float* __restrict__ o,
                                                     const float* __restrict__ g,
                                                     const float* __restrict__ bt) {
    __shared__ float red[16];
    const int row = blockIdx.x;
    const int t = threadIdx.x;
    float v0 = x[(size_t)row * DM + t]       + o[(size_t)row * DM + t];
    float v1 = x[(size_t)row * DM + 256 + t] + o[(size_t)row * DM + 256 + t];
    float mean = block_reduce_256(v0 + v1, red) * (1.f / DM);
    float d0 = v0 - mean, d1 = v1 - mean;
    float var = block_reduce_256(d0 * d0 + d1 * d1, red) * (1.f / DM);
    float r = rsqrtf(var + 1e-5f);
    x[(size_t)row * DM + t]       = d0 * r * g[t]       + bt[t];
    x[(size_t)row * DM + 256 + t] = d1 * r * g[256 + t] + bt[256 + t];
}

// ------------------------- row l2 normalize (rows of 512) ------------------
__global__ __launch_bounds__(256) void l2norm_kernel(const float* __restrict__ in,
                                                     float* __restrict__ out) {
    __shared__ float red[16];
    const int row = blockIdx.x;
    const int t = threadIdx.x;
    float v0 = in[(size_t)row * DM + t];
    float v1 = in[(size_t)row * DM + 256 + t];
    float ss = block_reduce_256(v0 * v0 + v1 * v1, red);
    float inv = 1.f / fmaxf(sqrtf(ss), 1e-12f);
    out[(size_t)row * DM + t]       = v0 * inv;
    out[(size_t)row * DM + 256 + t] = v1 * inv;
}

// ------------------------- MaxSim reduce + output --------------------------
__global__ void sim_out_kernel(const float* __restrict__ cf,
                               const float* __restrict__ cv,
                               float* __restrict__ out) {
    int p = blockIdx.x * 256 + threadIdx.x;  // 65536 pairs
    int i = p >> 8;     // query index
    int j = p & 255;    // video index
    const float* pf = cf + (size_t)i * NFR + j * NF;
    float mf = -1e30f;
#pragma unroll
    for (int f = 0; f < NF; f++) mf = fmaxf(mf, pf[f]);
    const float* pv = cv + (size_t)i * NROWS + j * NS;
    float mv = -1e30f;
#pragma unroll
    for (int v = 0; v < NS; v++) mv = fmaxf(mv, pv[v]);
    out[p]                 = mf + mv;
    out[NB * NB + p]       = mf;
    out[2 * NB * NB + p]   = mv;
}

// ------------------------- launcher ----------------------------------------
extern "C" void kernel_launch(void* const* d_in, const int* in_sizes, int n_in,
                              void* d_out, int out_size) {
    const float* text  = (const float*)d_in[0];
    const float* fr    = (const float*)d_in[1];
    const float* ex    = (const float*)d_in[2];
    const float* Wqkv  = (const float*)d_in[3];
    const float* bqkv  = (const float*)d_in[4];
    const float* Wo    = (const float*)d_in[5];
    const float* bo    = (const float*)d_in[6];
    const float* ln1w  = (const float*)d_in[7];
    const float* ln1b  = (const float*)d_in[8];
    const float* W1    = (const float*)d_in[9];
    const float* b1    = (const float*)d_in[10];
    const float* W2    = (const float*)d_in[11];
    const float* b2    = (const float*)d_in[12];
    const float* ln2w  = (const float*)d_in[13];
    const float* ln2b  = (const float*)d_in[14];
    float* out = (float*)d_out;

    float *px, *pqkv, *pattn, *pproj, *pff, *ptn, *pfn, *pvn, *pcf, *pcv;
    cudaGetSymbolAddress((void**)&px,    g_x);
    cudaGetSymbolAddress((void**)&pqkv,  g_qkv);
    cudaGetSymbolAddress((void**)&pattn, g_attn);
    cudaGetSymbolAddress((void**)&pproj, g_proj);
    cudaGetSymbolAddress((void**)&pff,   g_ff);
    cudaGetSymbolAddress((void**)&ptn,   g_tn);
    cudaGetSymbolAddress((void**)&pfn,   g_fn);
    cudaGetSymbolAddress((void**)&pvn,   g_vn);
    cudaGetSymbolAddress((void**)&pcf,   g_cf);
    cudaGetSymbolAddress((void**)&pcv,   g_cv);

    build_x_kernel<<<(NROWS * DM) / 256, 256>>>(fr, ex, px);

    for (int l = 0; l < NL; l++) {
        // QKV: [8192,512] x [1536,512]^T
        mma_nt<<<dim3(3 * DM / BN, NROWS / BM), 256>>>(
            px, Wqkv + (size_t)l * 3 * DM * DM, bqkv + (size_t)l * 3 * DM,
            pqkv, NROWS, 3 * DM, DM, 0);
        // attention per (batch, head)
        attn_kernel<<<dim3(NB, NH), dim3(32, 32)>>>(pqkv, pattn);
        // O projection
        mma_nt<<<dim3(DM / BN, NROWS / BM), 256>>>(
            pattn, Wo + (size_t)l * DM * DM, bo + (size_t)l * DM,
            pproj, NROWS, DM, DM, 0);
        add_ln_kernel<<<NROWS, 256>>>(px, pproj, ln1w + (size_t)l * DM, ln1b + (size_t)l * DM);
        // FF1 (+ReLU)
        mma_nt<<<dim3(FFD / BN, NROWS / BM), 256>>>(
            px, W1 + (size_t)l * FFD * DM, b1 + (size_t)l * FFD,
            pff, NROWS, FFD, DM, 1);
        // FF2
        mma_nt<<<dim3(DM / BN, NROWS / BM), 256>>>(
            pff, W2 + (size_t)l * DM * FFD, b2 + (size_t)l * DM,
            pproj, NROWS, DM, FFD, 0);
        add_ln_kernel<<<NROWS, 256>>>(px, pproj, ln2w + (size_t)l * DM, ln2b + (size_t)l * DM);
    }

    // normalizations
    l2norm_kernel<<<NB, 256>>>(text, ptn);
    l2norm_kernel<<<NFR, 256>>>(fr, pfn);
    l2norm_kernel<<<NROWS, 256>>>(px, pvn);

    // similarity dot-product GEMMs
    mma_nt<<<dim3(NFR / BN, NB / BM), 256>>>(ptn, pfn, nullptr, pcf, NB, NFR, DM, 0);
    mma_nt<<<dim3(NROWS / BN, NB / BM), 256>>>(ptn, pvn, nullptr, pcv, NB, NROWS, DM, 0);

    // MaxSim + write three output matrices
    sim_out_kernel<<<(NB * NB) / 256, 256>>>(pcf, pcv, out);
}

// round 5
// speedup vs baseline: 1.6903x; 1.1651x over previous
#include <cuda_runtime.h>
#include <cuda_bf16.h>
#include <math.h>

// Problem constants
#define NL 4
#define DM 512
#define NH 8
#define DH 64
#define FFD 2048
#define NB 256
#define NF 30
#define NS 32
#define NROWS (NB*NS)      // 8192
#define NFR   (NB*NF)      // 7680

// GEMM tile config
#define BM 128
#define BN 64
#define BK 32
#define W20 20             // smem row stride in 32-bit words (16 data + 4 pad)

// ------------------------- scratch (device globals, no allocs) -------------
__device__ __align__(16) float g_x[NROWS*DM];      // residual stream fp32
__device__ __align__(16) float g_qkv[NROWS*3*DM];  // qkv projection fp32
__device__ __align__(16) float g_proj[NROWS*DM];   // o-proj / ff2 output fp32
__device__ __align__(16) float g_cf[NB*NFR];       // text x frames dots
__device__ __align__(16) float g_cv[NB*NROWS];     // text x video dots

// packed bf16 hi/lo operand buffers (each unsigned = 2 bf16 along K)
__device__ __align__(16) unsigned g_xh [NROWS*DM/2],  g_xl [NROWS*DM/2];
__device__ __align__(16) unsigned g_ath[NROWS*DM/2],  g_atl[NROWS*DM/2];
__device__ __align__(16) unsigned g_ffh[NROWS*FFD/2], g_ffl[NROWS*FFD/2];
__device__ __align__(16) unsigned g_wqkvh[NL*3*DM*DM/2], g_wqkvl[NL*3*DM*DM/2];
__device__ __align__(16) unsigned g_woh [NL*DM*DM/2],    g_wol [NL*DM*DM/2];
__device__ __align__(16) unsigned g_w1h [NL*FFD*DM/2],   g_w1l [NL*FFD*DM/2];
__device__ __align__(16) unsigned g_w2h [NL*DM*FFD/2],   g_w2l [NL*DM*FFD/2];
__device__ __align__(16) unsigned g_tnh[NB*DM/2],   g_tnl[NB*DM/2];
__device__ __align__(16) unsigned g_fnh[NFR*DM/2],  g_fnl[NFR*DM/2];
__device__ __align__(16) unsigned g_vnh[NROWS*DM/2],g_vnl[NROWS*DM/2];

// ------------------------- bf16 hi/lo split helper -------------------------
__device__ __forceinline__ void split2(float f0, float f1, unsigned &h, unsigned &l) {
    __nv_bfloat162 hv = __floats2bfloat162_rn(f0, f1);
    h = reinterpret_cast<unsigned&>(hv);
    float r0 = f0 - __bfloat162float(hv.x);
    float r1 = f1 - __bfloat162float(hv.y);
    __nv_bfloat162 lv = __floats2bfloat162_rn(r0, r1);
    l = reinterpret_cast<unsigned&>(lv);
}

// ------------------------- generic fp32 -> split pre-pass -------------------
__global__ void split_pairs(const float* __restrict__ src,
                            unsigned* __restrict__ dh, unsigned* __restrict__ dl,
                            int nw) {
    int i = blockIdx.x * 256 + threadIdx.x;
    if (i < nw) {
        float2 v = *reinterpret_cast<const float2*>(src + 2 * (size_t)i);
        unsigned h, l;
        split2(v.x, v.y, h, l);
        dh[i] = h; dl[i] = l;
    }
}

// ------------------------- build x = [frames; expansion] (+split) ----------
__global__ void build_x_split(const float* __restrict__ fr,
                              const float* __restrict__ ex,
                              float* __restrict__ x,
                              unsigned* __restrict__ xh, unsigned* __restrict__ xl) {
    int widx = blockIdx.x * 256 + threadIdx.x;  // over NROWS*256 word-pairs
    int c2 = widx & 255;
    int row = widx >> 8;
    int b = row >> 5;
    int s = row & 31;
    float2 v = (s < NF)
        ? *reinterpret_cast<const float2*>(fr + ((size_t)(b * NF + s) * DM + 2 * c2))
        : *reinterpret_cast<const float2*>(ex + ((size_t)(s - NF) * DM + 2 * c2));
    *reinterpret_cast<float2*>(x + (size_t)row * DM + 2 * c2) = v;
    unsigned h, l;
    split2(v.x, v.y, h, l);
    xh[widx] = h; xl[widx] = l;
}

// ------------------------- bf16x3 tensor-core GEMM -------------------------
// C[M,N] = A[M,K] * B[N,K]^T (+bias)(relu). Operands pre-split into bf16
// hi/lo packed pairs. 3 mma per logical tile: hh + lh + hl.
// mma.sync.aligned.m16n8k16.row.col.f32.bf16.bf16.f32
#define MMA_BF16(d, a, b) \
    asm volatile("mma.sync.aligned.m16n8k16.row.col.f32.bf16.bf16.f32 " \
                 "{%0,%1,%2,%3}, {%4,%5,%6,%7}, {%8,%9}, {%0,%1,%2,%3};" \
                 : "+f"(d[0]), "+f"(d[1]), "+f"(d[2]), "+f"(d[3]) \
                 : "r"(a[0]), "r"(a[1]), "r"(a[2]), "r"(a[3]), \
                   "r"(b[0]), "r"(b[1]))

__global__ __launch_bounds__(256, 2) void mma_bf3(
    const unsigned* __restrict__ Ah, const unsigned* __restrict__ Al,
    const unsigned* __restrict__ Bh, const unsigned* __restrict__ Bl,
    const float* __restrict__ bias, float* __restrict__ C,
    unsigned* __restrict__ Ch, unsigned* __restrict__ Cl,
    int M, int N, int K, int relu)
{
    __shared__ unsigned sAh[BM * W20], sAl[BM * W20];
    __shared__ unsigned sBh[BN * W20], sBl[BN * W20];
    const int Kw = K >> 1;  // words per global row
    const int bn = blockIdx.x * BN;
    const int bm = blockIdx.y * BM;
    const int tid = threadIdx.x;
    const int warp = tid >> 5;
    const int lane = tid & 31;
    const int g = lane >> 2;      // 0..7
    const int t = lane & 3;       // 0..3
    const int wm = (warp & 3) * 32;
    const int wn = (warp >> 2) * 32;

    // staging mapping: A has 512 uint4 per tile (2/thread), B has 256 (1/thread)
    const int ua0 = tid * 2, ua1 = tid * 2 + 1;
    const int ra0 = ua0 >> 2, qa0 = (ua0 & 3) * 4;
    const int ra1 = ua1 >> 2, qa1 = (ua1 & 3) * 4;
    const int rb  = tid >> 2, qb  = (tid & 3) * 4;

    const unsigned* gAh0 = Ah + (size_t)(bm + ra0) * Kw + qa0;
    const unsigned* gAh1 = Ah + (size_t)(bm + ra1) * Kw + qa1;
    const unsigned* gAl0 = Al + (size_t)(bm + ra0) * Kw + qa0;
    const unsigned* gAl1 = Al + (size_t)(bm + ra1) * Kw + qa1;
    const unsigned* gBh0 = Bh + (size_t)(bn + rb) * Kw + qb;
    const unsigned* gBl0 = Bl + (size_t)(bn + rb) * Kw + qb;

    float acc[2][4][4];
#pragma unroll
    for (int mt = 0; mt < 2; mt++)
#pragma unroll
        for (int nt = 0; nt < 4; nt++)
#pragma unroll
            for (int i = 0; i < 4; i++) acc[mt][nt][i] = 0.f;

    uint4 pah0 = *reinterpret_cast<const uint4*>(gAh0);
    uint4 pah1 = *reinterpret_cast<const uint4*>(gAh1);
    uint4 pal0 = *reinterpret_cast<const uint4*>(gAl0);
    uint4 pal1 = *reinterpret_cast<const uint4*>(gAl1);
    uint4 pbh  = *reinterpret_cast<const uint4*>(gBh0);
    uint4 pbl  = *reinterpret_cast<const uint4*>(gBl0);
    *reinterpret_cast<uint4*>(sAh + ra0 * W20 + qa0) = pah0;
    *reinterpret_cast<uint4*>(sAh + ra1 * W20 + qa1) = pah1;
    *reinterpret_cast<uint4*>(sAl + ra0 * W20 + qa0) = pal0;
    *reinterpret_cast<uint4*>(sAl + ra1 * W20 + qa1) = pal1;
    *reinterpret_cast<uint4*>(sBh + rb  * W20 + qb)  = pbh;
    *reinterpret_cast<uint4*>(sBl + rb  * W20 + qb)  = pbl;
    __syncthreads();

    const int ntiles = K / BK;
    for (int tile = 0; tile < ntiles; tile++) {
        const bool more = (tile + 1) < ntiles;
        if (more) {
            const int kw = (tile + 1) * 16;
            pah0 = *reinterpret_cast<const uint4*>(gAh0 + kw);
            pah1 = *reinterpret_cast<const uint4*>(gAh1 + kw);
            pal0 = *reinterpret_cast<const uint4*>(gAl0 + kw);
            pal1 = *reinterpret_cast<const uint4*>(gAl1 + kw);
            pbh  = *reinterpret_cast<const uint4*>(gBh0 + kw);
            pbl  = *reinterpret_cast<const uint4*>(gBl0 + kw);
        }

#pragma unroll
        for (int step = 0; step < 2; step++) {
            const int kkw = step * 8;
            unsigned ah[2][4], al[2][4], bh[4][2], bl[4][2];
#pragma unroll
            for (int mt = 0; mt < 2; mt++) {
                const int r0 = (wm + mt * 16 + g) * W20 + kkw + t;
                const int r1 = (wm + mt * 16 + 8 + g) * W20 + kkw + t;
                ah[mt][0] = sAh[r0];     ah[mt][1] = sAh[r1];
                ah[mt][2] = sAh[r0 + 4]; ah[mt][3] = sAh[r1 + 4];
                al[mt][0] = sAl[r0];     al[mt][1] = sAl[r1];
                al[mt][2] = sAl[r0 + 4]; al[mt][3] = sAl[r1 + 4];
            }
#pragma unroll
            for (int nt = 0; nt < 4; nt++) {
                const int rB = (wn + nt * 8 + g) * W20 + kkw + t;
                bh[nt][0] = sBh[rB]; bh[nt][1] = sBh[rB + 4];
                bl[nt][0] = sBl[rB]; bl[nt][1] = sBl[rB + 4];
            }
#pragma unroll
            for (int mt = 0; mt < 2; mt++)
#pragma unroll
                for (int nt = 0; nt < 4; nt++) {
                    MMA_BF16(acc[mt][nt], ah[mt], bh[nt]);
                    MMA_BF16(acc[mt][nt], al[mt], bh[nt]);
                    MMA_BF16(acc[mt][nt], ah[mt], bl[nt]);
                }
        }

        if (more) {
            __syncthreads();
            *reinterpret_cast<uint4*>(sAh + ra0 * W20 + qa0) = pah0;
            *reinterpret_cast<uint4*>(sAh + ra1 * W20 + qa1) = pah1;
            *reinterpret_cast<uint4*>(sAl + ra0 * W20 + qa0) = pal0;
            *reinterpret_cast<uint4*>(sAl + ra1 * W20 + qa1) = pal1;
            *reinterpret_cast<uint4*>(sBh + rb  * W20 + qb)  = pbh;
            *reinterpret_cast<uint4*>(sBl + rb  * W20 + qb)  = pbl;
            __syncthreads();
        }
    }

    // epilogue
#pragma unroll
    for (int mt = 0; mt < 2; mt++) {
        const int r0 = bm + wm + mt * 16 + g;
#pragma unroll
        for (int nt = 0; nt < 4; nt++) {
            const int c = bn + wn + nt * 8 + 2 * t;
            float b0 = 0.f, b1 = 0.f;
            if (bias) { b0 = __ldg(bias + c); b1 = __ldg(bias + c + 1); }
            float v00 = acc[mt][nt][0] + b0;
            float v01 = acc[mt][nt][1] + b1;
            float v10 = acc[mt][nt][2] + b0;
            float v11 = acc[mt][nt][3] + b1;
            if (relu) {
                v00 = fmaxf(v00, 0.f); v01 = fmaxf(v01, 0.f);
                v10 = fmaxf(v10, 0.f); v11 = fmaxf(v11, 0.f);
            }
            if (Ch) {
                unsigned h, l;
                split2(v00, v01, h, l);
                size_t wi = ((size_t)r0 * N + c) >> 1;
                Ch[wi] = h; Cl[wi] = l;
                split2(v10, v11, h, l);
                wi = ((size_t)(r0 + 8) * N + c) >> 1;
                Ch[wi] = h; Cl[wi] = l;
            } else {
                *reinterpret_cast<float2*>(C + (size_t)r0 * N + c) = make_float2(v00, v01);
                *reinterpret_cast<float2*>(C + (size_t)(r0 + 8) * N + c) = make_float2(v10, v11);
            }
        }
    }
}

// ------------------------- attention (+split epilogue) ---------------------
__global__ __launch_bounds__(1024) void attn_split(const float* __restrict__ qkv,
                                                   unsigned* __restrict__ oh,
                                                   unsigned* __restrict__ ol) {
    const int b = blockIdx.x;
    const int hh = blockIdx.y;
    __shared__ float sq[32][65];
    __shared__ float sk[32][65];
    __shared__ float sv[32][65];
    __shared__ float sp[32][33];
    const int tx = threadIdx.x;   // 0..31
    const int ty = threadIdx.y;   // 0..31

    const float* base = qkv + (size_t)(b * NS + ty) * (3 * DM) + hh * DH;
    sq[ty][tx]      = base[tx];
    sq[ty][tx + 32] = base[tx + 32];
    sk[ty][tx]      = base[DM + tx];
    sk[ty][tx + 32] = base[DM + tx + 32];
    sv[ty][tx]      = base[2 * DM + tx];
    sv[ty][tx + 32] = base[2 * DM + tx + 32];
    __syncthreads();

    float acc = 0.f;
#pragma unroll
    for (int d = 0; d < DH; d++) acc += sq[ty][d] * sk[tx][d];
    acc *= 0.125f; // 1/sqrt(64)

    float m = acc;
#pragma unroll
    for (int o = 16; o; o >>= 1) m = fmaxf(m, __shfl_xor_sync(0xffffffffu, m, o));
    float e = __expf(acc - m);
    float s = e;
#pragma unroll
    for (int o = 16; o; o >>= 1) s += __shfl_xor_sync(0xffffffffu, s, o);
    sp[ty][tx] = e / s;
    __syncthreads();

    float o0 = 0.f, o1 = 0.f;
#pragma unroll
    for (int k = 0; k < NS; k++) {
        float p = sp[ty][k];
        o0 += p * sv[k][2 * tx];
        o1 += p * sv[k][2 * tx + 1];
    }
    unsigned h, l;
    split2(o0, o1, h, l);
    size_t wi = ((size_t)(b * NS + ty) * DM + hh * DH) / 2 + tx;
    oh[wi] = h; ol[wi] = l;
}

// ------------------------- block reduce (256 threads) ----------------------
__device__ __forceinline__ float block_reduce_256(float v, float* sh) {
    __syncthreads();
    int lane = threadIdx.x & 31, wid = threadIdx.x >> 5;
#pragma unroll
    for (int o = 16; o; o >>= 1) v += __shfl_xor_sync(0xffffffffu, v, o);
    if (lane == 0) sh[wid] = v;
    __syncthreads();
    if (threadIdx.x == 0) {
        float t = 0.f;
#pragma unroll
        for (int w = 0; w < 8; w++) t += sh[w];
        sh[8] = t;
    }
    __syncthreads();
    return sh[8];
}

// ------------------------- x = LayerNorm(x + o) (+split) -------------------
__global__ __launch_bounds__(256) void add_ln_split(float* __restrict__ x,
                                                    const float* __restrict__ o,
                                                    const float* __restrict__ g,
                                                    const float* __restrict__ bt,
                                                    unsigned* __restrict__ xh,
                                                    unsigned* __restrict__ xl) {
    __shared__ float red[16];
    const int row = blockIdx.x;
    const int t = threadIdx.x;   // pair index 0..255
    float2 xv = *reinterpret_cast<const float2*>(x + (size_t)row * DM + 2 * t);
    float2 ov = *reinterpret_cast<const float2*>(o + (size_t)row * DM + 2 * t);
    float v0 = xv.x + ov.x;
    float v1 = xv.y + ov.y;
    float mean = block_reduce_256(v0 + v1, red) * (1.f / DM);
    float d0 = v0 - mean, d1 = v1 - mean;
    float var = block_reduce_256(d0 * d0 + d1 * d1, red) * (1.f / DM);
    float rs = rsqrtf(var + 1e-5f);
    float2 gg = *reinterpret_cast<const float2*>(g + 2 * t);
    float2 bb = *reinterpret_cast<const float2*>(bt + 2 * t);
    float r0 = d0 * rs * gg.x + bb.x;
    float r1 = d1 * rs * gg.y + bb.y;
    *reinterpret_cast<float2*>(x + (size_t)row * DM + 2 * t) = make_float2(r0, r1);
    unsigned h, l;
    split2(r0, r1, h, l);
    xh[(size_t)row * 256 + t] = h;
    xl[(size_t)row * 256 + t] = l;
}

// ------------------------- row l2 normalize (+split only) ------------------
__global__ __launch_bounds__(256) void l2norm_split(const float* __restrict__ in,
                                                    unsigned* __restrict__ oh,
                                                    unsigned* __restrict__ ol) {
    __shared__ float red[16];
    const int row = blockIdx.x;
    const int t = threadIdx.x;
    float2 v = *reinterpret_cast<const float2*>(in + (size_t)row * DM + 2 * t);
    float ss = block_reduce_256(v.x * v.x + v.y * v.y, red);
    float inv = 1.f / fmaxf(sqrtf(ss), 1e-12f);
    float r0 = v.x * inv, r1 = v.y * inv;
    unsigned h, l;
    split2(r0, r1, h, l);
    oh[(size_t)row * 256 + t] = h;
    ol[(size_t)row * 256 + t] = l;
}

// ------------------------- MaxSim reduce + output --------------------------
__global__ void sim_out_kernel(const float* __restrict__ cf,
                               const float* __restrict__ cv,
                               float* __restrict__ out) {
    int p = blockIdx.x * 256 + threadIdx.x;  // 65536 pairs
    int i = p >> 8;
    int j = p & 255;
    const float* pf = cf + (size_t)i * NFR + j * NF;
    float mf = -1e30f;
#pragma unroll
    for (int f = 0; f < NF; f++) mf = fmaxf(mf, pf[f]);
    const float* pv = cv + (size_t)i * NROWS + j * NS;
    float mv = -1e30f;
#pragma unroll
    for (int v = 0; v < NS; v++) mv = fmaxf(mv, pv[v]);
    out[p]               = mf + mv;
    out[NB * NB + p]     = mf;
    out[2 * NB * NB + p] = mv;
}

// ------------------------- launcher ----------------------------------------
extern "C" void kernel_launch(void* const* d_in, const int* in_sizes, int n_in,
                              void* d_out, int out_size) {
    const float* text  = (const float*)d_in[0];
    const float* fr    = (const float*)d_in[1];
    const float* ex    = (const float*)d_in[2];
    const float* Wqkv  = (const float*)d_in[3];
    const float* bqkv  = (const float*)d_in[4];
    const float* Wo    = (const float*)d_in[5];
    const float* bo    = (const float*)d_in[6];
    const float* ln1w  = (const float*)d_in[7];
    const float* ln1b  = (const float*)d_in[8];
    const float* W1    = (const float*)d_in[9];
    const float* b1    = (const float*)d_in[10];
    const float* W2    = (const float*)d_in[11];
    const float* b2    = (const float*)d_in[12];
    const float* ln2w  = (const float*)d_in[13];
    const float* ln2b  = (const float*)d_in[14];
    float* out = (float*)d_out;

    float *px, *pqkv, *pproj, *pcf, *pcv;
    unsigned *pxh, *pxl, *path, *patl, *pffh, *pffl;
    unsigned *pwqkvh, *pwqkvl, *pwoh, *pwol, *pw1h, *pw1l, *pw2h, *pw2l;
    unsigned *ptnh, *ptnl, *pfnh, *pfnl, *pvnh, *pvnl;
    cudaGetSymbolAddress((void**)&px,     g_x);
    cudaGetSymbolAddress((void**)&pqkv,   g_qkv);
    cudaGetSymbolAddress((void**)&pproj,  g_proj);
    cudaGetSymbolAddress((void**)&pcf,    g_cf);
    cudaGetSymbolAddress((void**)&pcv,    g_cv);
    cudaGetSymbolAddress((void**)&pxh,    g_xh);
    cudaGetSymbolAddress((void**)&pxl,    g_xl);
    cudaGetSymbolAddress((void**)&path,   g_ath);
    cudaGetSymbolAddress((void**)&patl,   g_atl);
    cudaGetSymbolAddress((void**)&pffh,   g_ffh);
    cudaGetSymbolAddress((void**)&pffl,   g_ffl);
    cudaGetSymbolAddress((void**)&pwqkvh, g_wqkvh);
    cudaGetSymbolAddress((void**)&pwqkvl, g_wqkvl);
    cudaGetSymbolAddress((void**)&pwoh,   g_woh);
    cudaGetSymbolAddress((void**)&pwol,   g_wol);
    cudaGetSymbolAddress((void**)&pw1h,   g_w1h);
    cudaGetSymbolAddress((void**)&pw1l,   g_w1l);
    cudaGetSymbolAddress((void**)&pw2h,   g_w2h);
    cudaGetSymbolAddress((void**)&pw2l,   g_w2l);
    cudaGetSymbolAddress((void**)&ptnh,   g_tnh);
    cudaGetSymbolAddress((void**)&ptnl,   g_tnl);
    cudaGetSymbolAddress((void**)&pfnh,   g_fnh);
    cudaGetSymbolAddress((void**)&pfnl,   g_fnl);
    cudaGetSymbolAddress((void**)&pvnh,   g_vnh);
    cudaGetSymbolAddress((void**)&pvnl,   g_vnl);

    // weight pre-splits (cheap, memory-bound)
    {
        int nw;
        nw = NL * 3 * DM * DM / 2;
        split_pairs<<<(nw + 255) / 256, 256>>>(Wqkv, pwqkvh, pwqkvl, nw);
        nw = NL * DM * DM / 2;
        split_pairs<<<(nw + 255) / 256, 256>>>(Wo, pwoh, pwol, nw);
        nw = NL * FFD * DM / 2;
        split_pairs<<<(nw + 255) / 256, 256>>>(W1, pw1h, pw1l, nw);
        nw = NL * DM * FFD / 2;
        split_pairs<<<(nw + 255) / 256, 256>>>(W2, pw2h, pw2l, nw);
    }

    build_x_split<<<(NROWS * DM / 2) / 256, 256>>>(fr, ex, px, pxh, pxl);

    for (int l = 0; l < NL; l++) {
        // QKV: [8192,512] x [1536,512]^T -> fp32
        mma_bf3<<<dim3(3 * DM / BN, NROWS / BM), 256>>>(
            pxh, pxl,
            pwqkvh + (size_t)l * 3 * DM * DM / 2, pwqkvl + (size_t)l * 3 * DM * DM / 2,
            bqkv + (size_t)l * 3 * DM, pqkv, nullptr, nullptr,
            NROWS, 3 * DM, DM, 0);
        // attention per (batch, head), writes split output
        attn_split<<<dim3(NB, NH), dim3(32, 32)>>>(pqkv, path, patl);
        // O projection -> fp32
        mma_bf3<<<dim3(DM / BN, NROWS / BM), 256>>>(
            path, patl,
            pwoh + (size_t)l * DM * DM / 2, pwol + (size_t)l * DM * DM / 2,
            bo + (size_t)l * DM, pproj, nullptr, nullptr,
            NROWS, DM, DM, 0);
        add_ln_split<<<NROWS, 256>>>(px, pproj, ln1w + (size_t)l * DM,
                                     ln1b + (size_t)l * DM, pxh, pxl);
        // FF1 (+ReLU), writes split output directly
        mma_bf3<<<dim3(FFD / BN, NROWS / BM), 256>>>(
            pxh, pxl,
            pw1h + (size_t)l * FFD * DM / 2, pw1l + (size_t)l * FFD * DM / 2,
            b1 + (size_t)l * FFD, nullptr, pffh, pffl,
            NROWS, FFD, DM, 1);
        // FF2 -> fp32
        mma_bf3<<<dim3(DM / BN, NROWS / BM), 256>>>(
            pffh, pffl,
            pw2h + (size_t)l * DM * FFD / 2, pw2l + (size_t)l * DM * FFD / 2,
            b2 + (size_t)l * DM, pproj, nullptr, nullptr,
            NROWS, DM, FFD, 0);
        add_ln_split<<<NROWS, 256>>>(px, pproj, ln2w + (size_t)l * DM,
                                     ln2b + (size_t)l * DM, pxh, pxl);
    }

    // normalizations (write split operands only)
    l2norm_split<<<NB, 256>>>(text, ptnh, ptnl);
    l2norm_split<<<NFR, 256>>>(fr, pfnh, pfnl);
    l2norm_split<<<NROWS, 256>>>(px, pvnh, pvnl);

    // similarity dot-product GEMMs -> fp32
    mma_bf3<<<dim3(NFR / BN, NB / BM), 256>>>(
        ptnh, ptnl, pfnh, pfnl, nullptr, pcf, nullptr, nullptr, NB, NFR, DM, 0);
    mma_bf3<<<dim3(NROWS / BN, NB / BM), 256>>>(
        ptnh, ptnl, pvnh, pvnl, nullptr, pcv, nullptr, nullptr, NB, NROWS, DM, 0);

    // MaxSim + write three output matrices
    sim_out_kernel<<<(NB * NB) / 256, 256>>>(pcf, pcv, out);
}

// round 7
// speedup vs baseline: 2.5576x; 1.5131x over previous
#include <cuda_runtime.h>
#include <cuda_bf16.h>
#include <math.h>
#include <stdint.h>

// Problem constants
#define NL 4
#define DM 512
#define NH 8
#define DH 64
#define FFD 2048
#define NB 256
#define NF 30
#define NS 32
#define NROWS (NB*NS)      // 8192
#define NFR   (NB*NF)      // 7680

// GEMM config: CTA tile 128x128, BK=32, 512 threads (16 warps, 4x4),
// warp tile 32x32 (mt=2 m16 tiles, nt=4 n8 tiles), 3-stage cp.async pipeline.
#define SSTAGES 3
#define MATB 8192                 // bytes per matrix per stage (128 rows x 64B)
#define STAGEB (4*MATB)           // Ah, Al, Bh, Bl
#define TC_SMEM (SSTAGES*STAGEB)  // 98304

// ------------------------- scratch (device globals, no allocs) -------------
__device__ __align__(16) float g_x[NROWS*DM];      // residual stream fp32
__device__ __align__(16) float g_qkv[NROWS*3*DM];  // qkv projection fp32
__device__ __align__(16) float g_proj[NROWS*DM];   // o-proj / ff2 output fp32
__device__ __align__(16) float g_cf[NB*NFR];       // text x frames dots
__device__ __align__(16) float g_cv[NB*NROWS];     // text x video dots

// packed bf16 hi/lo operand buffers (each unsigned = 2 bf16 along K)
__device__ __align__(16) unsigned g_xh [NROWS*DM/2],  g_xl [NROWS*DM/2];
__device__ __align__(16) unsigned g_ath[NROWS*DM/2],  g_atl[NROWS*DM/2];
__device__ __align__(16) unsigned g_ffh[NROWS*FFD/2], g_ffl[NROWS*FFD/2];
__device__ __align__(16) unsigned g_wqkvh[NL*3*DM*DM/2], g_wqkvl[NL*3*DM*DM/2];
__device__ __align__(16) unsigned g_woh [NL*DM*DM/2],    g_wol [NL*DM*DM/2];
__device__ __align__(16) unsigned g_w1h [NL*FFD*DM/2],   g_w1l [NL*FFD*DM/2];
__device__ __align__(16) unsigned g_w2h [NL*DM*FFD/2],   g_w2l [NL*DM*FFD/2];
__device__ __align__(16) unsigned g_tnh[NB*DM/2],   g_tnl[NB*DM/2];
__device__ __align__(16) unsigned g_fnh[NFR*DM/2],  g_fnl[NFR*DM/2];
__device__ __align__(16) unsigned g_vnh[NROWS*DM/2],g_vnl[NROWS*DM/2];

// ------------------------- bf16 hi/lo split helper -------------------------
__device__ __forceinline__ void split2(float f0, float f1, unsigned &h, unsigned &l) {
    __nv_bfloat162 hv = __floats2bfloat162_rn(f0, f1);
    h = reinterpret_cast<unsigned&>(hv);
    float r0 = f0 - __bfloat162float(hv.x);
    float r1 = f1 - __bfloat162float(hv.y);
    __nv_bfloat162 lv = __floats2bfloat162_rn(r0, r1);
    l = reinterpret_cast<unsigned&>(lv);
}

__device__ __forceinline__ uint32_t smem_u32(const void* p) {
    uint32_t a;
    asm("{ .reg .u64 t; cvta.to.shared.u64 t, %1; cvt.u32.u64 %0, t; }"
        : "=r"(a) : "l"(p));
    return a;
}

#define MMA_BF16(d, a, b0, b1) \
    asm volatile("mma.sync.aligned.m16n8k16.row.col.f32.bf16.bf16.f32 " \
                 "{%0,%1,%2,%3}, {%4,%5,%6,%7}, {%8,%9}, {%0,%1,%2,%3};" \
                 : "+f"(d[0]), "+f"(d[1]), "+f"(d[2]), "+f"(d[3]) \
                 : "r"(a[0]), "r"(a[1]), "r"(a[2]), "r"(a[3]), \
                   "r"(b0), "r"(b1))

#define LDSM4(r, addr) \
    asm volatile("ldmatrix.sync.aligned.m8n8.x4.shared.b16 {%0,%1,%2,%3}, [%4];" \
                 : "=r"((r)[0]), "=r"((r)[1]), "=r"((r)[2]), "=r"((r)[3]) \
                 : "r"(addr))

#define CP_ASYNC16(dst, src) \
    asm volatile("cp.async.cg.shared.global [%0], [%1], 16;" \
                 :: "r"(dst), "l"(src) : "memory")

#define CP_COMMIT() asm volatile("cp.async.commit_group;" ::: "memory")
#define CP_WAIT1()  asm volatile("cp.async.wait_group 1;" ::: "memory")

// ------------------------- bf16x3 mma.sync GEMM ----------------------------
// C[M,N] = A[M,K]*B[N,K]^T (+bias)(relu). Operands pre-split bf16 hi/lo pairs.
__global__ __launch_bounds__(512) void mma_gemm(
    const unsigned* __restrict__ Ah, const unsigned* __restrict__ Al,
    const unsigned* __restrict__ Bh, const unsigned* __restrict__ Bl,
    const float* __restrict__ bias, float* __restrict__ C,
    unsigned* __restrict__ Ch, unsigned* __restrict__ Cl,
    int M, int N, int K, int relu)
{
    extern __shared__ __align__(16) char dsm[];
    const uint32_t sbase = smem_u32(dsm);

    const int tid  = threadIdx.x;
    const int warp = tid >> 5;
    const int lane = tid & 31;
    const int g = lane >> 2;        // 0..7
    const int t = lane & 3;         // 0..3
    const int wm = (warp & 3) * 32;
    const int wn = (warp >> 2) * 32;
    const int bm = blockIdx.y * 128;
    const int bn = blockIdx.x * 128;

    // ---- cp.async mapping: each thread loads one 16B chunk per matrix -----
    const int lrow = tid >> 2;      // 0..127
    const int lc   = tid & 3;       // 16B chunk within 64B row
    const int Kc16 = K >> 3;        // 16B chunks per global row
    const uint32_t swoff = lrow * 64 + ((lc ^ ((lrow >> 1) & 3)) << 4);

    const char* gAh = (const char*)Ah + ((size_t)(bm + lrow) * Kc16 + lc) * 16;
    const char* gAl = (const char*)Al + ((size_t)(bm + lrow) * Kc16 + lc) * 16;
    const char* gBh = (const char*)Bh + ((size_t)(bn + lrow) * Kc16 + lc) * 16;
    const char* gBl = (const char*)Bl + ((size_t)(bn + lrow) * Kc16 + lc) * 16;

    auto load_stage = [&](int chunk, int stage) {
        const size_t go = (size_t)chunk * 64;
        const uint32_t d = sbase + stage * STAGEB + swoff;
        CP_ASYNC16(d,            gAh + go);
        CP_ASYNC16(d + MATB,     gAl + go);
        CP_ASYNC16(d + 2*MATB,   gBh + go);
        CP_ASYNC16(d + 3*MATB,   gBl + go);
    };

    // ---- ldmatrix base addresses (stage 0, k-step 0) ----------------------
    const int mat  = lane >> 3;     // 0..3
    const int mrow = lane & 7;      // 0..7
    uint32_t aB[2][2], bB[2][2];    // [term][mt] / [term][pair]
#pragma unroll
    for (int mt = 0; mt < 2; mt++) {
        const int r = wm + mt * 16 + (mat & 1) * 8 + mrow;
        const uint32_t off = r * 64 + ((((unsigned)mat >> 1) ^ ((r >> 1) & 3)) << 4);
        aB[0][mt] = sbase + off;            // Ah
        aB[1][mt] = sbase + MATB + off;     // Al
    }
#pragma unroll
    for (int p = 0; p < 2; p++) {
        const int r = wn + p * 16 + (mat >> 1) * 8 + mrow;
        const uint32_t off = r * 64 + ((((unsigned)mat & 1) ^ ((r >> 1) & 3)) << 4);
        bB[0][p] = sbase + 2*MATB + off;    // Bh
        bB[1][p] = sbase + 3*MATB + off;    // Bl
    }

    float acc[2][4][4];
#pragma unroll
    for (int mt = 0; mt < 2; mt++)
#pragma unroll
        for (int nt = 0; nt < 4; nt++)
#pragma unroll
            for (int i = 0; i < 4; i++) acc[mt][nt][i] = 0.f;

    auto compute = [&](int stage) {
        const uint32_t so = stage * STAGEB;
#pragma unroll
        for (int s = 0; s < 2; s++) {
            const uint32_t sx = (uint32_t)(s << 5);   // k-step toggles bit5
            unsigned ah[2][4], al[2][4], bh[2][4], bl[2][4];
#pragma unroll
            for (int mt = 0; mt < 2; mt++) {
                LDSM4(ah[mt], (aB[0][mt] + so) ^ sx);
                LDSM4(al[mt], (aB[1][mt] + so) ^ sx);
            }
#pragma unroll
            for (int p = 0; p < 2; p++) {
                LDSM4(bh[p], (bB[0][p] + so) ^ sx);
                LDSM4(bl[p], (bB[1][p] + so) ^ sx);
            }
#pragma unroll
            for (int mt = 0; mt < 2; mt++)
#pragma unroll
                for (int nt = 0; nt < 4; nt++) {
                    const int p = nt >> 1, u = (nt & 1) * 2;
                    MMA_BF16(acc[mt][nt], ah[mt], bh[p][u], bh[p][u+1]);
                    MMA_BF16(acc[mt][nt], al[mt], bh[p][u], bh[p][u+1]);
                    MMA_BF16(acc[mt][nt], ah[mt], bl[p][u], bl[p][u+1]);
                }
        }
    };

    const int NC = K >> 5;          // K/32 chunks

    load_stage(0, 0); CP_COMMIT();
    load_stage(1, 1); CP_COMMIT();

    int stage = 0, pstage = 2, pchunk = 2;
    for (int c = 0; c < NC; c++) {
        CP_WAIT1();
        __syncthreads();
        if (pchunk < NC) load_stage(pchunk, pstage);
        CP_COMMIT();
        compute(stage);
        stage = (stage + 1 == SSTAGES) ? 0 : stage + 1;
        pstage = (pstage + 1 == SSTAGES) ? 0 : pstage + 1;
        pchunk++;
    }

    // ---- epilogue ---------------------------------------------------------
#pragma unroll
    for (int mt = 0; mt < 2; mt++) {
        const int r0 = bm + wm + mt * 16 + g;
#pragma unroll
        for (int nt = 0; nt < 4; nt++) {
            const int c = bn + wn + nt * 8 + 2 * t;
            float b0 = 0.f, b1 = 0.f;
            if (bias) { b0 = __ldg(bias + c); b1 = __ldg(bias + c + 1); }
            float v00 = acc[mt][nt][0] + b0;
            float v01 = acc[mt][nt][1] + b1;
            float v10 = acc[mt][nt][2] + b0;
            float v11 = acc[mt][nt][3] + b1;
            if (relu) {
                v00 = fmaxf(v00, 0.f); v01 = fmaxf(v01, 0.f);
                v10 = fmaxf(v10, 0.f); v11 = fmaxf(v11, 0.f);
            }
            if (Ch) {
                unsigned h, l;
                split2(v00, v01, h, l);
                size_t wi = ((size_t)r0 * N + c) >> 1;
                Ch[wi] = h; Cl[wi] = l;
                split2(v10, v11, h, l);
                wi = ((size_t)(r0 + 8) * N + c) >> 1;
                Ch[wi] = h; Cl[wi] = l;
            } else {
                *reinterpret_cast<float2*>(C + (size_t)r0 * N + c) = make_float2(v00, v01);
                *reinterpret_cast<float2*>(C + (size_t)(r0 + 8) * N + c) = make_float2(v10, v11);
            }
        }
    }
}

// ------------------------- generic fp32 -> split pre-pass -------------------
__global__ void split_pairs(const float* __restrict__ src,
                            unsigned* __restrict__ dh, unsigned* __restrict__ dl,
                            int nw) {
    int i = blockIdx.x * 256 + threadIdx.x;
    if (i < nw) {
        float2 v = *reinterpret_cast<const float2*>(src + 2 * (size_t)i);
        unsigned h, l;
        split2(v.x, v.y, h, l);
        dh[i] = h; dl[i] = l;
    }
}

// ------------------------- build x = [frames; expansion] (+split) ----------
__global__ void build_x_split(const float* __restrict__ fr,
                              const float* __restrict__ ex,
                              float* __restrict__ x,
                              unsigned* __restrict__ xh, unsigned* __restrict__ xl) {
    int widx = blockIdx.x * 256 + threadIdx.x;  // over NROWS*256 word-pairs
    int c2 = widx & 255;
    int row = widx >> 8;
    int b = row >> 5;
    int s = row & 31;
    float2 v = (s < NF)
        ? *reinterpret_cast<const float2*>(fr + ((size_t)(b * NF + s) * DM + 2 * c2))
        : *reinterpret_cast<const float2*>(ex + ((size_t)(s - NF) * DM + 2 * c2));
    *reinterpret_cast<float2*>(x + (size_t)row * DM + 2 * c2) = v;
    unsigned h, l;
    split2(v.x, v.y, h, l);
    xh[widx] = h; xl[widx] = l;
}

// ------------------------- attention (+split epilogue) ---------------------
__global__ __launch_bounds__(1024) void attn_split(const float* __restrict__ qkv,
                                                   unsigned* __restrict__ oh,
                                                   unsigned* __restrict__ ol) {
    const int b = blockIdx.x;
    const int hh = blockIdx.y;
    __shared__ float sq[32][65];
    __shared__ float sk[32][65];
    __shared__ float sv[32][65];
    __shared__ float sp[32][33];
    const int tx = threadIdx.x;   // 0..31
    const int ty = threadIdx.y;   // 0..31

    const float* base = qkv + (size_t)(b * NS + ty) * (3 * DM) + hh * DH;
    sq[ty][tx]      = base[tx];
    sq[ty][tx + 32] = base[tx + 32];
    sk[ty][tx]      = base[DM + tx];
    sk[ty][tx + 32] = base[DM + tx + 32];
    sv[ty][tx]      = base[2 * DM + tx];
    sv[ty][tx + 32] = base[2 * DM + tx + 32];
    __syncthreads();

    float acc = 0.f;
#pragma unroll
    for (int d = 0; d < DH; d++) acc += sq[ty][d] * sk[tx][d];
    acc *= 0.125f; // 1/sqrt(64)

    float m = acc;
#pragma unroll
    for (int o = 16; o; o >>= 1) m = fmaxf(m, __shfl_xor_sync(0xffffffffu, m, o));
    float e = __expf(acc - m);
    float s = e;
#pragma unroll
    for (int o = 16; o; o >>= 1) s += __shfl_xor_sync(0xffffffffu, s, o);
    sp[ty][tx] = e / s;
    __syncthreads();

    float o0 = 0.f, o1 = 0.f;
#pragma unroll
    for (int k = 0; k < NS; k++) {
        float p = sp[ty][k];
        o0 += p * sv[k][2 * tx];
        o1 += p * sv[k][2 * tx + 1];
    }
    unsigned h, l;
    split2(o0, o1, h, l);
    size_t wi = ((size_t)(b * NS + ty) * DM + hh * DH) / 2 + tx;
    oh[wi] = h; ol[wi] = l;
}

// ------------------------- block reduce (256 threads) ----------------------
__device__ __forceinline__ float block_reduce_256(float v, float* sh) {
    __syncthreads();
    int lane = threadIdx.x & 31, wid = threadIdx.x >> 5;
#pragma unroll
    for (int o = 16; o; o >>= 1) v += __shfl_xor_sync(0xffffffffu, v, o);
    if (lane == 0) sh[wid] = v;
    __syncthreads();
    if (threadIdx.x == 0) {
        float t = 0.f;
#pragma unroll
        for (int w = 0; w < 8; w++) t += sh[w];
        sh[8] = t;
    }
    __syncthreads();
    return sh[8];
}

// ------------------------- x = LayerNorm(x + o) (+split) -------------------
__global__ __launch_bounds__(256) void add_ln_split(float* __restrict__ x,
                                                    const float* __restrict__ o,
                                                    const float* __restrict__ g,
                                                    const float* __restrict__ bt,
                                                    unsigned* __restrict__ xh,
                                                    unsigned* __restrict__ xl) {
    __shared__ float red[16];
    const int row = blockIdx.x;
    const int t = threadIdx.x;   // pair index 0..255
    float2 xv = *reinterpret_cast<const float2*>(x + (size_t)row * DM + 2 * t);
    float2 ov = *reinterpret_cast<const float2*>(o + (size_t)row * DM + 2 * t);
    float v0 = xv.x + ov.x;
    float v1 = xv.y + ov.y;
    float mean = block_reduce_256(v0 + v1, red) * (1.f / DM);
    float d0 = v0 - mean, d1 = v1 - mean;
    float var = block_reduce_256(d0 * d0 + d1 * d1, red) * (1.f / DM);
    float rs = rsqrtf(var + 1e-5f);
    float2 gg = *reinterpret_cast<const float2*>(g + 2 * t);
    float2 bb = *reinterpret_cast<const float2*>(bt + 2 * t);
    float r0 = d0 * rs * gg.x + bb.x;
    float r1 = d1 * rs * gg.y + bb.y;
    *reinterpret_cast<float2*>(x + (size_t)row * DM + 2 * t) = make_float2(r0, r1);
    unsigned h, l;
    split2(r0, r1, h, l);
    xh[(size_t)row * 256 + t] = h;
    xl[(size_t)row * 256 + t] = l;
}

// ------------------------- row l2 normalize (+split only) ------------------
__global__ __launch_bounds__(256) void l2norm_split(const float* __restrict__ in,
                                                    unsigned* __restrict__ oh,
                                                    unsigned* __restrict__ ol) {
    __shared__ float red[16];
    const int row = blockIdx.x;
    const int t = threadIdx.x;
    float2 v = *reinterpret_cast<const float2*>(in + (size_t)row * DM + 2 * t);
    float ss = block_reduce_256(v.x * v.x + v.y * v.y, red);
    float inv = 1.f / fmaxf(sqrtf(ss), 1e-12f);
    float r0 = v.x * inv, r1 = v.y * inv;
    unsigned h, l;
    split2(r0, r1, h, l);
    oh[(size_t)row * 256 + t] = h;
    ol[(size_t)row * 256 + t] = l;
}

// ------------------------- MaxSim reduce + output --------------------------
__global__ void sim_out_kernel(const float* __restrict__ cf,
                               const float* __restrict__ cv,
                               float* __restrict__ out) {
    int p = blockIdx.x * 256 + threadIdx.x;  // 65536 pairs
    int i = p >> 8;
    int j = p & 255;
    const float* pf = cf + (size_t)i * NFR + j * NF;
    float mf = -1e30f;
#pragma unroll
    for (int f = 0; f < NF; f++) mf = fmaxf(mf, pf[f]);
    const float* pv = cv + (size_t)i * NROWS + j * NS;
    float mv = -1e30f;
#pragma unroll
    for (int v = 0; v < NS; v++) mv = fmaxf(mv, pv[v]);
    out[p]               = mf + mv;
    out[NB * NB + p]     = mf;
    out[2 * NB * NB + p] = mv;
}

// ------------------------- launcher ----------------------------------------
extern "C" void kernel_launch(void* const* d_in, const int* in_sizes, int n_in,
                              void* d_out, int out_size) {
    const float* text  = (const float*)d_in[0];
    const float* fr    = (const float*)d_in[1];
    const float* ex    = (const float*)d_in[2];
    const float* Wqkv  = (const float*)d_in[3];
    const float* bqkv  = (const float*)d_in[4];
    const float* Wo    = (const float*)d_in[5];
    const float* bo    = (const float*)d_in[6];
    const float* ln1w  = (const float*)d_in[7];
    const float* ln1b  = (const float*)d_in[8];
    const float* W1    = (const float*)d_in[9];
    const float* b1    = (const float*)d_in[10];
    const float* W2    = (const float*)d_in[11];
    const float* b2    = (const float*)d_in[12];
    const float* ln2w  = (const float*)d_in[13];
    const float* ln2b  = (const float*)d_in[14];
    float* out = (float*)d_out;

    float *px, *pqkv, *pproj, *pcf, *pcv;
    unsigned *pxh, *pxl, *path, *patl, *pffh, *pffl;
    unsigned *pwqkvh, *pwqkvl, *pwoh, *pwol, *pw1h, *pw1l, *pw2h, *pw2l;
    unsigned *ptnh, *ptnl, *pfnh, *pfnl, *pvnh, *pvnl;
    cudaGetSymbolAddress((void**)&px,     g_x);
    cudaGetSymbolAddress((void**)&pqkv,   g_qkv);
    cudaGetSymbolAddress((void**)&pproj,  g_proj);
    cudaGetSymbolAddress((void**)&pcf,    g_cf);
    cudaGetSymbolAddress((void**)&pcv,    g_cv);
    cudaGetSymbolAddress((void**)&pxh,    g_xh);
    cudaGetSymbolAddress((void**)&pxl,    g_xl);
    cudaGetSymbolAddress((void**)&path,   g_ath);
    cudaGetSymbolAddress((void**)&patl,   g_atl);
    cudaGetSymbolAddress((void**)&pffh,   g_ffh);
    cudaGetSymbolAddress((void**)&pffl,   g_ffl);
    cudaGetSymbolAddress((void**)&pwqkvh, g_wqkvh);
    cudaGetSymbolAddress((void**)&pwqkvl, g_wqkvl);
    cudaGetSymbolAddress((void**)&pwoh,   g_woh);
    cudaGetSymbolAddress((void**)&pwol,   g_wol);
    cudaGetSymbolAddress((void**)&pw1h,   g_w1h);
    cudaGetSymbolAddress((void**)&pw1l,   g_w1l);
    cudaGetSymbolAddress((void**)&pw2h,   g_w2h);
    cudaGetSymbolAddress((void**)&pw2l,   g_w2l);
    cudaGetSymbolAddress((void**)&ptnh,   g_tnh);
    cudaGetSymbolAddress((void**)&ptnl,   g_tnl);
    cudaGetSymbolAddress((void**)&pfnh,   g_fnh);
    cudaGetSymbolAddress((void**)&pfnl,   g_fnl);
    cudaGetSymbolAddress((void**)&pvnh,   g_vnh);
    cudaGetSymbolAddress((void**)&pvnl,   g_vnl);

    cudaFuncSetAttribute(mma_gemm, cudaFuncAttributeMaxDynamicSharedMemorySize, TC_SMEM);

    // weight pre-splits (cheap, memory-bound)
    {
        int nw;
        nw = NL * 3 * DM * DM / 2;
        split_pairs<<<(nw + 255) / 256, 256>>>(Wqkv, pwqkvh, pwqkvl, nw);
        nw = NL * DM * DM / 2;
        split_pairs<<<(nw + 255) / 256, 256>>>(Wo, pwoh, pwol, nw);
        nw = NL * FFD * DM / 2;
        split_pairs<<<(nw + 255) / 256, 256>>>(W1, pw1h, pw1l, nw);
        nw = NL * DM * FFD / 2;
        split_pairs<<<(nw + 255) / 256, 256>>>(W2, pw2h, pw2l, nw);
    }

    build_x_split<<<(NROWS * DM / 2) / 256, 256>>>(fr, ex, px, pxh, pxl);

    for (int l = 0; l < NL; l++) {
        // QKV: [8192,512] x [1536,512]^T -> fp32
        mma_gemm<<<dim3(3 * DM / 128, NROWS / 128), 512, TC_SMEM>>>(
            pxh, pxl,
            pwqkvh + (size_t)l * 3 * DM * DM / 2, pwqkvl + (size_t)l * 3 * DM * DM / 2,
            bqkv + (size_t)l * 3 * DM, pqkv, nullptr, nullptr,
            NROWS, 3 * DM, DM, 0);
        // attention per (batch, head), writes split output
        attn_split<<<dim3(NB, NH), dim3(32, 32)>>>(pqkv, path, patl);
        // O projection -> fp32
        mma_gemm<<<dim3(DM / 128, NROWS / 128), 512, TC_SMEM>>>(
            path, patl,
            pwoh + (size_t)l * DM * DM / 2, pwol + (size_t)l * DM * DM / 2,
            bo + (size_t)l * DM, pproj, nullptr, nullptr,
            NROWS, DM, DM, 0);
        add_ln_split<<<NROWS, 256>>>(px, pproj, ln1w + (size_t)l * DM,
                                     ln1b + (size_t)l * DM, pxh, pxl);
        // FF1 (+ReLU), writes split output directly
        mma_gemm<<<dim3(FFD / 128, NROWS / 128), 512, TC_SMEM>>>(
            pxh, pxl,
            pw1h + (size_t)l * FFD * DM / 2, pw1l + (size_t)l * FFD * DM / 2,
            b1 + (size_t)l * FFD, nullptr, pffh, pffl,
            NROWS, FFD, DM, 1);
        // FF2 -> fp32
        mma_gemm<<<dim3(DM / 128, NROWS / 128), 512, TC_SMEM>>>(
            pffh, pffl,
            pw2h + (size_t)l * DM * FFD / 2, pw2l + (size_t)l * DM * FFD / 2,
            b2 + (size_t)l * DM, pproj, nullptr, nullptr,
            NROWS, DM, FFD, 0);
        add_ln_split<<<NROWS, 256>>>(px, pproj, ln2w + (size_t)l * DM,
                                     ln2b + (size_t)l * DM, pxh, pxl);
    }

    // normalizations (write split operands only)
    l2norm_split<<<NB, 256>>>(text, ptnh, ptnl);
    l2norm_split<<<NFR, 256>>>(fr, pfnh, pfnl);
    l2norm_split<<<NROWS, 256>>>(px, pvnh, pvnl);

    // similarity dot-product GEMMs -> fp32
    mma_gemm<<<dim3(NFR / 128, NB / 128), 512, TC_SMEM>>>(
        ptnh, ptnl, pfnh, pfnl, nullptr, pcf, nullptr, nullptr, NB, NFR, DM, 0);
    mma_gemm<<<dim3(NROWS / 128, NB / 128), 512, TC_SMEM>>>(
        ptnh, ptnl, pvnh, pvnl, nullptr, pcv, nullptr, nullptr, NB, NROWS, DM, 0);

    // MaxSim + write three output matrices
    sim_out_kernel<<<(NB * NB) / 256, 256>>>(pcf, pcv, out);
}

// round 8
// speedup vs baseline: 2.5592x; 1.0006x over previous
#include <cuda_runtime.h>
#include <cuda_bf16.h>
#include <math.h>
#include <stdint.h>

// Problem constants
#define NL 4
#define DM 512
#define NH 8
#define DH 64
#define FFD 2048
#define NB 256
#define NF 30
#define NS 32
#define NROWS (NB*NS)      // 8192
#define NFR   (NB*NF)      // 7680

// GEMM config: CTA tile 128x128, BK=32, 512 threads (16 warps, 4x4),
// warp tile 32x32 (mt=2 m16 tiles, nt=4 n8 tiles), 3-stage cp.async pipeline.
#define SSTAGES 3
#define MATB 8192                 // bytes per matrix per stage (128 rows x 64B)
#define STAGEB (4*MATB)           // Ah, Al, Bh, Bl
#define TC_SMEM (SSTAGES*STAGEB)  // 98304

// ------------------------- scratch (device globals, no allocs) -------------
__device__ __align__(16) float g_x[NROWS*DM];      // residual stream fp32
__device__ __align__(16) float g_qkv[NROWS*3*DM];  // qkv projection fp32
__device__ __align__(16) float g_proj[NROWS*DM];   // o-proj / ff2 output fp32
__device__ __align__(16) float g_cf[NB*NFR];       // text x frames dots
__device__ __align__(16) float g_cv[NB*NROWS];     // text x video dots

// packed bf16 hi/lo operand buffers (each unsigned = 2 bf16 along K)
__device__ __align__(16) unsigned g_xh [NROWS*DM/2],  g_xl [NROWS*DM/2];
__device__ __align__(16) unsigned g_ath[NROWS*DM/2],  g_atl[NROWS*DM/2];
__device__ __align__(16) unsigned g_ffh[NROWS*FFD/2], g_ffl[NROWS*FFD/2];
__device__ __align__(16) unsigned g_wqkvh[NL*3*DM*DM/2], g_wqkvl[NL*3*DM*DM/2];
__device__ __align__(16) unsigned g_woh [NL*DM*DM/2],    g_wol [NL*DM*DM/2];
__device__ __align__(16) unsigned g_w1h [NL*FFD*DM/2],   g_w1l [NL*FFD*DM/2];
__device__ __align__(16) unsigned g_w2h [NL*DM*FFD/2],   g_w2l [NL*DM*FFD/2];
__device__ __align__(16) unsigned g_tnh[NB*DM/2],   g_tnl[NB*DM/2];
__device__ __align__(16) unsigned g_fnh[NFR*DM/2],  g_fnl[NFR*DM/2];
__device__ __align__(16) unsigned g_vnh[NROWS*DM/2],g_vnl[NROWS*DM/2];

// ------------------------- bf16 hi/lo split helper -------------------------
__device__ __forceinline__ void split2(float f0, float f1, unsigned &h, unsigned &l) {
    __nv_bfloat162 hv = __floats2bfloat162_rn(f0, f1);
    h = reinterpret_cast<unsigned&>(hv);
    float r0 = f0 - __bfloat162float(hv.x);
    float r1 = f1 - __bfloat162float(hv.y);
    __nv_bfloat162 lv = __floats2bfloat162_rn(r0, r1);
    l = reinterpret_cast<unsigned&>(lv);
}

__device__ __forceinline__ uint32_t smem_u32(const void* p) {
    uint32_t a;
    asm("{ .reg .u64 t; cvta.to.shared.u64 t, %1; cvt.u32.u64 %0, t; }"
        : "=r"(a) : "l"(p));
    return a;
}

#define MMA_BF16(d, a, b0, b1) \
    asm volatile("mma.sync.aligned.m16n8k16.row.col.f32.bf16.bf16.f32 " \
                 "{%0,%1,%2,%3}, {%4,%5,%6,%7}, {%8,%9}, {%0,%1,%2,%3};" \
                 : "+f"(d[0]), "+f"(d[1]), "+f"(d[2]), "+f"(d[3]) \
                 : "r"(a[0]), "r"(a[1]), "r"(a[2]), "r"(a[3]), \
                   "r"(b0), "r"(b1))

#define LDSM4(r, addr) \
    asm volatile("ldmatrix.sync.aligned.m8n8.x4.shared.b16 {%0,%1,%2,%3}, [%4];" \
                 : "=r"((r)[0]), "=r"((r)[1]), "=r"((r)[2]), "=r"((r)[3]) \
                 : "r"(addr))

#define CP_ASYNC16(dst, src) \
    asm volatile("cp.async.cg.shared.global [%0], [%1], 16;" \
                 :: "r"(dst), "l"(src) : "memory")

#define CP_COMMIT() asm volatile("cp.async.commit_group;" ::: "memory")
#define CP_WAIT1()  asm volatile("cp.async.wait_group 1;" ::: "memory")

// ------------------------- bf16x3 mma.sync GEMM ----------------------------
// C[M,N] = A[M,K]*B[N,K]^T (+bias)(relu). Operands pre-split bf16 hi/lo pairs.
__global__ __launch_bounds__(512) void mma_gemm(
    const unsigned* __restrict__ Ah, const unsigned* __restrict__ Al,
    const unsigned* __restrict__ Bh, const unsigned* __restrict__ Bl,
    const float* __restrict__ bias, float* __restrict__ C,
    unsigned* __restrict__ Ch, unsigned* __restrict__ Cl,
    int M, int N, int K, int relu)
{
    extern __shared__ __align__(16) char dsm[];
    const uint32_t sbase = smem_u32(dsm);

    const int tid  = threadIdx.x;
    const int warp = tid >> 5;
    const int lane = tid & 31;
    const int g = lane >> 2;        // 0..7
    const int t = lane & 3;         // 0..3
    const int wm = (warp & 3) * 32;
    const int wn = (warp >> 2) * 32;
    const int bm = blockIdx.y * 128;
    const int bn = blockIdx.x * 128;

    // ---- cp.async mapping: each thread loads one 16B chunk per matrix -----
    const int lrow = tid >> 2;      // 0..127
    const int lc   = tid & 3;       // 16B chunk within 64B row
    const int Kc16 = K >> 3;        // 16B chunks per global row
    const uint32_t swoff = lrow * 64 + ((lc ^ ((lrow >> 1) & 3)) << 4);

    const char* gAh = (const char*)Ah + ((size_t)(bm + lrow) * Kc16 + lc) * 16;
    const char* gAl = (const char*)Al + ((size_t)(bm + lrow) * Kc16 + lc) * 16;
    const char* gBh = (const char*)Bh + ((size_t)(bn + lrow) * Kc16 + lc) * 16;
    const char* gBl = (const char*)Bl + ((size_t)(bn + lrow) * Kc16 + lc) * 16;

    auto load_stage = [&](int chunk, int stage) {
        const size_t go = (size_t)chunk * 64;
        const uint32_t d = sbase + stage * STAGEB + swoff;
        CP_ASYNC16(d,            gAh + go);
        CP_ASYNC16(d + MATB,     gAl + go);
        CP_ASYNC16(d + 2*MATB,   gBh + go);
        CP_ASYNC16(d + 3*MATB,   gBl + go);
    };

    // ---- ldmatrix base addresses (stage 0, k-step 0) ----------------------
    const int mat  = lane >> 3;     // 0..3
    const int mrow = lane & 7;      // 0..7
    uint32_t aB[2][2], bB[2][2];    // [term][mt] / [term][pair]
#pragma unroll
    for (int mt = 0; mt < 2; mt++) {
        const int r = wm + mt * 16 + (mat & 1) * 8 + mrow;
        const uint32_t off = r * 64 + ((((unsigned)mat >> 1) ^ ((r >> 1) & 3)) << 4);
        aB[0][mt] = sbase + off;            // Ah
        aB[1][mt] = sbase + MATB + off;     // Al
    }
#pragma unroll
    for (int p = 0; p < 2; p++) {
        const int r = wn + p * 16 + (mat >> 1) * 8 + mrow;
        const uint32_t off = r * 64 + ((((unsigned)mat & 1) ^ ((r >> 1) & 3)) << 4);
        bB[0][p] = sbase + 2*MATB + off;    // Bh
        bB[1][p] = sbase + 3*MATB + off;    // Bl
    }

    float acc[2][4][4];
#pragma unroll
    for (int mt = 0; mt < 2; mt++)
#pragma unroll
        for (int nt = 0; nt < 4; nt++)
#pragma unroll
            for (int i = 0; i < 4; i++) acc[mt][nt][i] = 0.f;

    auto compute = [&](int stage) {
        const uint32_t so = stage * STAGEB;
#pragma unroll
        for (int s = 0; s < 2; s++) {
            const uint32_t sx = (uint32_t)(s << 5);   // k-step toggles bit5
            unsigned ah[2][4], al[2][4], bh[2][4], bl[2][4];
#pragma unroll
            for (int mt = 0; mt < 2; mt++) {
                LDSM4(ah[mt], (aB[0][mt] + so) ^ sx);
                LDSM4(al[mt], (aB[1][mt] + so) ^ sx);
            }
#pragma unroll
            for (int p = 0; p < 2; p++) {
                LDSM4(bh[p], (bB[0][p] + so) ^ sx);
                LDSM4(bl[p], (bB[1][p] + so) ^ sx);
            }
#pragma unroll
            for (int mt = 0; mt < 2; mt++)
#pragma unroll
                for (int nt = 0; nt < 4; nt++) {
                    const int p = nt >> 1, u = (nt & 1) * 2;
                    MMA_BF16(acc[mt][nt], ah[mt], bh[p][u], bh[p][u+1]);
                    MMA_BF16(acc[mt][nt], al[mt], bh[p][u], bh[p][u+1]);
                    MMA_BF16(acc[mt][nt], ah[mt], bl[p][u], bl[p][u+1]);
                }
        }
    };

    const int NC = K >> 5;          // K/32 chunks

    load_stage(0, 0); CP_COMMIT();
    load_stage(1, 1); CP_COMMIT();

    int stage = 0, pstage = 2, pchunk = 2;
    for (int c = 0; c < NC; c++) {
        CP_WAIT1();
        __syncthreads();
        if (pchunk < NC) load_stage(pchunk, pstage);
        CP_COMMIT();
        compute(stage);
        stage = (stage + 1 == SSTAGES) ? 0 : stage + 1;
        pstage = (pstage + 1 == SSTAGES) ? 0 : pstage + 1;
        pchunk++;
    }

    // ---- epilogue ---------------------------------------------------------
#pragma unroll
    for (int mt = 0; mt < 2; mt++) {
        const int r0 = bm + wm + mt * 16 + g;
#pragma unroll
        for (int nt = 0; nt < 4; nt++) {
            const int c = bn + wn + nt * 8 + 2 * t;
            float b0 = 0.f, b1 = 0.f;
            if (bias) { b0 = __ldg(bias + c); b1 = __ldg(bias + c + 1); }
            float v00 = acc[mt][nt][0] + b0;
            float v01 = acc[mt][nt][1] + b1;
            float v10 = acc[mt][nt][2] + b0;
            float v11 = acc[mt][nt][3] + b1;
            if (relu) {
                v00 = fmaxf(v00, 0.f); v01 = fmaxf(v01, 0.f);
                v10 = fmaxf(v10, 0.f); v11 = fmaxf(v11, 0.f);
            }
            if (Ch) {
                unsigned h, l;
                split2(v00, v01, h, l);
                size_t wi = ((size_t)r0 * N + c) >> 1;
                Ch[wi] = h; Cl[wi] = l;
                split2(v10, v11, h, l);
                wi = ((size_t)(r0 + 8) * N + c) >> 1;
                Ch[wi] = h; Cl[wi] = l;
            } else {
                *reinterpret_cast<float2*>(C + (size_t)r0 * N + c) = make_float2(v00, v01);
                *reinterpret_cast<float2*>(C + (size_t)(r0 + 8) * N + c) = make_float2(v10, v11);
            }
        }
    }
}

// ------------------------- generic fp32 -> split pre-pass -------------------
__global__ void split_pairs(const float* __restrict__ src,
                            unsigned* __restrict__ dh, unsigned* __restrict__ dl,
                            int nw) {
    int i = blockIdx.x * 256 + threadIdx.x;
    if (i < nw) {
        float2 v = *reinterpret_cast<const float2*>(src + 2 * (size_t)i);
        unsigned h, l;
        split2(v.x, v.y, h, l);
        dh[i] = h; dl[i] = l;
    }
}

// ------------------------- build x = [frames; expansion] (+split) ----------
__global__ void build_x_split(const float* __restrict__ fr,
                              const float* __restrict__ ex,
                              float* __restrict__ x,
                              unsigned* __restrict__ xh, unsigned* __restrict__ xl) {
    int widx = blockIdx.x * 256 + threadIdx.x;  // over NROWS*256 word-pairs
    int c2 = widx & 255;
    int row = widx >> 8;
    int b = row >> 5;
    int s = row & 31;
    float2 v = (s < NF)
        ? *reinterpret_cast<const float2*>(fr + ((size_t)(b * NF + s) * DM + 2 * c2))
        : *reinterpret_cast<const float2*>(ex + ((size_t)(s - NF) * DM + 2 * c2));
    *reinterpret_cast<float2*>(x + (size_t)row * DM + 2 * c2) = v;
    unsigned h, l;
    split2(v.x, v.y, h, l);
    xh[widx] = h; xl[widx] = l;
}

// ------------------------- attention (+split epilogue) ---------------------
__global__ __launch_bounds__(1024) void attn_split(const float* __restrict__ qkv,
                                                   unsigned* __restrict__ oh,
                                                   unsigned* __restrict__ ol) {
    const int b = blockIdx.x;
    const int hh = blockIdx.y;
    __shared__ float sq[32][65];
    __shared__ float sk[32][65];
    __shared__ float sv[32][65];
    __shared__ float sp[32][33];
    const int tx = threadIdx.x;   // 0..31
    const int ty = threadIdx.y;   // 0..31

    const float* base = qkv + (size_t)(b * NS + ty) * (3 * DM) + hh * DH;
    sq[ty][tx]      = base[tx];
    sq[ty][tx + 32] = base[tx + 32];
    sk[ty][tx]      = base[DM + tx];
    sk[ty][tx + 32] = base[DM + tx + 32];
    sv[ty][tx]      = base[2 * DM + tx];
    sv[ty][tx + 32] = base[2 * DM + tx + 32];
    __syncthreads();

    float acc = 0.f;
#pragma unroll
    for (int d = 0; d < DH; d++) acc += sq[ty][d] * sk[tx][d];
    acc *= 0.125f; // 1/sqrt(64)

    float m = acc;
#pragma unroll
    for (int o = 16; o; o >>= 1) m = fmaxf(m, __shfl_xor_sync(0xffffffffu, m, o));
    float e = __expf(acc - m);
    float s = e;
#pragma unroll
    for (int o = 16; o; o >>= 1) s += __shfl_xor_sync(0xffffffffu, s, o);
    sp[ty][tx] = e / s;
    __syncthreads();

    float o0 = 0.f, o1 = 0.f;
#pragma unroll
    for (int k = 0; k < NS; k++) {
        float p = sp[ty][k];
        o0 += p * sv[k][2 * tx];
        o1 += p * sv[k][2 * tx + 1];
    }
    unsigned h, l;
    split2(o0, o1, h, l);
    size_t wi = ((size_t)(b * NS + ty) * DM + hh * DH) / 2 + tx;
    oh[wi] = h; ol[wi] = l;
}

// ------------------------- block reduce (256 threads) ----------------------
__device__ __forceinline__ float block_reduce_256(float v, float* sh) {
    __syncthreads();
    int lane = threadIdx.x & 31, wid = threadIdx.x >> 5;
#pragma unroll
    for (int o = 16; o; o >>= 1) v += __shfl_xor_sync(0xffffffffu, v, o);
    if (lane == 0) sh[wid] = v;
    __syncthreads();
    if (threadIdx.x == 0) {
        float t = 0.f;
#pragma unroll
        for (int w = 0; w < 8; w++) t += sh[w];
        sh[8] = t;
    }
    __syncthreads();
    return sh[8];
}

// ------------------------- x = LayerNorm(x + o) (+split) -------------------
__global__ __launch_bounds__(256) void add_ln_split(float* __restrict__ x,
                                                    const float* __restrict__ o,
                                                    const float* __restrict__ g,
                                                    const float* __restrict__ bt,
                                                    unsigned* __restrict__ xh,
                                                    unsigned* __restrict__ xl) {
    __shared__ float red[16];
    const int row = blockIdx.x;
    const int t = threadIdx.x;   // pair index 0..255
    float2 xv = *reinterpret_cast<const float2*>(x + (size_t)row * DM + 2 * t);
    float2 ov = *reinterpret_cast<const float2*>(o + (size_t)row * DM + 2 * t);
    float v0 = xv.x + ov.x;
    float v1 = xv.y + ov.y;
    float mean = block_reduce_256(v0 + v1, red) * (1.f / DM);
    float d0 = v0 - mean, d1 = v1 - mean;
    float var = block_reduce_256(d0 * d0 + d1 * d1, red) * (1.f / DM);
    float rs = rsqrtf(var + 1e-5f);
    float2 gg = *reinterpret_cast<const float2*>(g + 2 * t);
    float2 bb = *reinterpret_cast<const float2*>(bt + 2 * t);
    float r0 = d0 * rs * gg.x + bb.x;
    float r1 = d1 * rs * gg.y + bb.y;
    *reinterpret_cast<float2*>(x + (size_t)row * DM + 2 * t) = make_float2(r0, r1);
    unsigned h, l;
    split2(r0, r1, h, l);
    xh[(size_t)row * 256 + t] = h;
    xl[(size_t)row * 256 + t] = l;
}

// ------------------------- row l2 normalize (+split only) ------------------
__global__ __launch_bounds__(256) void l2norm_split(const float* __restrict__ in,
                                                    unsigned* __restrict__ oh,
                                                    unsigned* __restrict__ ol) {
    __shared__ float red[16];
    const int row = blockIdx.x;
    const int t = threadIdx.x;
    float2 v = *reinterpret_cast<const float2*>(in + (size_t)row * DM + 2 * t);
    float ss = block_reduce_256(v.x * v.x + v.y * v.y, red);
    float inv = 1.f / fmaxf(sqrtf(ss), 1e-12f);
    float r0 = v.x * inv, r1 = v.y * inv;
    unsigned h, l;
    split2(r0, r1, h, l);
    oh[(size_t)row * 256 + t] = h;
    ol[(size_t)row * 256 + t] = l;
}

// ------------------------- MaxSim reduce + output --------------------------
__global__ void sim_out_kernel(const float* __restrict__ cf,
                               const float* __restrict__ cv,
                               float* __restrict__ out) {
    int p = blockIdx.x * 256 + threadIdx.x;  // 65536 pairs
    int i = p >> 8;
    int j = p & 255;
    const float* pf = cf + (size_t)i * NFR + j * NF;
    float mf = -1e30f;
#pragma unroll
    for (int f = 0; f < NF; f++) mf = fmaxf(mf, pf[f]);
    const float* pv = cv + (size_t)i * NROWS + j * NS;
    float mv = -1e30f;
#pragma unroll
    for (int v = 0; v < NS; v++) mv = fmaxf(mv, pv[v]);
    out[p]               = mf + mv;
    out[NB * NB + p]     = mf;
    out[2 * NB * NB + p] = mv;
}

// ------------------------- launcher ----------------------------------------
extern "C" void kernel_launch(void* const* d_in, const int* in_sizes, int n_in,
                              void* d_out, int out_size) {
    const float* text  = (const float*)d_in[0];
    const float* fr    = (const float*)d_in[1];
    const float* ex    = (const float*)d_in[2];
    const float* Wqkv  = (const float*)d_in[3];
    const float* bqkv  = (const float*)d_in[4];
    const float* Wo    = (const float*)d_in[5];
    const float* bo    = (const float*)d_in[6];
    const float* ln1w  = (const float*)d_in[7];
    const float* ln1b  = (const float*)d_in[8];
    const float* W1    = (const float*)d_in[9];
    const float* b1    = (const float*)d_in[10];
    const float* W2    = (const float*)d_in[11];
    const float* b2    = (const float*)d_in[12];
    const float* ln2w  = (const float*)d_in[13];
    const float* ln2b  = (const float*)d_in[14];
    float* out = (float*)d_out;

    float *px, *pqkv, *pproj, *pcf, *pcv;
    unsigned *pxh, *pxl, *path, *patl, *pffh, *pffl;
    unsigned *pwqkvh, *pwqkvl, *pwoh, *pwol, *pw1h, *pw1l, *pw2h, *pw2l;
    unsigned *ptnh, *ptnl, *pfnh, *pfnl, *pvnh, *pvnl;
    cudaGetSymbolAddress((void**)&px,     g_x);
    cudaGetSymbolAddress((void**)&pqkv,   g_qkv);
    cudaGetSymbolAddress((void**)&pproj,  g_proj);
    cudaGetSymbolAddress((void**)&pcf,    g_cf);
    cudaGetSymbolAddress((void**)&pcv,    g_cv);
    cudaGetSymbolAddress((void**)&pxh,    g_xh);
    cudaGetSymbolAddress((void**)&pxl,    g_xl);
    cudaGetSymbolAddress((void**)&path,   g_ath);
    cudaGetSymbolAddress((void**)&patl,   g_atl);
    cudaGetSymbolAddress((void**)&pffh,   g_ffh);
    cudaGetSymbolAddress((void**)&pffl,   g_ffl);
    cudaGetSymbolAddress((void**)&pwqkvh, g_wqkvh);
    cudaGetSymbolAddress((void**)&pwqkvl, g_wqkvl);
    cudaGetSymbolAddress((void**)&pwoh,   g_woh);
    cudaGetSymbolAddress((void**)&pwol,   g_wol);
    cudaGetSymbolAddress((void**)&pw1h,   g_w1h);
    cudaGetSymbolAddress((void**)&pw1l,   g_w1l);
    cudaGetSymbolAddress((void**)&pw2h,   g_w2h);
    cudaGetSymbolAddress((void**)&pw2l,   g_w2l);
    cudaGetSymbolAddress((void**)&ptnh,   g_tnh);
    cudaGetSymbolAddress((void**)&ptnl,   g_tnl);
    cudaGetSymbolAddress((void**)&pfnh,   g_fnh);
    cudaGetSymbolAddress((void**)&pfnl,   g_fnl);
    cudaGetSymbolAddress((void**)&pvnh,   g_vnh);
    cudaGetSymbolAddress((void**)&pvnl,   g_vnl);

    cudaFuncSetAttribute(mma_gemm, cudaFuncAttributeMaxDynamicSharedMemorySize, TC_SMEM);

    // weight pre-splits (cheap, memory-bound)
    {
        int nw;
        nw = NL * 3 * DM * DM / 2;
        split_pairs<<<(nw + 255) / 256, 256>>>(Wqkv, pwqkvh, pwqkvl, nw);
        nw = NL * DM * DM / 2;
        split_pairs<<<(nw + 255) / 256, 256>>>(Wo, pwoh, pwol, nw);
        nw = NL * FFD * DM / 2;
        split_pairs<<<(nw + 255) / 256, 256>>>(W1, pw1h, pw1l, nw);
        nw = NL * DM * FFD / 2;
        split_pairs<<<(nw + 255) / 256, 256>>>(W2, pw2h, pw2l, nw);
    }

    build_x_split<<<(NROWS * DM / 2) / 256, 256>>>(fr, ex, px, pxh, pxl);

    for (int l = 0; l < NL; l++) {
        // QKV: [8192,512] x [1536,512]^T -> fp32
        mma_gemm<<<dim3(3 * DM / 128, NROWS / 128), 512, TC_SMEM>>>(
            pxh, pxl,
            pwqkvh + (size_t)l * 3 * DM * DM / 2, pwqkvl + (size_t)l * 3 * DM * DM / 2,
            bqkv + (size_t)l * 3 * DM, pqkv, nullptr, nullptr,
            NROWS, 3 * DM, DM, 0);
        // attention per (batch, head), writes split output
        attn_split<<<dim3(NB, NH), dim3(32, 32)>>>(pqkv, path, patl);
        // O projection -> fp32
        mma_gemm<<<dim3(DM / 128, NROWS / 128), 512, TC_SMEM>>>(
            path, patl,
            pwoh + (size_t)l * DM * DM / 2, pwol + (size_t)l * DM * DM / 2,
            bo + (size_t)l * DM, pproj, nullptr, nullptr,
            NROWS, DM, DM, 0);
        add_ln_split<<<NROWS, 256>>>(px, pproj, ln1w + (size_t)l * DM,
                                     ln1b + (size_t)l * DM, pxh, pxl);
        // FF1 (+ReLU), writes split output directly
        mma_gemm<<<dim3(FFD / 128, NROWS / 128), 512, TC_SMEM>>>(
            pxh, pxl,
            pw1h + (size_t)l * FFD * DM / 2, pw1l + (size_t)l * FFD * DM / 2,
            b1 + (size_t)l * FFD, nullptr, pffh, pffl,
            NROWS, FFD, DM, 1);
        // FF2 -> fp32
        mma_gemm<<<dim3(DM / 128, NROWS / 128), 512, TC_SMEM>>>(
            pffh, pffl,
            pw2h + (size_t)l * DM * FFD / 2, pw2l + (size_t)l * DM * FFD / 2,
            b2 + (size_t)l * DM, pproj, nullptr, nullptr,
            NROWS, DM, FFD, 0);
        add_ln_split<<<NROWS, 256>>>(px, pproj, ln2w + (size_t)l * DM,
                                     ln2b + (size_t)l * DM, pxh, pxl);
    }

    // normalizations (write split operands only)
    l2norm_split<<<NB, 256>>>(text, ptnh, ptnl);
    l2norm_split<<<NFR, 256>>>(fr, pfnh, pfnl);
    l2norm_split<<<NROWS, 256>>>(px, pvnh, pvnl);

    // similarity dot-product GEMMs -> fp32
    mma_gemm<<<dim3(NFR / 128, NB / 128), 512, TC_SMEM>>>(
        ptnh, ptnl, pfnh, pfnl, nullptr, pcf, nullptr, nullptr, NB, NFR, DM, 0);
    mma_gemm<<<dim3(NROWS / 128, NB / 128), 512, TC_SMEM>>>(
        ptnh, ptnl, pvnh, pvnl, nullptr, pcv, nullptr, nullptr, NB, NROWS, DM, 0);

    // MaxSim + write three output matrices
    sim_out_kernel<<<(NB * NB) / 256, 256>>>(pcf, pcv, out);
}

// round 9
// speedup vs baseline: 2.5625x; 1.0013x over previous
#include <cuda_runtime.h>
#include <cuda_bf16.h>
#include <math.h>
#include <stdint.h>

// Problem constants
#define NL 4
#define DM 512
#define NH 8
#define DH 64
#define FFD 2048
#define NB 256
#define NF 30
#define NS 32
#define NROWS (NB*NS)      // 8192
#define NFR   (NB*NF)      // 7680

// GEMM config: CTA tile 128x128, BK=32, 512 threads (16 warps, 4x4),
// warp tile 32x32 (mt=2 m16 tiles, nt=4 n8 tiles), 3-stage cp.async pipeline.
#define SSTAGES 3
#define MATB 8192                 // bytes per matrix per stage (128 rows x 64B)
#define STAGEB (4*MATB)           // Ah, Al, Bh, Bl
#define TC_SMEM (SSTAGES*STAGEB)  // 98304

// ------------------------- scratch (device globals, no allocs) -------------
__device__ __align__(16) float g_x[NROWS*DM];      // residual stream fp32
__device__ __align__(16) float g_qkv[NROWS*3*DM];  // qkv projection fp32
__device__ __align__(16) float g_proj[NROWS*DM];   // o-proj / ff2 output fp32
__device__ __align__(16) float g_cf[NB*NFR];       // text x frames dots
__device__ __align__(16) float g_cv[NB*NROWS];     // text x video dots

// packed bf16 hi/lo operand buffers (each unsigned = 2 bf16 along K)
__device__ __align__(16) unsigned g_xh [NROWS*DM/2],  g_xl [NROWS*DM/2];
__device__ __align__(16) unsigned g_ath[NROWS*DM/2],  g_atl[NROWS*DM/2];
__device__ __align__(16) unsigned g_ffh[NROWS*FFD/2], g_ffl[NROWS*FFD/2];
__device__ __align__(16) unsigned g_wqkvh[NL*3*DM*DM/2], g_wqkvl[NL*3*DM*DM/2];
__device__ __align__(16) unsigned g_woh [NL*DM*DM/2],    g_wol [NL*DM*DM/2];
__device__ __align__(16) unsigned g_w1h [NL*FFD*DM/2],   g_w1l [NL*FFD*DM/2];
__device__ __align__(16) unsigned g_w2h [NL*DM*FFD/2],   g_w2l [NL*DM*FFD/2];
__device__ __align__(16) unsigned g_tnh[NB*DM/2],   g_tnl[NB*DM/2];
__device__ __align__(16) unsigned g_fnh[NFR*DM/2],  g_fnl[NFR*DM/2];
__device__ __align__(16) unsigned g_vnh[NROWS*DM/2],g_vnl[NROWS*DM/2];

// ------------------------- bf16 hi/lo split helper -------------------------
__device__ __forceinline__ void split2(float f0, float f1, unsigned &h, unsigned &l) {
    __nv_bfloat162 hv = __floats2bfloat162_rn(f0, f1);
    h = reinterpret_cast<unsigned&>(hv);
    float r0 = f0 - __bfloat162float(hv.x);
    float r1 = f1 - __bfloat162float(hv.y);
    __nv_bfloat162 lv = __floats2bfloat162_rn(r0, r1);
    l = reinterpret_cast<unsigned&>(lv);
}

__device__ __forceinline__ uint32_t smem_u32(const void* p) {
    uint32_t a;
    asm("{ .reg .u64 t; cvta.to.shared.u64 t, %1; cvt.u32.u64 %0, t; }"
        : "=r"(a) : "l"(p));
    return a;
}

#define MMA_BF16(d, a, b0, b1) \
    asm volatile("mma.sync.aligned.m16n8k16.row.col.f32.bf16.bf16.f32 " \
                 "{%0,%1,%2,%3}, {%4,%5,%6,%7}, {%8,%9}, {%0,%1,%2,%3};" \
                 : "+f"(d[0]), "+f"(d[1]), "+f"(d[2]), "+f"(d[3]) \
                 : "r"(a[0]), "r"(a[1]), "r"(a[2]), "r"(a[3]), \
                   "r"(b0), "r"(b1))

#define LDSM4(r, addr) \
    asm volatile("ldmatrix.sync.aligned.m8n8.x4.shared.b16 {%0,%1,%2,%3}, [%4];" \
                 : "=r"((r)[0]), "=r"((r)[1]), "=r"((r)[2]), "=r"((r)[3]) \
                 : "r"(addr))

#define CP_ASYNC16(dst, src) \
    asm volatile("cp.async.cg.shared.global [%0], [%1], 16;" \
                 :: "r"(dst), "l"(src) : "memory")

#define CP_COMMIT() asm volatile("cp.async.commit_group;" ::: "memory")
#define CP_WAIT1()  asm volatile("cp.async.wait_group 1;" ::: "memory")

// ------------------------- bf16x3 mma.sync GEMM ----------------------------
// C[M,N] = A[M,K]*B[N,K]^T (+bias)(relu). Operands pre-split bf16 hi/lo pairs.
__global__ __launch_bounds__(512) void mma_gemm(
    const unsigned* __restrict__ Ah, const unsigned* __restrict__ Al,
    const unsigned* __restrict__ Bh, const unsigned* __restrict__ Bl,
    const float* __restrict__ bias, float* __restrict__ C,
    unsigned* __restrict__ Ch, unsigned* __restrict__ Cl,
    int M, int N, int K, int relu)
{
    extern __shared__ __align__(16) char dsm[];
    const uint32_t sbase = smem_u32(dsm);

    const int tid  = threadIdx.x;
    const int warp = tid >> 5;
    const int lane = tid & 31;
    const int g = lane >> 2;        // 0..7
    const int t = lane & 3;         // 0..3
    const int wm = (warp & 3) * 32;
    const int wn = (warp >> 2) * 32;
    const int bm = blockIdx.y * 128;
    const int bn = blockIdx.x * 128;

    // ---- cp.async mapping: each thread loads one 16B chunk per matrix -----
    const int lrow = tid >> 2;      // 0..127
    const int lc   = tid & 3;       // 16B chunk within 64B row
    const int Kc16 = K >> 3;        // 16B chunks per global row
    const uint32_t swoff = lrow * 64 + ((lc ^ ((lrow >> 1) & 3)) << 4);

    const char* gAh = (const char*)Ah + ((size_t)(bm + lrow) * Kc16 + lc) * 16;
    const char* gAl = (const char*)Al + ((size_t)(bm + lrow) * Kc16 + lc) * 16;
    const char* gBh = (const char*)Bh + ((size_t)(bn + lrow) * Kc16 + lc) * 16;
    const char* gBl = (const char*)Bl + ((size_t)(bn + lrow) * Kc16 + lc) * 16;

    auto load_stage = [&](int chunk, int stage) {
        const size_t go = (size_t)chunk * 64;
        const uint32_t d = sbase + stage * STAGEB + swoff;
        CP_ASYNC16(d,            gAh + go);
        CP_ASYNC16(d + MATB,     gAl + go);
        CP_ASYNC16(d + 2*MATB,   gBh + go);
        CP_ASYNC16(d + 3*MATB,   gBl + go);
    };

    // ---- ldmatrix base addresses (stage 0, k-step 0) ----------------------
    const int mat  = lane >> 3;     // 0..3
    const int mrow = lane & 7;      // 0..7
    uint32_t aB[2][2], bB[2][2];    // [term][mt] / [term][pair]
#pragma unroll
    for (int mt = 0; mt < 2; mt++) {
        const int r = wm + mt * 16 + (mat & 1) * 8 + mrow;
        const uint32_t off = r * 64 + ((((unsigned)mat >> 1) ^ ((r >> 1) & 3)) << 4);
        aB[0][mt] = sbase + off;            // Ah
        aB[1][mt] = sbase + MATB + off;     // Al
    }
#pragma unroll
    for (int p = 0; p < 2; p++) {
        const int r = wn + p * 16 + (mat >> 1) * 8 + mrow;
        const uint32_t off = r * 64 + ((((unsigned)mat & 1) ^ ((r >> 1) & 3)) << 4);
        bB[0][p] = sbase + 2*MATB + off;    // Bh
        bB[1][p] = sbase + 3*MATB + off;    // Bl
    }

    float acc[2][4][4];
#pragma unroll
    for (int mt = 0; mt < 2; mt++)
#pragma unroll
        for (int nt = 0; nt < 4; nt++)
#pragma unroll
            for (int i = 0; i < 4; i++) acc[mt][nt][i] = 0.f;

    auto compute = [&](int stage) {
        const uint32_t so = stage * STAGEB;
#pragma unroll
        for (int s = 0; s < 2; s++) {
            const uint32_t sx = (uint32_t)(s << 5);   // k-step toggles bit5
            unsigned ah[2][4], al[2][4], bh[2][4], bl[2][4];
#pragma unroll
            for (int mt = 0; mt < 2; mt++) {
                LDSM4(ah[mt], (aB[0][mt] + so) ^ sx);
                LDSM4(al[mt], (aB[1][mt] + so) ^ sx);
            }
#pragma unroll
            for (int p = 0; p < 2; p++) {
                LDSM4(bh[p], (bB[0][p] + so) ^ sx);
                LDSM4(bl[p], (bB[1][p] + so) ^ sx);
            }
#pragma unroll
            for (int mt = 0; mt < 2; mt++)
#pragma unroll
                for (int nt = 0; nt < 4; nt++) {
                    const int p = nt >> 1, u = (nt & 1) * 2;
                    MMA_BF16(acc[mt][nt], ah[mt], bh[p][u], bh[p][u+1]);
                    MMA_BF16(acc[mt][nt], al[mt], bh[p][u], bh[p][u+1]);
                    MMA_BF16(acc[mt][nt], ah[mt], bl[p][u], bl[p][u+1]);
                }
        }
    };

    const int NC = K >> 5;          // K/32 chunks

    load_stage(0, 0); CP_COMMIT();
    load_stage(1, 1); CP_COMMIT();

    int stage = 0, pstage = 2, pchunk = 2;
    for (int c = 0; c < NC; c++) {
        CP_WAIT1();
        __syncthreads();
        if (pchunk < NC) load_stage(pchunk, pstage);
        CP_COMMIT();
        compute(stage);
        stage = (stage + 1 == SSTAGES) ? 0 : stage + 1;
        pstage = (pstage + 1 == SSTAGES) ? 0 : pstage + 1;
        pchunk++;
    }

    // ---- epilogue ---------------------------------------------------------
#pragma unroll
    for (int mt = 0; mt < 2; mt++) {
        const int r0 = bm + wm + mt * 16 + g;
#pragma unroll
        for (int nt = 0; nt < 4; nt++) {
            const int c = bn + wn + nt * 8 + 2 * t;
            float b0 = 0.f, b1 = 0.f;
            if (bias) { b0 = __ldg(bias + c); b1 = __ldg(bias + c + 1); }
            float v00 = acc[mt][nt][0] + b0;
            float v01 = acc[mt][nt][1] + b1;
            float v10 = acc[mt][nt][2] + b0;
            float v11 = acc[mt][nt][3] + b1;
            if (relu) {
                v00 = fmaxf(v00, 0.f); v01 = fmaxf(v01, 0.f);
                v10 = fmaxf(v10, 0.f); v11 = fmaxf(v11, 0.f);
            }
            if (Ch) {
                unsigned h, l;
                split2(v00, v01, h, l);
                size_t wi = ((size_t)r0 * N + c) >> 1;
                Ch[wi] = h; Cl[wi] = l;
                split2(v10, v11, h, l);
                wi = ((size_t)(r0 + 8) * N + c) >> 1;
                Ch[wi] = h; Cl[wi] = l;
            } else {
                *reinterpret_cast<float2*>(C + (size_t)r0 * N + c) = make_float2(v00, v01);
                *reinterpret_cast<float2*>(C + (size_t)(r0 + 8) * N + c) = make_float2(v10, v11);
            }
        }
    }
}

// ------------------------- generic fp32 -> split pre-pass -------------------
__global__ void split_pairs(const float* __restrict__ src,
                            unsigned* __restrict__ dh, unsigned* __restrict__ dl,
                            int nw) {
    int i = blockIdx.x * 256 + threadIdx.x;
    if (i < nw) {
        float2 v = *reinterpret_cast<const float2*>(src + 2 * (size_t)i);
        unsigned h, l;
        split2(v.x, v.y, h, l);
        dh[i] = h; dl[i] = l;
    }
}

// ------------------------- build x = [frames; expansion] (+split) ----------
__global__ void build_x_split(const float* __restrict__ fr,
                              const float* __restrict__ ex,
                              float* __restrict__ x,
                              unsigned* __restrict__ xh, unsigned* __restrict__ xl) {
    int widx = blockIdx.x * 256 + threadIdx.x;  // over NROWS*256 word-pairs
    int c2 = widx & 255;
    int row = widx >> 8;
    int b = row >> 5;
    int s = row & 31;
    float2 v = (s < NF)
        ? *reinterpret_cast<const float2*>(fr + ((size_t)(b * NF + s) * DM + 2 * c2))
        : *reinterpret_cast<const float2*>(ex + ((size_t)(s - NF) * DM + 2 * c2));
    *reinterpret_cast<float2*>(x + (size_t)row * DM + 2 * c2) = v;
    unsigned h, l;
    split2(v.x, v.y, h, l);
    xh[widx] = h; xl[widx] = l;
}

// ------------------------- attention (+split epilogue) ---------------------
__global__ __launch_bounds__(1024) void attn_split(const float* __restrict__ qkv,
                                                   unsigned* __restrict__ oh,
                                                   unsigned* __restrict__ ol) {
    const int b = blockIdx.x;
    const int hh = blockIdx.y;
    __shared__ float sq[32][65];
    __shared__ float sk[32][65];
    __shared__ float sv[32][65];
    __shared__ float sp[32][33];
    const int tx = threadIdx.x;   // 0..31
    const int ty = threadIdx.y;   // 0..31

    const float* base = qkv + (size_t)(b * NS + ty) * (3 * DM) + hh * DH;
    sq[ty][tx]      = base[tx];
    sq[ty][tx + 32] = base[tx + 32];
    sk[ty][tx]      = base[DM + tx];
    sk[ty][tx + 32] = base[DM + tx + 32];
    sv[ty][tx]      = base[2 * DM + tx];
    sv[ty][tx + 32] = base[2 * DM + tx + 32];
    __syncthreads();

    float acc = 0.f;
#pragma unroll
    for (int d = 0; d < DH; d++) acc += sq[ty][d] * sk[tx][d];
    acc *= 0.125f; // 1/sqrt(64)

    float m = acc;
#pragma unroll
    for (int o = 16; o; o >>= 1) m = fmaxf(m, __shfl_xor_sync(0xffffffffu, m, o));
    float e = __expf(acc - m);
    float s = e;
#pragma unroll
    for (int o = 16; o; o >>= 1) s += __shfl_xor_sync(0xffffffffu, s, o);
    sp[ty][tx] = e / s;
    __syncthreads();

    float o0 = 0.f, o1 = 0.f;
#pragma unroll
    for (int k = 0; k < NS; k++) {
        float p = sp[ty][k];
        o0 += p * sv[k][2 * tx];
        o1 += p * sv[k][2 * tx + 1];
    }
    unsigned h, l;
    split2(o0, o1, h, l);
    size_t wi = ((size_t)(b * NS + ty) * DM + hh * DH) / 2 + tx;
    oh[wi] = h; ol[wi] = l;
}

// ------------------------- block reduce (256 threads) ----------------------
__device__ __forceinline__ float block_reduce_256(float v, float* sh) {
    __syncthreads();
    int lane = threadIdx.x & 31, wid = threadIdx.x >> 5;
#pragma unroll
    for (int o = 16; o; o >>= 1) v += __shfl_xor_sync(0xffffffffu, v, o);
    if (lane == 0) sh[wid] = v;
    __syncthreads();
    if (threadIdx.x == 0) {
        float t = 0.f;
#pragma unroll
        for (int w = 0; w < 8; w++) t += sh[w];
        sh[8] = t;
    }
    __syncthreads();
    return sh[8];
}

// ------------------------- x = LayerNorm(x + o) (+split) -------------------
__global__ __launch_bounds__(256) void add_ln_split(float* __restrict__ x,
                                                    const float* __restrict__ o,
                                                    const float* __restrict__ g,
                                                    const float* __restrict__ bt,
                                                    unsigned* __restrict__ xh,
                                                    unsigned* __restrict__ xl) {
    __shared__ float red[16];
    const int row = blockIdx.x;
    const int t = threadIdx.x;   // pair index 0..255
    float2 xv = *reinterpret_cast<const float2*>(x + (size_t)row * DM + 2 * t);
    float2 ov = *reinterpret_cast<const float2*>(o + (size_t)row * DM + 2 * t);
    float v0 = xv.x + ov.x;
    float v1 = xv.y + ov.y;
    float mean = block_reduce_256(v0 + v1, red) * (1.f / DM);
    float d0 = v0 - mean, d1 = v1 - mean;
    float var = block_reduce_256(d0 * d0 + d1 * d1, red) * (1.f / DM);
    float rs = rsqrtf(var + 1e-5f);
    float2 gg = *reinterpret_cast<const float2*>(g + 2 * t);
    float2 bb = *reinterpret_cast<const float2*>(bt + 2 * t);
    float r0 = d0 * rs * gg.x + bb.x;
    float r1 = d1 * rs * gg.y + bb.y;
    *reinterpret_cast<float2*>(x + (size_t)row * DM + 2 * t) = make_float2(r0, r1);
    unsigned h, l;
    split2(r0, r1, h, l);
    xh[(size_t)row * 256 + t] = h;
    xl[(size_t)row * 256 + t] = l;
}

// ------------------------- row l2 normalize (+split only) ------------------
__global__ __launch_bounds__(256) void l2norm_split(const float* __restrict__ in,
                                                    unsigned* __restrict__ oh,
                                                    unsigned* __restrict__ ol) {
    __shared__ float red[16];
    const int row = blockIdx.x;
    const int t = threadIdx.x;
    float2 v = *reinterpret_cast<const float2*>(in + (size_t)row * DM + 2 * t);
    float ss = block_reduce_256(v.x * v.x + v.y * v.y, red);
    float inv = 1.f / fmaxf(sqrtf(ss), 1e-12f);
    float r0 = v.x * inv, r1 = v.y * inv;
    unsigned h, l;
    split2(r0, r1, h, l);
    oh[(size_t)row * 256 + t] = h;
    ol[(size_t)row * 256 + t] = l;
}

// ------------------------- MaxSim reduce + output --------------------------
__global__ void sim_out_kernel(const float* __restrict__ cf,
                               const float* __restrict__ cv,
                               float* __restrict__ out) {
    int p = blockIdx.x * 256 + threadIdx.x;  // 65536 pairs
    int i = p >> 8;
    int j = p & 255;
    const float* pf = cf + (size_t)i * NFR + j * NF;
    float mf = -1e30f;
#pragma unroll
    for (int f = 0; f < NF; f++) mf = fmaxf(mf, pf[f]);
    const float* pv = cv + (size_t)i * NROWS + j * NS;
    float mv = -1e30f;
#pragma unroll
    for (int v = 0; v < NS; v++) mv = fmaxf(mv, pv[v]);
    out[p]               = mf + mv;
    out[NB * NB + p]     = mf;
    out[2 * NB * NB + p] = mv;
}

// ------------------------- launcher ----------------------------------------
extern "C" void kernel_launch(void* const* d_in, const int* in_sizes, int n_in,
                              void* d_out, int out_size) {
    const float* text  = (const float*)d_in[0];
    const float* fr    = (const float*)d_in[1];
    const float* ex    = (const float*)d_in[2];
    const float* Wqkv  = (const float*)d_in[3];
    const float* bqkv  = (const float*)d_in[4];
    const float* Wo    = (const float*)d_in[5];
    const float* bo    = (const float*)d_in[6];
    const float* ln1w  = (const float*)d_in[7];
    const float* ln1b  = (const float*)d_in[8];
    const float* W1    = (const float*)d_in[9];
    const float* b1    = (const float*)d_in[10];
    const float* W2    = (const float*)d_in[11];
    const float* b2    = (const float*)d_in[12];
    const float* ln2w  = (const float*)d_in[13];
    const float* ln2b  = (const float*)d_in[14];
    float* out = (float*)d_out;

    float *px, *pqkv, *pproj, *pcf, *pcv;
    unsigned *pxh, *pxl, *path, *patl, *pffh, *pffl;
    unsigned *pwqkvh, *pwqkvl, *pwoh, *pwol, *pw1h, *pw1l, *pw2h, *pw2l;
    unsigned *ptnh, *ptnl, *pfnh, *pfnl, *pvnh, *pvnl;
    cudaGetSymbolAddress((void**)&px,     g_x);
    cudaGetSymbolAddress((void**)&pqkv,   g_qkv);
    cudaGetSymbolAddress((void**)&pproj,  g_proj);
    cudaGetSymbolAddress((void**)&pcf,    g_cf);
    cudaGetSymbolAddress((void**)&pcv,    g_cv);
    cudaGetSymbolAddress((void**)&pxh,    g_xh);
    cudaGetSymbolAddress((void**)&pxl,    g_xl);
    cudaGetSymbolAddress((void**)&path,   g_ath);
    cudaGetSymbolAddress((void**)&patl,   g_atl);
    cudaGetSymbolAddress((void**)&pffh,   g_ffh);
    cudaGetSymbolAddress((void**)&pffl,   g_ffl);
    cudaGetSymbolAddress((void**)&pwqkvh, g_wqkvh);
    cudaGetSymbolAddress((void**)&pwqkvl, g_wqkvl);
    cudaGetSymbolAddress((void**)&pwoh,   g_woh);
    cudaGetSymbolAddress((void**)&pwol,   g_wol);
    cudaGetSymbolAddress((void**)&pw1h,   g_w1h);
    cudaGetSymbolAddress((void**)&pw1l,   g_w1l);
    cudaGetSymbolAddress((void**)&pw2h,   g_w2h);
    cudaGetSymbolAddress((void**)&pw2l,   g_w2l);
    cudaGetSymbolAddress((void**)&ptnh,   g_tnh);
    cudaGetSymbolAddress((void**)&ptnl,   g_tnl);
    cudaGetSymbolAddress((void**)&pfnh,   g_fnh);
    cudaGetSymbolAddress((void**)&pfnl,   g_fnl);
    cudaGetSymbolAddress((void**)&pvnh,   g_vnh);
    cudaGetSymbolAddress((void**)&pvnl,   g_vnl);

    cudaFuncSetAttribute(mma_gemm, cudaFuncAttributeMaxDynamicSharedMemorySize, TC_SMEM);

    // weight pre-splits (cheap, memory-bound)
    {
        int nw;
        nw = NL * 3 * DM * DM / 2;
        split_pairs<<<(nw + 255) / 256, 256>>>(Wqkv, pwqkvh, pwqkvl, nw);
        nw = NL * DM * DM / 2;
        split_pairs<<<(nw + 255) / 256, 256>>>(Wo, pwoh, pwol, nw);
        nw = NL * FFD * DM / 2;
        split_pairs<<<(nw + 255) / 256, 256>>>(W1, pw1h, pw1l, nw);
        nw = NL * DM * FFD / 2;
        split_pairs<<<(nw + 255) / 256, 256>>>(W2, pw2h, pw2l, nw);
    }

    build_x_split<<<(NROWS * DM / 2) / 256, 256>>>(fr, ex, px, pxh, pxl);

    for (int l = 0; l < NL; l++) {
        // QKV: [8192,512] x [1536,512]^T -> fp32
        mma_gemm<<<dim3(3 * DM / 128, NROWS / 128), 512, TC_SMEM>>>(
            pxh, pxl,
            pwqkvh + (size_t)l * 3 * DM * DM / 2, pwqkvl + (size_t)l * 3 * DM * DM / 2,
            bqkv + (size_t)l * 3 * DM, pqkv, nullptr, nullptr,
            NROWS, 3 * DM, DM, 0);
        // attention per (batch, head), writes split output
        attn_split<<<dim3(NB, NH), dim3(32, 32)>>>(pqkv, path, patl);
        // O projection -> fp32
        mma_gemm<<<dim3(DM / 128, NROWS / 128), 512, TC_SMEM>>>(
            path, patl,
            pwoh + (size_t)l * DM * DM / 2, pwol + (size_t)l * DM * DM / 2,
            bo + (size_t)l * DM, pproj, nullptr, nullptr,
            NROWS, DM, DM, 0);
        add_ln_split<<<NROWS, 256>>>(px, pproj, ln1w + (size_t)l * DM,
                                     ln1b + (size_t)l * DM, pxh, pxl);
        // FF1 (+ReLU), writes split output directly
        mma_gemm<<<dim3(FFD / 128, NROWS / 128), 512, TC_SMEM>>>(
            pxh, pxl,
            pw1h + (size_t)l * FFD * DM / 2, pw1l + (size_t)l * FFD * DM / 2,
            b1 + (size_t)l * FFD, nullptr, pffh, pffl,
            NROWS, FFD, DM, 1);
        // FF2 -> fp32
        mma_gemm<<<dim3(DM / 128, NROWS / 128), 512, TC_SMEM>>>(
            pffh, pffl,
            pw2h + (size_t)l * DM * FFD / 2, pw2l + (size_t)l * DM * FFD / 2,
            b2 + (size_t)l * DM, pproj, nullptr, nullptr,
            NROWS, DM, FFD, 0);
        add_ln_split<<<NROWS, 256>>>(px, pproj, ln2w + (size_t)l * DM,
                                     ln2b + (size_t)l * DM, pxh, pxl);
    }

    // normalizations (write split operands only)
    l2norm_split<<<NB, 256>>>(text, ptnh, ptnl);
    l2norm_split<<<NFR, 256>>>(fr, pfnh, pfnl);
    l2norm_split<<<NROWS, 256>>>(px, pvnh, pvnl);

    // similarity dot-product GEMMs -> fp32
    mma_gemm<<<dim3(NFR / 128, NB / 128), 512, TC_SMEM>>>(
        ptnh, ptnl, pfnh, pfnl, nullptr, pcf, nullptr, nullptr, NB, NFR, DM, 0);
    mma_gemm<<<dim3(NROWS / 128, NB / 128), 512, TC_SMEM>>>(
        ptnh, ptnl, pvnh, pvnl, nullptr, pcv, nullptr, nullptr, NB, NROWS, DM, 0);

    // MaxSim + write three output matrices
    sim_out_kernel<<<(NB * NB) / 256, 256>>>(pcf, pcv, out);
}

// round 10
// speedup vs baseline: 3.3489x; 1.3069x over previous
#include <cuda_runtime.h>
#include <cuda_fp16.h>
#include <math.h>
#include <stdint.h>

// Problem constants
#define NL 4
#define DM 512
#define NH 8
#define DH 64
#define FFD 2048
#define NB 256
#define NF 30
#define NS 32
#define NROWS (NB*NS)      // 8192
#define NFR   (NB*NF)      // 7680

// GEMM config: CTA tile 128x128, BK=32, 512 threads (16 warps, 4x4),
// warp tile 32x32, 4-stage cp.async pipeline, fp16 (A hi/lo, B single).
#define SSTAGES 4
#define MATB 8192                 // bytes per matrix per stage (128 rows x 64B)
#define STAGEB (3*MATB)           // Ah, Al, Bh
#define TC_SMEM (SSTAGES*STAGEB)  // 98304

// ------------------------- scratch (device globals, no allocs) -------------
__device__ __align__(16) float g_x[NROWS*DM];      // residual stream fp32
__device__ __align__(16) float g_qkv[NROWS*3*DM];  // qkv projection fp32
__device__ __align__(16) float g_proj[NROWS*DM];   // o-proj / ff2 output fp32
__device__ __align__(16) float g_cf[NB*NFR];       // text x frames dots
__device__ __align__(16) float g_cv[NB*NROWS];     // text x video dots

// packed fp16 operand buffers (each unsigned = 2 fp16 along K)
__device__ __align__(16) unsigned g_xh [NROWS*DM/2],  g_xl [NROWS*DM/2];
__device__ __align__(16) unsigned g_ath[NROWS*DM/2],  g_atl[NROWS*DM/2];
__device__ __align__(16) unsigned g_ffh[NROWS*FFD/2], g_ffl[NROWS*FFD/2];
__device__ __align__(16) unsigned g_wqkvh[NL*3*DM*DM/2];
__device__ __align__(16) unsigned g_woh [NL*DM*DM/2];
__device__ __align__(16) unsigned g_w1h [NL*FFD*DM/2];
__device__ __align__(16) unsigned g_w2h [NL*DM*FFD/2];
__device__ __align__(16) unsigned g_tnh[NB*DM/2],   g_tnl[NB*DM/2];
__device__ __align__(16) unsigned g_fnh[NFR*DM/2],  g_fnl[NFR*DM/2];
__device__ __align__(16) unsigned g_vnh[NROWS*DM/2],g_vnl[NROWS*DM/2];

// ------------------------- fp16 hi/lo split helpers ------------------------
__device__ __forceinline__ void split2h(float f0, float f1, unsigned &h, unsigned &l) {
    __half2 hv = __floats2half2_rn(f0, f1);
    h = reinterpret_cast<unsigned&>(hv);
    float r0 = f0 - __half2float(__low2half(hv));
    float r1 = f1 - __half2float(__high2half(hv));
    __half2 lv = __floats2half2_rn(r0, r1);
    l = reinterpret_cast<unsigned&>(lv);
}

__device__ __forceinline__ unsigned cvt2h(float f0, float f1) {
    __half2 hv = __floats2half2_rn(f0, f1);
    return reinterpret_cast<unsigned&>(hv);
}

__device__ __forceinline__ uint32_t smem_u32(const void* p) {
    uint32_t a;
    asm("{ .reg .u64 t; cvta.to.shared.u64 t, %1; cvt.u32.u64 %0, t; }"
        : "=r"(a) : "l"(p));
    return a;
}

#define MMA_F16(d, a, b0, b1) \
    asm volatile("mma.sync.aligned.m16n8k16.row.col.f32.f16.f16.f32 " \
                 "{%0,%1,%2,%3}, {%4,%5,%6,%7}, {%8,%9}, {%0,%1,%2,%3};" \
                 : "+f"(d[0]), "+f"(d[1]), "+f"(d[2]), "+f"(d[3]) \
                 : "r"(a[0]), "r"(a[1]), "r"(a[2]), "r"(a[3]), \
                   "r"(b0), "r"(b1))

#define LDSM4(r, addr) \
    asm volatile("ldmatrix.sync.aligned.m8n8.x4.shared.b16 {%0,%1,%2,%3}, [%4];" \
                 : "=r"((r)[0]), "=r"((r)[1]), "=r"((r)[2]), "=r"((r)[3]) \
                 : "r"(addr))

#define CP_ASYNC16(dst, src) \
    asm volatile("cp.async.cg.shared.global [%0], [%1], 16;" \
                 :: "r"(dst), "l"(src) : "memory")

#define CP_COMMIT() asm volatile("cp.async.commit_group;" ::: "memory")
#define CP_WAIT2()  asm volatile("cp.async.wait_group 2;" ::: "memory")

// ------------------------- fp16x2 mma.sync GEMM ----------------------------
// C[M,N] = A[M,K]*B[N,K]^T (+bias)(relu).
// A pre-split fp16 hi/lo pairs (near-exact); B single fp16.
__global__ __launch_bounds__(512) void mma_gemm(
    const unsigned* __restrict__ Ah, const unsigned* __restrict__ Al,
    const unsigned* __restrict__ Bh,
    const float* __restrict__ bias, float* __restrict__ C,
    unsigned* __restrict__ Ch, unsigned* __restrict__ Cl,
    int M, int N, int K, int relu)
{
    extern __shared__ __align__(16) char dsm[];
    const uint32_t sbase = smem_u32(dsm);

    const int tid  = threadIdx.x;
    const int warp = tid >> 5;
    const int lane = tid & 31;
    const int g = lane >> 2;        // 0..7
    const int t = lane & 3;         // 0..3
    const int wm = (warp & 3) * 32;
    const int wn = (warp >> 2) * 32;
    const int bm = blockIdx.y * 128;
    const int bn = blockIdx.x * 128;

    // ---- cp.async mapping: each thread loads one 16B chunk per matrix -----
    const int lrow = tid >> 2;      // 0..127
    const int lc   = tid & 3;       // 16B chunk within 64B row
    const int Kc16 = K >> 3;        // 16B chunks per global row
    const uint32_t swoff = lrow * 64 + ((lc ^ ((lrow >> 1) & 3)) << 4);

    const char* gAh = (const char*)Ah + ((size_t)(bm + lrow) * Kc16 + lc) * 16;
    const char* gAl = (const char*)Al + ((size_t)(bm + lrow) * Kc16 + lc) * 16;
    const char* gBh = (const char*)Bh + ((size_t)(bn + lrow) * Kc16 + lc) * 16;

    auto load_stage = [&](int chunk, int stage) {
        const size_t go = (size_t)chunk * 64;
        const uint32_t d = sbase + stage * STAGEB + swoff;
        CP_ASYNC16(d,          gAh + go);
        CP_ASYNC16(d + MATB,   gAl + go);
        CP_ASYNC16(d + 2*MATB, gBh + go);
    };

    // ---- ldmatrix base addresses (stage 0, k-step 0) ----------------------
    const int mat  = lane >> 3;     // 0..3
    const int mrow = lane & 7;      // 0..7
    uint32_t aB[2][2], bB[2];       // [term][mt] / [pair]
#pragma unroll
    for (int mt = 0; mt < 2; mt++) {
        const int r = wm + mt * 16 + (mat & 1) * 8 + mrow;
        const uint32_t off = r * 64 + ((((unsigned)mat >> 1) ^ ((r >> 1) & 3)) << 4);
        aB[0][mt] = sbase + off;            // Ah
        aB[1][mt] = sbase + MATB + off;     // Al
    }
#pragma unroll
    for (int p = 0; p < 2; p++) {
        const int r = wn + p * 16 + (mat >> 1) * 8 + mrow;
        const uint32_t off = r * 64 + ((((unsigned)mat & 1) ^ ((r >> 1) & 3)) << 4);
        bB[p] = sbase + 2*MATB + off;       // Bh
    }

    float acc[2][4][4];
#pragma unroll
    for (int mt = 0; mt < 2; mt++)
#pragma unroll
        for (int nt = 0; nt < 4; nt++)
#pragma unroll
            for (int i = 0; i < 4; i++) acc[mt][nt][i] = 0.f;

    auto compute = [&](int stage) {
        const uint32_t so = stage * STAGEB;
#pragma unroll
        for (int s = 0; s < 2; s++) {
            const uint32_t sx = (uint32_t)(s << 5);   // k-step toggles bit5
            unsigned ah[2][4], al[2][4], bh[2][4];
#pragma unroll
            for (int mt = 0; mt < 2; mt++) {
                LDSM4(ah[mt], (aB[0][mt] + so) ^ sx);
                LDSM4(al[mt], (aB[1][mt] + so) ^ sx);
            }
#pragma unroll
            for (int p = 0; p < 2; p++) {
                LDSM4(bh[p], (bB[p] + so) ^ sx);
            }
#pragma unroll
            for (int mt = 0; mt < 2; mt++)
#pragma unroll
                for (int nt = 0; nt < 4; nt++) {
                    const int p = nt >> 1, u = (nt & 1) * 2;
                    MMA_F16(acc[mt][nt], ah[mt], bh[p][u], bh[p][u+1]);
                    MMA_F16(acc[mt][nt], al[mt], bh[p][u], bh[p][u+1]);
                }
        }
    };

    const int NC = K >> 5;          // K/32 chunks

    load_stage(0, 0); CP_COMMIT();
    load_stage(1, 1); CP_COMMIT();
    load_stage(2, 2); CP_COMMIT();

    for (int c = 0; c < NC; c++) {
        CP_WAIT2();
        __syncthreads();
        if (c + 3 < NC) load_stage(c + 3, (c + 3) & 3);
        CP_COMMIT();
        compute(c & 3);
    }

    // ---- epilogue ---------------------------------------------------------
#pragma unroll
    for (int mt = 0; mt < 2; mt++) {
        const int r0 = bm + wm + mt * 16 + g;
#pragma unroll
        for (int nt = 0; nt < 4; nt++) {
            const int c = bn + wn + nt * 8 + 2 * t;
            float b0 = 0.f, b1 = 0.f;
            if (bias) { b0 = __ldg(bias + c); b1 = __ldg(bias + c + 1); }
            float v00 = acc[mt][nt][0] + b0;
            float v01 = acc[mt][nt][1] + b1;
            float v10 = acc[mt][nt][2] + b0;
            float v11 = acc[mt][nt][3] + b1;
            if (relu) {
                v00 = fmaxf(v00, 0.f); v01 = fmaxf(v01, 0.f);
                v10 = fmaxf(v10, 0.f); v11 = fmaxf(v11, 0.f);
            }
            if (Ch) {
                unsigned h, l;
                split2h(v00, v01, h, l);
                size_t wi = ((size_t)r0 * N + c) >> 1;
                Ch[wi] = h; Cl[wi] = l;
                split2h(v10, v11, h, l);
                wi = ((size_t)(r0 + 8) * N + c) >> 1;
                Ch[wi] = h; Cl[wi] = l;
            } else {
                *reinterpret_cast<float2*>(C + (size_t)r0 * N + c) = make_float2(v00, v01);
                *reinterpret_cast<float2*>(C + (size_t)(r0 + 8) * N + c) = make_float2(v10, v11);
            }
        }
    }
}

// ------------------------- fp32 -> single fp16 pre-pass (weights) ----------
__global__ void cvt_pairs(const float* __restrict__ src,
                          unsigned* __restrict__ dh, int nw) {
    int i = blockIdx.x * 256 + threadIdx.x;
    if (i < nw) {
        float2 v = *reinterpret_cast<const float2*>(src + 2 * (size_t)i);
        dh[i] = cvt2h(v.x, v.y);
    }
}

// ------------------------- build x = [frames; expansion] (+split) ----------
__global__ void build_x_split(const float* __restrict__ fr,
                              const float* __restrict__ ex,
                              float* __restrict__ x,
                              unsigned* __restrict__ xh, unsigned* __restrict__ xl) {
    int widx = blockIdx.x * 256 + threadIdx.x;  // over NROWS*256 word-pairs
    int c2 = widx & 255;
    int row = widx >> 8;
    int b = row >> 5;
    int s = row & 31;
    float2 v = (s < NF)
        ? *reinterpret_cast<const float2*>(fr + ((size_t)(b * NF + s) * DM + 2 * c2))
        : *reinterpret_cast<const float2*>(ex + ((size_t)(s - NF) * DM + 2 * c2));
    *reinterpret_cast<float2*>(x + (size_t)row * DM + 2 * c2) = v;
    unsigned h, l;
    split2h(v.x, v.y, h, l);
    xh[widx] = h; xl[widx] = l;
}

// ------------------------- attention (+split epilogue) ---------------------
__global__ __launch_bounds__(1024) void attn_split(const float* __restrict__ qkv,
                                                   unsigned* __restrict__ oh,
                                                   unsigned* __restrict__ ol) {
    const int b = blockIdx.x;
    const int hh = blockIdx.y;
    __shared__ float sq[32][65];
    __shared__ float sk[32][65];
    __shared__ float sv[32][65];
    __shared__ float sp[32][33];
    const int tx = threadIdx.x;   // 0..31
    const int ty = threadIdx.y;   // 0..31

    const float* base = qkv + (size_t)(b * NS + ty) * (3 * DM) + hh * DH;
    sq[ty][tx]      = base[tx];
    sq[ty][tx + 32] = base[tx + 32];
    sk[ty][tx]      = base[DM + tx];
    sk[ty][tx + 32] = base[DM + tx + 32];
    sv[ty][tx]      = base[2 * DM + tx];
    sv[ty][tx + 32] = base[2 * DM + tx + 32];
    __syncthreads();

    float acc = 0.f;
#pragma unroll
    for (int d = 0; d < DH; d++) acc += sq[ty][d] * sk[tx][d];
    acc *= 0.125f; // 1/sqrt(64)

    float m = acc;
#pragma unroll
    for (int o = 16; o; o >>= 1) m = fmaxf(m, __shfl_xor_sync(0xffffffffu, m, o));
    float e = __expf(acc - m);
    float s = e;
#pragma unroll
    for (int o = 16; o; o >>= 1) s += __shfl_xor_sync(0xffffffffu, s, o);
    sp[ty][tx] = e / s;
    __syncthreads();

    float o0 = 0.f, o1 = 0.f;
#pragma unroll
    for (int k = 0; k < NS; k++) {
        float p = sp[ty][k];
        o0 += p * sv[k][2 * tx];
        o1 += p * sv[k][2 * tx + 1];
    }
    unsigned h, l;
    split2h(o0, o1, h, l);
    size_t wi = ((size_t)(b * NS + ty) * DM + hh * DH) / 2 + tx;
    oh[wi] = h; ol[wi] = l;
}

// ------------------------- block reduce (256 threads) ----------------------
__device__ __forceinline__ float block_reduce_256(float v, float* sh) {
    __syncthreads();
    int lane = threadIdx.x & 31, wid = threadIdx.x >> 5;
#pragma unroll
    for (int o = 16; o; o >>= 1) v += __shfl_xor_sync(0xffffffffu, v, o);
    if (lane == 0) sh[wid] = v;
    __syncthreads();
    if (threadIdx.x == 0) {
        float t = 0.f;
#pragma unroll
        for (int w = 0; w < 8; w++) t += sh[w];
        sh[8] = t;
    }
    __syncthreads();
    return sh[8];
}

// ------------------------- x = LayerNorm(x + o) (+split) -------------------
__global__ __launch_bounds__(256) void add_ln_split(float* __restrict__ x,
                                                    const float* __restrict__ o,
                                                    const float* __restrict__ g,
                                                    const float* __restrict__ bt,
                                                    unsigned* __restrict__ xh,
                                                    unsigned* __restrict__ xl) {
    __shared__ float red[16];
    const int row = blockIdx.x;
    const int t = threadIdx.x;   // pair index 0..255
    float2 xv = *reinterpret_cast<const float2*>(x + (size_t)row * DM + 2 * t);
    float2 ov = *reinterpret_cast<const float2*>(o + (size_t)row * DM + 2 * t);
    float v0 = xv.x + ov.x;
    float v1 = xv.y + ov.y;
    float mean = block_reduce_256(v0 + v1, red) * (1.f / DM);
    float d0 = v0 - mean, d1 = v1 - mean;
    float var = block_reduce_256(d0 * d0 + d1 * d1, red) * (1.f / DM);
    float rs = rsqrtf(var + 1e-5f);
    float2 gg = *reinterpret_cast<const float2*>(g + 2 * t);
    float2 bb = *reinterpret_cast<const float2*>(bt + 2 * t);
    float r0 = d0 * rs * gg.x + bb.x;
    float r1 = d1 * rs * gg.y + bb.y;
    *reinterpret_cast<float2*>(x + (size_t)row * DM + 2 * t) = make_float2(r0, r1);
    unsigned h, l;
    split2h(r0, r1, h, l);
    xh[(size_t)row * 256 + t] = h;
    xl[(size_t)row * 256 + t] = l;
}

// ------------------------- row l2 normalize (+split only) ------------------
__global__ __launch_bounds__(256) void l2norm_split(const float* __restrict__ in,
                                                    unsigned* __restrict__ oh,
                                                    unsigned* __restrict__ ol) {
    __shared__ float red[16];
    const int row = blockIdx.x;
    const int t = threadIdx.x;
    float2 v = *reinterpret_cast<const float2*>(in + (size_t)row * DM + 2 * t);
    float ss = block_reduce_256(v.x * v.x + v.y * v.y, red);
    float inv = 1.f / fmaxf(sqrtf(ss), 1e-12f);
    float r0 = v.x * inv, r1 = v.y * inv;
    unsigned h, l;
    split2h(r0, r1, h, l);
    oh[(size_t)row * 256 + t] = h;
    ol[(size_t)row * 256 + t] = l;
}

// ------------------------- MaxSim reduce + output --------------------------
__global__ void sim_out_kernel(const float* __restrict__ cf,
                               const float* __restrict__ cv,
                               float* __restrict__ out) {
    int p = blockIdx.x * 256 + threadIdx.x;  // 65536 pairs
    int i = p >> 8;
    int j = p & 255;
    const float* pf = cf + (size_t)i * NFR + j * NF;
    float mf = -1e30f;
#pragma unroll
    for (int f = 0; f < NF; f++) mf = fmaxf(mf, pf[f]);
    const float* pv = cv + (size_t)i * NROWS + j * NS;
    float mv = -1e30f;
#pragma unroll
    for (int v = 0; v < NS; v++) mv = fmaxf(mv, pv[v]);
    out[p]               = mf + mv;
    out[NB * NB + p]     = mf;
    out[2 * NB * NB + p] = mv;
}

// ------------------------- launcher ----------------------------------------
extern "C" void kernel_launch(void* const* d_in, const int* in_sizes, int n_in,
                              void* d_out, int out_size) {
    const float* text  = (const float*)d_in[0];
    const float* fr    = (const float*)d_in[1];
    const float* ex    = (const float*)d_in[2];
    const float* Wqkv  = (const float*)d_in[3];
    const float* bqkv  = (const float*)d_in[4];
    const float* Wo    = (const float*)d_in[5];
    const float* bo    = (const float*)d_in[6];
    const float* ln1w  = (const float*)d_in[7];
    const float* ln1b  = (const float*)d_in[8];
    const float* W1    = (const float*)d_in[9];
    const float* b1    = (const float*)d_in[10];
    const float* W2    = (const float*)d_in[11];
    const float* b2    = (const float*)d_in[12];
    const float* ln2w  = (const float*)d_in[13];
    const float* ln2b  = (const float*)d_in[14];
    float* out = (float*)d_out;

    float *px, *pqkv, *pproj, *pcf, *pcv;
    unsigned *pxh, *pxl, *path, *patl, *pffh, *pffl;
    unsigned *pwqkvh, *pwoh, *pw1h, *pw2h;
    unsigned *ptnh, *ptnl, *pfnh, *pfnl, *pvnh, *pvnl;
    cudaGetSymbolAddress((void**)&px,     g_x);
    cudaGetSymbolAddress((void**)&pqkv,   g_qkv);
    cudaGetSymbolAddress((void**)&pproj,  g_proj);
    cudaGetSymbolAddress((void**)&pcf,    g_cf);
    cudaGetSymbolAddress((void**)&pcv,    g_cv);
    cudaGetSymbolAddress((void**)&pxh,    g_xh);
    cudaGetSymbolAddress((void**)&pxl,    g_xl);
    cudaGetSymbolAddress((void**)&path,   g_ath);
    cudaGetSymbolAddress((void**)&patl,   g_atl);
    cudaGetSymbolAddress((void**)&pffh,   g_ffh);
    cudaGetSymbolAddress((void**)&pffl,   g_ffl);
    cudaGetSymbolAddress((void**)&pwqkvh, g_wqkvh);
    cudaGetSymbolAddress((void**)&pwoh,   g_woh);
    cudaGetSymbolAddress((void**)&pw1h,   g_w1h);
    cudaGetSymbolAddress((void**)&pw2h,   g_w2h);
    cudaGetSymbolAddress((void**)&ptnh,   g_tnh);
    cudaGetSymbolAddress((void**)&ptnl,   g_tnl);
    cudaGetSymbolAddress((void**)&pfnh,   g_fnh);
    cudaGetSymbolAddress((void**)&pfnl,   g_fnl);
    cudaGetSymbolAddress((void**)&pvnh,   g_vnh);
    cudaGetSymbolAddress((void**)&pvnl,   g_vnl);

    cudaFuncSetAttribute(mma_gemm, cudaFuncAttributeMaxDynamicSharedMemorySize, TC_SMEM);

    // weight conversions (cheap, memory-bound)
    {
        int nw;
        nw = NL * 3 * DM * DM / 2;
        cvt_pairs<<<(nw + 255) / 256, 256>>>(Wqkv, pwqkvh, nw);
        nw = NL * DM * DM / 2;
        cvt_pairs<<<(nw + 255) / 256, 256>>>(Wo, pwoh, nw);
        nw = NL * FFD * DM / 2;
        cvt_pairs<<<(nw + 255) / 256, 256>>>(W1, pw1h, nw);
        nw = NL * DM * FFD / 2;
        cvt_pairs<<<(nw + 255) / 256, 256>>>(W2, pw2h, nw);
    }

    build_x_split<<<(NROWS * DM / 2) / 256, 256>>>(fr, ex, px, pxh, pxl);

    for (int l = 0; l < NL; l++) {
        // QKV: [8192,512] x [1536,512]^T -> fp32
        mma_gemm<<<dim3(3 * DM / 128, NROWS / 128), 512, TC_SMEM>>>(
            pxh, pxl, pwqkvh + (size_t)l * 3 * DM * DM / 2,
            bqkv + (size_t)l * 3 * DM, pqkv, nullptr, nullptr,
            NROWS, 3 * DM, DM, 0);
        // attention per (batch, head), writes split output
        attn_split<<<dim3(NB, NH), dim3(32, 32)>>>(pqkv, path, patl);
        // O projection -> fp32
        mma_gemm<<<dim3(DM / 128, NROWS / 128), 512, TC_SMEM>>>(
            path, patl, pwoh + (size_t)l * DM * DM / 2,
            bo + (size_t)l * DM, pproj, nullptr, nullptr,
            NROWS, DM, DM, 0);
        add_ln_split<<<NROWS, 256>>>(px, pproj, ln1w + (size_t)l * DM,
                                     ln1b + (size_t)l * DM, pxh, pxl);
        // FF1 (+ReLU), writes split output directly
        mma_gemm<<<dim3(FFD / 128, NROWS / 128), 512, TC_SMEM>>>(
            pxh, pxl, pw1h + (size_t)l * FFD * DM / 2,
            b1 + (size_t)l * FFD, nullptr, pffh, pffl,
            NROWS, FFD, DM, 1);
        // FF2 -> fp32
        mma_gemm<<<dim3(DM / 128, NROWS / 128), 512, TC_SMEM>>>(
            pffh, pffl, pw2h + (size_t)l * DM * FFD / 2,
            b2 + (size_t)l * DM, pproj, nullptr, nullptr,
            NROWS, DM, FFD, 0);
        add_ln_split<<<NROWS, 256>>>(px, pproj, ln2w + (size_t)l * DM,
                                     ln2b + (size_t)l * DM, pxh, pxl);
    }

    // normalizations (write split operands only)
    l2norm_split<<<NB, 256>>>(text, ptnh, ptnl);
    l2norm_split<<<NFR, 256>>>(fr, pfnh, pfnl);
    l2norm_split<<<NROWS, 256>>>(px, pvnh, pvnl);

    // similarity dot-product GEMMs -> fp32 (B side = single fp16 hi)
    mma_gemm<<<dim3(NFR / 128, NB / 128), 512, TC_SMEM>>>(
        ptnh, ptnl, pfnh, nullptr, pcf, nullptr, nullptr, NB, NFR, DM, 0);
    mma_gemm<<<dim3(NROWS / 128, NB / 128), 512, TC_SMEM>>>(
        ptnh, ptnl, pvnh, nullptr, pcv, nullptr, nullptr, NB, NROWS, DM, 0);

    // MaxSim + write three output matrices
    sim_out_kernel<<<(NB * NB) / 256, 256>>>(pcf, pcv, out);
}

// round 11
// speedup vs baseline: 4.7951x; 1.4318x over previous
#include <cuda_runtime.h>
#include <cuda_fp16.h>
#include <math.h>
#include <stdint.h>

// Problem constants
#define NL 4
#define DM 512
#define NH 8
#define DH 64
#define FFD 2048
#define NB 256
#define NF 30
#define NS 32
#define NROWS (NB*NS)      // 8192
#define NFR   (NB*NF)      // 7680

// GEMM config: CTA tile 128x128, BK=32, 512 threads (16 warps, 4x4),
// warp tile 32x32, 4-stage cp.async pipeline, fp16.
#define SSTAGES 4
#define MATB 8192                 // bytes per matrix per stage (128 rows x 64B)

// ------------------------- scratch (device globals, no allocs) -------------
__device__ __align__(16) float g_x[NROWS*DM];      // residual stream fp32
__device__ __align__(16) float g_qkv[NROWS*3*DM];  // qkv projection fp32
__device__ __align__(16) float g_proj[NROWS*DM];   // o-proj / ff2 output fp32
__device__ __align__(16) float g_cf[NB*NFR];       // text x frames dots
__device__ __align__(16) float g_cv[NB*NROWS];     // text x video dots

// packed fp16 operand buffers (each unsigned = 2 fp16 along K)
__device__ __align__(16) unsigned g_xh [NROWS*DM/2];
__device__ __align__(16) unsigned g_ath[NROWS*DM/2];
__device__ __align__(16) unsigned g_ffh[NROWS*FFD/2];
__device__ __align__(16) unsigned g_wqkvh[NL*3*DM*DM/2];
__device__ __align__(16) unsigned g_woh [NL*DM*DM/2];
__device__ __align__(16) unsigned g_w1h [NL*FFD*DM/2];
__device__ __align__(16) unsigned g_w2h [NL*DM*FFD/2];
__device__ __align__(16) unsigned g_tnh[NB*DM/2],   g_tnl[NB*DM/2];
__device__ __align__(16) unsigned g_fnh[NFR*DM/2];
__device__ __align__(16) unsigned g_vnh[NROWS*DM/2];

// ------------------------- fp16 helpers ------------------------------------
__device__ __forceinline__ void split2h(float f0, float f1, unsigned &h, unsigned &l) {
    __half2 hv = __floats2half2_rn(f0, f1);
    h = reinterpret_cast<unsigned&>(hv);
    float r0 = f0 - __half2float(__low2half(hv));
    float r1 = f1 - __half2float(__high2half(hv));
    __half2 lv = __floats2half2_rn(r0, r1);
    l = reinterpret_cast<unsigned&>(lv);
}

__device__ __forceinline__ unsigned cvt2h(float f0, float f1) {
    __half2 hv = __floats2half2_rn(f0, f1);
    return reinterpret_cast<unsigned&>(hv);
}

__device__ __forceinline__ uint32_t smem_u32(const void* p) {
    uint32_t a;
    asm("{ .reg .u64 t; cvta.to.shared.u64 t, %1; cvt.u32.u64 %0, t; }"
        : "=r"(a) : "l"(p));
    return a;
}

#define MMA_F16(d, a, b0, b1) \
    asm volatile("mma.sync.aligned.m16n8k16.row.col.f32.f16.f16.f32 " \
                 "{%0,%1,%2,%3}, {%4,%5,%6,%7}, {%8,%9}, {%0,%1,%2,%3};" \
                 : "+f"(d[0]), "+f"(d[1]), "+f"(d[2]), "+f"(d[3]) \
                 : "r"(a[0]), "r"(a[1]), "r"(a[2]), "r"(a[3]), \
                   "r"(b0), "r"(b1))

#define LDSM4(r, addr) \
    asm volatile("ldmatrix.sync.aligned.m8n8.x4.shared.b16 {%0,%1,%2,%3}, [%4];" \
                 : "=r"((r)[0]), "=r"((r)[1]), "=r"((r)[2]), "=r"((r)[3]) \
                 : "r"(addr))

#define CP_ASYNC16(dst, src) \
    asm volatile("cp.async.cg.shared.global [%0], [%1], 16;" \
                 :: "r"(dst), "l"(src) : "memory")

#define CP_COMMIT() asm volatile("cp.async.commit_group;" ::: "memory")
#define CP_WAIT2()  asm volatile("cp.async.wait_group 2;" ::: "memory")

// ------------------------- fp16 mma.sync GEMM ------------------------------
// C[M,N] = A[M,K]*B[N,K]^T (+bias)(relu). B single fp16.
// USE_LO=false: A single fp16 (1 MMA/tile). USE_LO=true: A hi/lo (2 MMA/tile).
template<bool USE_LO>
__global__ __launch_bounds__(512) void mma_gemm(
    const unsigned* __restrict__ Ah, const unsigned* __restrict__ Al,
    const unsigned* __restrict__ Bh,
    const float* __restrict__ bias, float* __restrict__ C,
    unsigned* __restrict__ Ch,
    int M, int N, int K, int relu)
{
    constexpr int NMAT = USE_LO ? 3 : 2;
    constexpr int STAGEB = NMAT * MATB;

    extern __shared__ __align__(16) char dsm[];
    const uint32_t sbase = smem_u32(dsm);

    const int tid  = threadIdx.x;
    const int warp = tid >> 5;
    const int lane = tid & 31;
    const int g = lane >> 2;        // 0..7
    const int t = lane & 3;         // 0..3
    const int wm = (warp & 3) * 32;
    const int wn = (warp >> 2) * 32;
    const int bm = blockIdx.y * 128;
    const int bn = blockIdx.x * 128;

    // ---- cp.async mapping: each thread loads one 16B chunk per matrix -----
    const int lrow = tid >> 2;      // 0..127
    const int lc   = tid & 3;       // 16B chunk within 64B row
    const int Kc16 = K >> 3;        // 16B chunks per global row
    const uint32_t swoff = lrow * 64 + ((lc ^ ((lrow >> 1) & 3)) << 4);

    const char* gAh = (const char*)Ah + ((size_t)(bm + lrow) * Kc16 + lc) * 16;
    const char* gAl = USE_LO ? (const char*)Al + ((size_t)(bm + lrow) * Kc16 + lc) * 16 : nullptr;
    const char* gBh = (const char*)Bh + ((size_t)(bn + lrow) * Kc16 + lc) * 16;

    auto load_stage = [&](int chunk, int stage) {
        const size_t go = (size_t)chunk * 64;
        const uint32_t d = sbase + stage * STAGEB + swoff;
        CP_ASYNC16(d, gAh + go);
        if (USE_LO) CP_ASYNC16(d + MATB, gAl + go);
        CP_ASYNC16(d + (NMAT - 1) * MATB, gBh + go);
    };

    // ---- ldmatrix base addresses (stage 0, k-step 0) ----------------------
    const int mat  = lane >> 3;     // 0..3
    const int mrow = lane & 7;      // 0..7
    uint32_t aB[2][2], bB[2];       // [term][mt] / [pair]
#pragma unroll
    for (int mt = 0; mt < 2; mt++) {
        const int r = wm + mt * 16 + (mat & 1) * 8 + mrow;
        const uint32_t off = r * 64 + ((((unsigned)mat >> 1) ^ ((r >> 1) & 3)) << 4);
        aB[0][mt] = sbase + off;                       // Ah
        if (USE_LO) aB[1][mt] = sbase + MATB + off;    // Al
    }
#pragma unroll
    for (int p = 0; p < 2; p++) {
        const int r = wn + p * 16 + (mat >> 1) * 8 + mrow;
        const uint32_t off = r * 64 + ((((unsigned)mat & 1) ^ ((r >> 1) & 3)) << 4);
        bB[p] = sbase + (NMAT - 1) * MATB + off;       // Bh
    }

    float acc[2][4][4];
#pragma unroll
    for (int mt = 0; mt < 2; mt++)
#pragma unroll
        for (int nt = 0; nt < 4; nt++)
#pragma unroll
            for (int i = 0; i < 4; i++) acc[mt][nt][i] = 0.f;

    auto compute = [&](int stage) {
        const uint32_t so = stage * STAGEB;
#pragma unroll
        for (int s = 0; s < 2; s++) {
            const uint32_t sx = (uint32_t)(s << 5);   // k-step toggles bit5
            unsigned ah[2][4], al[2][4], bh[2][4];
#pragma unroll
            for (int mt = 0; mt < 2; mt++) {
                LDSM4(ah[mt], (aB[0][mt] + so) ^ sx);
                if (USE_LO) LDSM4(al[mt], (aB[1][mt] + so) ^ sx);
            }
#pragma unroll
            for (int p = 0; p < 2; p++) {
                LDSM4(bh[p], (bB[p] + so) ^ sx);
            }
#pragma unroll
            for (int mt = 0; mt < 2; mt++)
#pragma unroll
                for (int nt = 0; nt < 4; nt++) {
                    const int p = nt >> 1, u = (nt & 1) * 2;
                    MMA_F16(acc[mt][nt], ah[mt], bh[p][u], bh[p][u+1]);
                    if (USE_LO)
                        MMA_F16(acc[mt][nt], al[mt], bh[p][u], bh[p][u+1]);
                }
        }
    };

    const int NC = K >> 5;          // K/32 chunks

    load_stage(0, 0); CP_COMMIT();
    load_stage(1, 1); CP_COMMIT();
    load_stage(2, 2); CP_COMMIT();

    for (int c = 0; c < NC; c++) {
        CP_WAIT2();
        __syncthreads();
        if (c + 3 < NC) load_stage(c + 3, (c + 3) & 3);
        CP_COMMIT();
        compute(c & 3);
    }

    // ---- epilogue ---------------------------------------------------------
#pragma unroll
    for (int mt = 0; mt < 2; mt++) {
        const int r0 = bm + wm + mt * 16 + g;
#pragma unroll
        for (int nt = 0; nt < 4; nt++) {
            const int c = bn + wn + nt * 8 + 2 * t;
            float b0 = 0.f, b1 = 0.f;
            if (bias) { b0 = __ldg(bias + c); b1 = __ldg(bias + c + 1); }
            float v00 = acc[mt][nt][0] + b0;
            float v01 = acc[mt][nt][1] + b1;
            float v10 = acc[mt][nt][2] + b0;
            float v11 = acc[mt][nt][3] + b1;
            if (relu) {
                v00 = fmaxf(v00, 0.f); v01 = fmaxf(v01, 0.f);
                v10 = fmaxf(v10, 0.f); v11 = fmaxf(v11, 0.f);
            }
            if (Ch) {
                Ch[((size_t)r0 * N + c) >> 1]       = cvt2h(v00, v01);
                Ch[((size_t)(r0 + 8) * N + c) >> 1] = cvt2h(v10, v11);
            } else {
                *reinterpret_cast<float2*>(C + (size_t)r0 * N + c) = make_float2(v00, v01);
                *reinterpret_cast<float2*>(C + (size_t)(r0 + 8) * N + c) = make_float2(v10, v11);
            }
        }
    }
}

// ------------------------- fp32 -> single fp16 pre-pass (weights) ----------
__global__ void cvt_pairs(const float* __restrict__ src,
                          unsigned* __restrict__ dh, int nw) {
    int i = blockIdx.x * 256 + threadIdx.x;
    if (i < nw) {
        float2 v = *reinterpret_cast<const float2*>(src + 2 * (size_t)i);
        dh[i] = cvt2h(v.x, v.y);
    }
}

// ------------------------- build x = [frames; expansion] (+cvt) ------------
__global__ void build_x_split(const float* __restrict__ fr,
                              const float* __restrict__ ex,
                              float* __restrict__ x,
                              unsigned* __restrict__ xh) {
    int widx = blockIdx.x * 256 + threadIdx.x;  // over NROWS*256 word-pairs
    int c2 = widx & 255;
    int row = widx >> 8;
    int b = row >> 5;
    int s = row & 31;
    float2 v = (s < NF)
        ? *reinterpret_cast<const float2*>(fr + ((size_t)(b * NF + s) * DM + 2 * c2))
        : *reinterpret_cast<const float2*>(ex + ((size_t)(s - NF) * DM + 2 * c2));
    *reinterpret_cast<float2*>(x + (size_t)row * DM + 2 * c2) = v;
    xh[widx] = cvt2h(v.x, v.y);
}

// ------------------------- attention (+cvt epilogue) -----------------------
__global__ __launch_bounds__(1024) void attn_split(const float* __restrict__ qkv,
                                                   unsigned* __restrict__ oh) {
    const int b = blockIdx.x;
    const int hh = blockIdx.y;
    __shared__ float sq[32][65];
    __shared__ float sk[32][65];
    __shared__ float sv[32][65];
    __shared__ float sp[32][33];
    const int tx = threadIdx.x;   // 0..31
    const int ty = threadIdx.y;   // 0..31

    const float* base = qkv + (size_t)(b * NS + ty) * (3 * DM) + hh * DH;
    sq[ty][tx]      = base[tx];
    sq[ty][tx + 32] = base[tx + 32];
    sk[ty][tx]      = base[DM + tx];
    sk[ty][tx + 32] = base[DM + tx + 32];
    sv[ty][tx]      = base[2 * DM + tx];
    sv[ty][tx + 32] = base[2 * DM + tx + 32];
    __syncthreads();

    float acc = 0.f;
#pragma unroll
    for (int d = 0; d < DH; d++) acc += sq[ty][d] * sk[tx][d];
    acc *= 0.125f; // 1/sqrt(64)

    float m = acc;
#pragma unroll
    for (int o = 16; o; o >>= 1) m = fmaxf(m, __shfl_xor_sync(0xffffffffu, m, o));
    float e = __expf(acc - m);
    float s = e;
#pragma unroll
    for (int o = 16; o; o >>= 1) s += __shfl_xor_sync(0xffffffffu, s, o);
    sp[ty][tx] = e / s;
    __syncthreads();

    float o0 = 0.f, o1 = 0.f;
#pragma unroll
    for (int k = 0; k < NS; k++) {
        float p = sp[ty][k];
        o0 += p * sv[k][2 * tx];
        o1 += p * sv[k][2 * tx + 1];
    }
    size_t wi = ((size_t)(b * NS + ty) * DM + hh * DH) / 2 + tx;
    oh[wi] = cvt2h(o0, o1);
}

// ------------------------- block reduce (256 threads) ----------------------
__device__ __forceinline__ float block_reduce_256(float v, float* sh) {
    __syncthreads();
    int lane = threadIdx.x & 31, wid = threadIdx.x >> 5;
#pragma unroll
    for (int o = 16; o; o >>= 1) v += __shfl_xor_sync(0xffffffffu, v, o);
    if (lane == 0) sh[wid] = v;
    __syncthreads();
    if (threadIdx.x == 0) {
        float t = 0.f;
#pragma unroll
        for (int w = 0; w < 8; w++) t += sh[w];
        sh[8] = t;
    }
    __syncthreads();
    return sh[8];
}

// ------------------------- x = LayerNorm(x + o) (+cvt) ---------------------
__global__ __launch_bounds__(256) void add_ln_split(float* __restrict__ x,
                                                    const float* __restrict__ o,
                                                    const float* __restrict__ g,
                                                    const float* __restrict__ bt,
                                                    unsigned* __restrict__ xh) {
    __shared__ float red[16];
    const int row = blockIdx.x;
    const int t = threadIdx.x;   // pair index 0..255
    float2 xv = *reinterpret_cast<const float2*>(x + (size_t)row * DM + 2 * t);
    float2 ov = *reinterpret_cast<const float2*>(o + (size_t)row * DM + 2 * t);
    float v0 = xv.x + ov.x;
    float v1 = xv.y + ov.y;
    float mean = block_reduce_256(v0 + v1, red) * (1.f / DM);
    float d0 = v0 - mean, d1 = v1 - mean;
    float var = block_reduce_256(d0 * d0 + d1 * d1, red) * (1.f / DM);
    float rs = rsqrtf(var + 1e-5f);
    float2 gg = *reinterpret_cast<const float2*>(g + 2 * t);
    float2 bb = *reinterpret_cast<const float2*>(bt + 2 * t);
    float r0 = d0 * rs * gg.x + bb.x;
    float r1 = d1 * rs * gg.y + bb.y;
    *reinterpret_cast<float2*>(x + (size_t)row * DM + 2 * t) = make_float2(r0, r1);
    xh[(size_t)row * 256 + t] = cvt2h(r0, r1);
}

// ------------------------- row l2 normalize (+cvt/split) -------------------
__global__ __launch_bounds__(256) void l2norm_split(const float* __restrict__ in,
                                                    unsigned* __restrict__ oh,
                                                    unsigned* __restrict__ ol) {
    __shared__ float red[16];
    const int row = blockIdx.x;
    const int t = threadIdx.x;
    float2 v = *reinterpret_cast<const float2*>(in + (size_t)row * DM + 2 * t);
    float ss = block_reduce_256(v.x * v.x + v.y * v.y, red);
    float inv = 1.f / fmaxf(sqrtf(ss), 1e-12f);
    float r0 = v.x * inv, r1 = v.y * inv;
    if (ol) {
        unsigned h, l;
        split2h(r0, r1, h, l);
        oh[(size_t)row * 256 + t] = h;
        ol[(size_t)row * 256 + t] = l;
    } else {
        oh[(size_t)row * 256 + t] = cvt2h(r0, r1);
    }
}

// ------------------------- MaxSim reduce + output --------------------------
__global__ void sim_out_kernel(const float* __restrict__ cf,
                               const float* __restrict__ cv,
                               float* __restrict__ out) {
    int p = blockIdx.x * 256 + threadIdx.x;  // 65536 pairs
    int i = p >> 8;
    int j = p & 255;
    const float* pf = cf + (size_t)i * NFR + j * NF;
    float mf = -1e30f;
#pragma unroll
    for (int f = 0; f < NF; f++) mf = fmaxf(mf, pf[f]);
    const float* pv = cv + (size_t)i * NROWS + j * NS;
    float mv = -1e30f;
#pragma unroll
    for (int v = 0; v < NS; v++) mv = fmaxf(mv, pv[v]);
    out[p]               = mf + mv;
    out[NB * NB + p]     = mf;
    out[2 * NB * NB + p] = mv;
}

// ------------------------- launcher ----------------------------------------
#define SMEM1 (SSTAGES * 2 * MATB)   // 65536 (USE_LO=false)
#define SMEM2 (SSTAGES * 3 * MATB)   // 98304 (USE_LO=true)

extern "C" void kernel_launch(void* const* d_in, const int* in_sizes, int n_in,
                              void* d_out, int out_size) {
    const float* text  = (const float*)d_in[0];
    const float* fr    = (const float*)d_in[1];
    const float* ex    = (const float*)d_in[2];
    const float* Wqkv  = (const float*)d_in[3];
    const float* bqkv  = (const float*)d_in[4];
    const float* Wo    = (const float*)d_in[5];
    const float* bo    = (const float*)d_in[6];
    const float* ln1w  = (const float*)d_in[7];
    const float* ln1b  = (const float*)d_in[8];
    const float* W1    = (const float*)d_in[9];
    const float* b1    = (const float*)d_in[10];
    const float* W2    = (const float*)d_in[11];
    const float* b2    = (const float*)d_in[12];
    const float* ln2w  = (const float*)d_in[13];
    const float* ln2b  = (const float*)d_in[14];
    float* out = (float*)d_out;

    float *px, *pqkv, *pproj, *pcf, *pcv;
    unsigned *pxh, *path, *pffh;
    unsigned *pwqkvh, *pwoh, *pw1h, *pw2h;
    unsigned *ptnh, *ptnl, *pfnh, *pvnh;
    cudaGetSymbolAddress((void**)&px,     g_x);
    cudaGetSymbolAddress((void**)&pqkv,   g_qkv);
    cudaGetSymbolAddress((void**)&pproj,  g_proj);
    cudaGetSymbolAddress((void**)&pcf,    g_cf);
    cudaGetSymbolAddress((void**)&pcv,    g_cv);
    cudaGetSymbolAddress((void**)&pxh,    g_xh);
    cudaGetSymbolAddress((void**)&path,   g_ath);
    cudaGetSymbolAddress((void**)&pffh,   g_ffh);
    cudaGetSymbolAddress((void**)&pwqkvh, g_wqkvh);
    cudaGetSymbolAddress((void**)&pwoh,   g_woh);
    cudaGetSymbolAddress((void**)&pw1h,   g_w1h);
    cudaGetSymbolAddress((void**)&pw2h,   g_w2h);
    cudaGetSymbolAddress((void**)&ptnh,   g_tnh);
    cudaGetSymbolAddress((void**)&ptnl,   g_tnl);
    cudaGetSymbolAddress((void**)&pfnh,   g_fnh);
    cudaGetSymbolAddress((void**)&pvnh,   g_vnh);

    cudaFuncSetAttribute(mma_gemm<false>, cudaFuncAttributeMaxDynamicSharedMemorySize, SMEM1);
    cudaFuncSetAttribute(mma_gemm<true>,  cudaFuncAttributeMaxDynamicSharedMemorySize, SMEM2);

    // weight conversions (cheap, memory-bound)
    {
        int nw;
        nw = NL * 3 * DM * DM / 2;
        cvt_pairs<<<(nw + 255) / 256, 256>>>(Wqkv, pwqkvh, nw);
        nw = NL * DM * DM / 2;
        cvt_pairs<<<(nw + 255) / 256, 256>>>(Wo, pwoh, nw);
        nw = NL * FFD * DM / 2;
        cvt_pairs<<<(nw + 255) / 256, 256>>>(W1, pw1h, nw);
        nw = NL * DM * FFD / 2;
        cvt_pairs<<<(nw + 255) / 256, 256>>>(W2, pw2h, nw);
    }

    build_x_split<<<(NROWS * DM / 2) / 256, 256>>>(fr, ex, px, pxh);

    for (int l = 0; l < NL; l++) {
        // QKV: [8192,512] x [1536,512]^T -> fp32
        mma_gemm<false><<<dim3(3 * DM / 128, NROWS / 128), 512, SMEM1>>>(
            pxh, nullptr, pwqkvh + (size_t)l * 3 * DM * DM / 2,
            bqkv + (size_t)l * 3 * DM, pqkv, nullptr,
            NROWS, 3 * DM, DM, 0);
        // attention per (batch, head), writes fp16 output
        attn_split<<<dim3(NB, NH), dim3(32, 32)>>>(pqkv, path);
        // O projection -> fp32
        mma_gemm<false><<<dim3(DM / 128, NROWS / 128), 512, SMEM1>>>(
            path, nullptr, pwoh + (size_t)l * DM * DM / 2,
            bo + (size_t)l * DM, pproj, nullptr,
            NROWS, DM, DM, 0);
        add_ln_split<<<NROWS, 256>>>(px, pproj, ln1w + (size_t)l * DM,
                                     ln1b + (size_t)l * DM, pxh);
        // FF1 (+ReLU), writes fp16 output directly
        mma_gemm<false><<<dim3(FFD / 128, NROWS / 128), 512, SMEM1>>>(
            pxh, nullptr, pw1h + (size_t)l * FFD * DM / 2,
            b1 + (size_t)l * FFD, nullptr, pffh,
            NROWS, FFD, DM, 1);
        // FF2 -> fp32
        mma_gemm<false><<<dim3(DM / 128, NROWS / 128), 512, SMEM1>>>(
            pffh, nullptr, pw2h + (size_t)l * DM * FFD / 2,
            b2 + (size_t)l * DM, pproj, nullptr,
            NROWS, DM, FFD, 0);
        add_ln_split<<<NROWS, 256>>>(px, pproj, ln2w + (size_t)l * DM,
                                     ln2b + (size_t)l * DM, pxh);
    }

    // normalizations (text keeps hi/lo for MaxSim precision)
    l2norm_split<<<NB, 256>>>(text, ptnh, ptnl);
    l2norm_split<<<NFR, 256>>>(fr, pfnh, nullptr);
    l2norm_split<<<NROWS, 256>>>(px, pvnh, nullptr);

    // similarity dot-product GEMMs -> fp32 (text hi/lo, 2-MMA path)
    mma_gemm<true><<<dim3(NFR / 128, NB / 128), 512, SMEM2>>>(
        ptnh, ptnl, pfnh, nullptr, pcf, nullptr, NB, NFR, DM, 0);
    mma_gemm<true><<<dim3(NROWS / 128, NB / 128), 512, SMEM2>>>(
        ptnh, ptnl, pvnh, nullptr, pcv, nullptr, NB, NROWS, DM, 0);

    // MaxSim + write three output matrices
    sim_out_kernel<<<(NB * NB) / 256, 256>>>(pcf, pcv, out);
}

// round 12
// speedup vs baseline: 5.0161x; 1.0461x over previous
#include <cuda_runtime.h>
#include <cuda_fp16.h>
#include <math.h>
#include <stdint.h>

// Problem constants
#define NL 4
#define DM 512
#define NH 8
#define DH 64
#define FFD 2048
#define NB 256
#define NF 30
#define NS 32
#define NROWS (NB*NS)      // 8192
#define NFR   (NB*NF)      // 7680

// GEMM config: CTA tile 128x128, BK=32, 512 threads (16 warps, 4x4),
// warp tile 32x32, 4-stage cp.async pipeline, fp16.
#define SSTAGES 4
#define MATB 8192                 // bytes per matrix per stage (128 rows x 64B)

// ------------------------- scratch (device globals, no allocs) -------------
__device__ __align__(16) float g_x[NROWS*DM];      // residual stream fp32
__device__ __align__(16) float g_proj[NROWS*DM];   // o-proj / ff2 output fp32
__device__ __align__(16) float g_cf[NB*NFR];       // text x frames dots
__device__ __align__(16) float g_cv[NB*NROWS];     // text x video dots

// packed fp16 operand buffers (each unsigned = 2 fp16 along K)
__device__ __align__(16) unsigned g_xh  [NROWS*DM/2];
__device__ __align__(16) unsigned g_qkvh[NROWS*3*DM/2];
__device__ __align__(16) unsigned g_ath [NROWS*DM/2];
__device__ __align__(16) unsigned g_ffh [NROWS*FFD/2];
__device__ __align__(16) unsigned g_wqkvh[NL*3*DM*DM/2];
__device__ __align__(16) unsigned g_woh [NL*DM*DM/2];
__device__ __align__(16) unsigned g_w1h [NL*FFD*DM/2];
__device__ __align__(16) unsigned g_w2h [NL*DM*FFD/2];
__device__ __align__(16) unsigned g_tnh[NB*DM/2],   g_tnl[NB*DM/2];
__device__ __align__(16) unsigned g_fnh[NFR*DM/2];
__device__ __align__(16) unsigned g_vnh[NROWS*DM/2];

// ------------------------- fp16 helpers ------------------------------------
__device__ __forceinline__ void split2h(float f0, float f1, unsigned &h, unsigned &l) {
    __half2 hv = __floats2half2_rn(f0, f1);
    h = reinterpret_cast<unsigned&>(hv);
    float r0 = f0 - __half2float(__low2half(hv));
    float r1 = f1 - __half2float(__high2half(hv));
    __half2 lv = __floats2half2_rn(r0, r1);
    l = reinterpret_cast<unsigned&>(lv);
}

__device__ __forceinline__ unsigned cvt2h(float f0, float f1) {
    __half2 hv = __floats2half2_rn(f0, f1);
    return reinterpret_cast<unsigned&>(hv);
}

__device__ __forceinline__ float2 h2f(unsigned u) {
    __half2 h = reinterpret_cast<__half2&>(u);
    return __half22float2(h);
}

__device__ __forceinline__ uint32_t smem_u32(const void* p) {
    uint32_t a;
    asm("{ .reg .u64 t; cvta.to.shared.u64 t, %1; cvt.u32.u64 %0, t; }"
        : "=r"(a) : "l"(p));
    return a;
}

#define MMA_F16(d, a, b0, b1) \
    asm volatile("mma.sync.aligned.m16n8k16.row.col.f32.f16.f16.f32 " \
                 "{%0,%1,%2,%3}, {%4,%5,%6,%7}, {%8,%9}, {%0,%1,%2,%3};" \
                 : "+f"(d[0]), "+f"(d[1]), "+f"(d[2]), "+f"(d[3]) \
                 : "r"(a[0]), "r"(a[1]), "r"(a[2]), "r"(a[3]), \
                   "r"(b0), "r"(b1))

#define LDSM4(r, addr) \
    asm volatile("ldmatrix.sync.aligned.m8n8.x4.shared.b16 {%0,%1,%2,%3}, [%4];" \
                 : "=r"((r)[0]), "=r"((r)[1]), "=r"((r)[2]), "=r"((r)[3]) \
                 : "r"(addr))

#define CP_ASYNC16(dst, src) \
    asm volatile("cp.async.cg.shared.global [%0], [%1], 16;" \
                 :: "r"(dst), "l"(src) : "memory")

#define CP_COMMIT() asm volatile("cp.async.commit_group;" ::: "memory")
#define CP_WAIT2()  asm volatile("cp.async.wait_group 2;" ::: "memory")

// ------------------------- fp16 mma.sync GEMM ------------------------------
// C[M,N] = A[M,K]*B[N,K]^T (+bias)(relu). B single fp16.
// USE_LO=false: A single fp16 (1 MMA/tile). USE_LO=true: A hi/lo (2 MMA/tile).
template<bool USE_LO>
__global__ __launch_bounds__(512) void mma_gemm(
    const unsigned* __restrict__ Ah, const unsigned* __restrict__ Al,
    const unsigned* __restrict__ Bh,
    const float* __restrict__ bias, float* __restrict__ C,
    unsigned* __restrict__ Ch,
    int M, int N, int K, int relu)
{
    constexpr int NMAT = USE_LO ? 3 : 2;
    constexpr int STAGEB = NMAT * MATB;

    extern __shared__ __align__(16) char dsm[];
    const uint32_t sbase = smem_u32(dsm);

    const int tid  = threadIdx.x;
    const int warp = tid >> 5;
    const int lane = tid & 31;
    const int g = lane >> 2;        // 0..7
    const int t = lane & 3;         // 0..3
    const int wm = (warp & 3) * 32;
    const int wn = (warp >> 2) * 32;
    const int bm = blockIdx.y * 128;
    const int bn = blockIdx.x * 128;

    // ---- cp.async mapping: each thread loads one 16B chunk per matrix -----
    const int lrow = tid >> 2;      // 0..127
    const int lc   = tid & 3;       // 16B chunk within 64B row
    const int Kc16 = K >> 3;        // 16B chunks per global row
    const uint32_t swoff = lrow * 64 + ((lc ^ ((lrow >> 1) & 3)) << 4);

    const char* gAh = (const char*)Ah + ((size_t)(bm + lrow) * Kc16 + lc) * 16;
    const char* gAl = USE_LO ? (const char*)Al + ((size_t)(bm + lrow) * Kc16 + lc) * 16 : nullptr;
    const char* gBh = (const char*)Bh + ((size_t)(bn + lrow) * Kc16 + lc) * 16;

    auto load_stage = [&](int chunk, int stage) {
        const size_t go = (size_t)chunk * 64;
        const uint32_t d = sbase + stage * STAGEB + swoff;
        CP_ASYNC16(d, gAh + go);
        if (USE_LO) CP_ASYNC16(d + MATB, gAl + go);
        CP_ASYNC16(d + (NMAT - 1) * MATB, gBh + go);
    };

    // ---- ldmatrix base addresses (stage 0, k-step 0) ----------------------
    const int mat  = lane >> 3;     // 0..3
    const int mrow = lane & 7;      // 0..7
    uint32_t aB[2][2], bB[2];       // [term][mt] / [pair]
#pragma unroll
    for (int mt = 0; mt < 2; mt++) {
        const int r = wm + mt * 16 + (mat & 1) * 8 + mrow;
        const uint32_t off = r * 64 + ((((unsigned)mat >> 1) ^ ((r >> 1) & 3)) << 4);
        aB[0][mt] = sbase + off;                       // Ah
        if (USE_LO) aB[1][mt] = sbase + MATB + off;    // Al
    }
#pragma unroll
    for (int p = 0; p < 2; p++) {
        const int r = wn + p * 16 + (mat >> 1) * 8 + mrow;
        const uint32_t off = r * 64 + ((((unsigned)mat & 1) ^ ((r >> 1) & 3)) << 4);
        bB[p] = sbase + (NMAT - 1) * MATB + off;       // Bh
    }

    float acc[2][4][4];
#pragma unroll
    for (int mt = 0; mt < 2; mt++)
#pragma unroll
        for (int nt = 0; nt < 4; nt++)
#pragma unroll
            for (int i = 0; i < 4; i++) acc[mt][nt][i] = 0.f;

    auto compute = [&](int stage) {
        const uint32_t so = stage * STAGEB;
#pragma unroll
        for (int s = 0; s < 2; s++) {
            const uint32_t sx = (uint32_t)(s << 5);   // k-step toggles bit5
            unsigned ah[2][4], al[2][4], bh[2][4];
#pragma unroll
            for (int mt = 0; mt < 2; mt++) {
                LDSM4(ah[mt], (aB[0][mt] + so) ^ sx);
                if (USE_LO) LDSM4(al[mt], (aB[1][mt] + so) ^ sx);
            }
#pragma unroll
            for (int p = 0; p < 2; p++) {
                LDSM4(bh[p], (bB[p] + so) ^ sx);
            }
#pragma unroll
            for (int mt = 0; mt < 2; mt++)
#pragma unroll
                for (int nt = 0; nt < 4; nt++) {
                    const int p = nt >> 1, u = (nt & 1) * 2;
                    MMA_F16(acc[mt][nt], ah[mt], bh[p][u], bh[p][u+1]);
                    if (USE_LO)
                        MMA_F16(acc[mt][nt], al[mt], bh[p][u], bh[p][u+1]);
                }
        }
    };

    const int NC = K >> 5;          // K/32 chunks

    load_stage(0, 0); CP_COMMIT();
    load_stage(1, 1); CP_COMMIT();
    load_stage(2, 2); CP_COMMIT();

    for (int c = 0; c < NC; c++) {
        CP_WAIT2();
        __syncthreads();
        if (c + 3 < NC) load_stage(c + 3, (c + 3) & 3);
        CP_COMMIT();
        compute(c & 3);
    }

    // ---- epilogue ---------------------------------------------------------
#pragma unroll
    for (int mt = 0; mt < 2; mt++) {
        const int r0 = bm + wm + mt * 16 + g;
#pragma unroll
        for (int nt = 0; nt < 4; nt++) {
            const int c = bn + wn + nt * 8 + 2 * t;
            float b0 = 0.f, b1 = 0.f;
            if (bias) { b0 = __ldg(bias + c); b1 = __ldg(bias + c + 1); }
            float v00 = acc[mt][nt][0] + b0;
            float v01 = acc[mt][nt][1] + b1;
            float v10 = acc[mt][nt][2] + b0;
            float v11 = acc[mt][nt][3] + b1;
            if (relu) {
                v00 = fmaxf(v00, 0.f); v01 = fmaxf(v01, 0.f);
                v10 = fmaxf(v10, 0.f); v11 = fmaxf(v11, 0.f);
            }
            if (Ch) {
                Ch[((size_t)r0 * N + c) >> 1]       = cvt2h(v00, v01);
                Ch[((size_t)(r0 + 8) * N + c) >> 1] = cvt2h(v10, v11);
            } else {
                *reinterpret_cast<float2*>(C + (size_t)r0 * N + c) = make_float2(v00, v01);
                *reinterpret_cast<float2*>(C + (size_t)(r0 + 8) * N + c) = make_float2(v10, v11);
            }
        }
    }
}

// ------------------------- merged weight conversion ------------------------
// Converts 4 weight regions fp32 -> fp16 pairs, one launch, float4 per thread.
__global__ void cvt_weights(const float* __restrict__ s0, unsigned* __restrict__ d0, int n0,
                            const float* __restrict__ s1, unsigned* __restrict__ d1, int n1,
                            const float* __restrict__ s2, unsigned* __restrict__ d2, int n2,
                            const float* __restrict__ s3, unsigned* __restrict__ d3, int n3) {
    int i = blockIdx.x * 256 + threadIdx.x;   // pair-of-words index (4 floats)
    int lw = i * 2;                            // word offset in concatenated space
    const float* s; unsigned* d;
    if (lw < n0) { s = s0; d = d0; }
    else { lw -= n0;
        if (lw < n1) { s = s1; d = d1; }
        else { lw -= n1;
            if (lw < n2) { s = s2; d = d2; }
            else { lw -= n2; if (lw >= n3) return; s = s3; d = d3; }
        }
    }
    float4 v = *reinterpret_cast<const float4*>(s + (size_t)lw * 2);
    d[lw]     = cvt2h(v.x, v.y);
    d[lw + 1] = cvt2h(v.z, v.w);
}

// ------------------------- build x = [frames; expansion] (+cvt) ------------
__global__ void build_x_split(const float* __restrict__ fr,
                              const float* __restrict__ ex,
                              float* __restrict__ x,
                              unsigned* __restrict__ xh) {
    int i = blockIdx.x * 256 + threadIdx.x;   // over NROWS*128 float4 units
    int c4 = i & 127;
    int row = i >> 7;
    int b = row >> 5;
    int s = row & 31;
    float4 v = (s < NF)
        ? *reinterpret_cast<const float4*>(fr + ((size_t)(b * NF + s) * DM + c4 * 4))
        : *reinterpret_cast<const float4*>(ex + ((size_t)(s - NF) * DM + c4 * 4));
    *reinterpret_cast<float4*>(x + (size_t)row * DM + c4 * 4) = v;
    uint2 u = make_uint2(cvt2h(v.x, v.y), cvt2h(v.z, v.w));
    *reinterpret_cast<uint2*>(xh + (size_t)row * 256 + c4 * 2) = u;
}

// ------------------------- attention (fp16 qkv in, fp16 out) ---------------
__global__ __launch_bounds__(1024) void attn_h(const unsigned* __restrict__ qkvh,
                                               unsigned* __restrict__ oh) {
    const int b = blockIdx.x;
    const int hh = blockIdx.y;
    __shared__ float sq[32][65];
    __shared__ float sk[32][65];
    __shared__ float sv[32][65];
    __shared__ float sp[32][33];
    const int tx = threadIdx.x;   // 0..31
    const int ty = threadIdx.y;   // 0..31

    const size_t wbase = (size_t)(b * NS + ty) * 768 + hh * 32 + tx;
    float2 q2 = h2f(qkvh[wbase]);
    float2 k2 = h2f(qkvh[wbase + 256]);
    float2 v2 = h2f(qkvh[wbase + 512]);
    sq[ty][2 * tx] = q2.x; sq[ty][2 * tx + 1] = q2.y;
    sk[ty][2 * tx] = k2.x; sk[ty][2 * tx + 1] = k2.y;
    sv[ty][2 * tx] = v2.x; sv[ty][2 * tx + 1] = v2.y;
    __syncthreads();

    float acc = 0.f;
#pragma unroll
    for (int d = 0; d < DH; d++) acc += sq[ty][d] * sk[tx][d];
    acc *= 0.125f; // 1/sqrt(64)

    float m = acc;
#pragma unroll
    for (int o = 16; o; o >>= 1) m = fmaxf(m, __shfl_xor_sync(0xffffffffu, m, o));
    float e = __expf(acc - m);
    float s = e;
#pragma unroll
    for (int o = 16; o; o >>= 1) s += __shfl_xor_sync(0xffffffffu, s, o);
    sp[ty][tx] = e / s;
    __syncthreads();

    float o0 = 0.f, o1 = 0.f;
#pragma unroll
    for (int k = 0; k < NS; k++) {
        float p = sp[ty][k];
        o0 += p * sv[k][2 * tx];
        o1 += p * sv[k][2 * tx + 1];
    }
    oh[(size_t)(b * NS + ty) * 256 + hh * 32 + tx] = cvt2h(o0, o1);
}

// ------------------------- warp-per-row LayerNorm (+cvt) -------------------
// x = LayerNorm(x + o)*g + b, writes fp32 x and fp16 xh. 32 rows per block.
__global__ __launch_bounds__(1024) void add_ln_warp(float* __restrict__ x,
                                                    const float* __restrict__ o,
                                                    const float* __restrict__ g,
                                                    const float* __restrict__ bt,
                                                    unsigned* __restrict__ xh) {
    const int w = threadIdx.x >> 5;
    const int lane = threadIdx.x & 31;
    const int row = blockIdx.x * 32 + w;
    float* xr = x + (size_t)row * DM;
    const float* orr = o + (size_t)row * DM;

    float4 v[4];
    float s = 0.f, s2 = 0.f;
#pragma unroll
    for (int i = 0; i < 4; i++) {
        const int e = (lane + 32 * i) * 4;
        float4 a = *reinterpret_cast<const float4*>(xr + e);
        float4 b = *reinterpret_cast<const float4*>(orr + e);
        a.x += b.x; a.y += b.y; a.z += b.z; a.w += b.w;
        v[i] = a;
        s  += a.x + a.y + a.z + a.w;
        s2 += a.x * a.x + a.y * a.y + a.z * a.z + a.w * a.w;
    }
#pragma unroll
    for (int off = 16; off; off >>= 1) {
        s  += __shfl_xor_sync(0xffffffffu, s, off);
        s2 += __shfl_xor_sync(0xffffffffu, s2, off);
    }
    const float mean = s * (1.f / DM);
    const float var = fmaxf(s2 * (1.f / DM) - mean * mean, 0.f);
    const float rs = rsqrtf(var + 1e-5f);

#pragma unroll
    for (int i = 0; i < 4; i++) {
        const int e = (lane + 32 * i) * 4;
        float4 gg = *reinterpret_cast<const float4*>(g + e);
        float4 bb = *reinterpret_cast<const float4*>(bt + e);
        float4 r;
        r.x = (v[i].x - mean) * rs * gg.x + bb.x;
        r.y = (v[i].y - mean) * rs * gg.y + bb.y;
        r.z = (v[i].z - mean) * rs * gg.z + bb.z;
        r.w = (v[i].w - mean) * rs * gg.w + bb.w;
        *reinterpret_cast<float4*>(xr + e) = r;
        uint2 u = make_uint2(cvt2h(r.x, r.y), cvt2h(r.z, r.w));
        *reinterpret_cast<uint2*>(xh + (size_t)row * 256 + e / 2) = u;
    }
}

// ------------------------- warp-per-row l2 normalize (+cvt/split) ----------
__global__ __launch_bounds__(1024) void l2norm_warp(const float* __restrict__ in,
                                                    unsigned* __restrict__ oh,
                                                    unsigned* __restrict__ ol) {
    const int w = threadIdx.x >> 5;
    const int lane = threadIdx.x & 31;
    const int row = blockIdx.x * 32 + w;
    const float* r = in + (size_t)row * DM;

    float4 v[4];
    float ss = 0.f;
#pragma unroll
    for (int i = 0; i < 4; i++) {
        v[i] = *reinterpret_cast<const float4*>(r + (lane + 32 * i) * 4);
        ss += v[i].x * v[i].x + v[i].y * v[i].y + v[i].z * v[i].z + v[i].w * v[i].w;
    }
#pragma unroll
    for (int off = 16; off; off >>= 1)
        ss += __shfl_xor_sync(0xffffffffu, ss, off);
    const float inv = 1.f / fmaxf(sqrtf(ss), 1e-12f);

#pragma unroll
    for (int i = 0; i < 4; i++) {
        const int e = (lane + 32 * i) * 4;
        float f0 = v[i].x * inv, f1 = v[i].y * inv;
        float f2 = v[i].z * inv, f3 = v[i].w * inv;
        if (ol) {
            unsigned h0, l0, h1, l1;
            split2h(f0, f1, h0, l0);
            split2h(f2, f3, h1, l1);
            *reinterpret_cast<uint2*>(oh + (size_t)row * 256 + e / 2) = make_uint2(h0, h1);
            *reinterpret_cast<uint2*>(ol + (size_t)row * 256 + e / 2) = make_uint2(l0, l1);
        } else {
            uint2 u = make_uint2(cvt2h(f0, f1), cvt2h(f2, f3));
            *reinterpret_cast<uint2*>(oh + (size_t)row * 256 + e / 2) = u;
        }
    }
}

// ------------------------- MaxSim reduce + output --------------------------
__global__ void sim_out_kernel(const float* __restrict__ cf,
                               const float* __restrict__ cv,
                               float* __restrict__ out) {
    int p = blockIdx.x * 256 + threadIdx.x;  // 65536 pairs
    int i = p >> 8;
    int j = p & 255;
    const float* pf = cf + (size_t)i * NFR + j * NF;
    float mf = -1e30f;
#pragma unroll
    for (int f = 0; f < NF; f++) mf = fmaxf(mf, pf[f]);
    const float* pv = cv + (size_t)i * NROWS + j * NS;
    float mv = -1e30f;
#pragma unroll
    for (int v = 0; v < NS; v++) mv = fmaxf(mv, pv[v]);
    out[p]               = mf + mv;
    out[NB * NB + p]     = mf;
    out[2 * NB * NB + p] = mv;
}

// ------------------------- launcher ----------------------------------------
#define SMEM1 (SSTAGES * 2 * MATB)   // 65536 (USE_LO=false)
#define SMEM2 (SSTAGES * 3 * MATB)   // 98304 (USE_LO=true)

extern "C" void kernel_launch(void* const* d_in, const int* in_sizes, int n_in,
                              void* d_out, int out_size) {
    const float* text  = (const float*)d_in[0];
    const float* fr    = (const float*)d_in[1];
    const float* ex    = (const float*)d_in[2];
    const float* Wqkv  = (const float*)d_in[3];
    const float* bqkv  = (const float*)d_in[4];
    const float* Wo    = (const float*)d_in[5];
    const float* bo    = (const float*)d_in[6];
    const float* ln1w  = (const float*)d_in[7];
    const float* ln1b  = (const float*)d_in[8];
    const float* W1    = (const float*)d_in[9];
    const float* b1    = (const float*)d_in[10];
    const float* W2    = (const float*)d_in[11];
    const float* b2    = (const float*)d_in[12];
    const float* ln2w  = (const float*)d_in[13];
    const float* ln2b  = (const float*)d_in[14];
    float* out = (float*)d_out;

    float *px, *pproj, *pcf, *pcv;
    unsigned *pxh, *pqkvh, *path, *pffh;
    unsigned *pwqkvh, *pwoh, *pw1h, *pw2h;
    unsigned *ptnh, *ptnl, *pfnh, *pvnh;
    cudaGetSymbolAddress((void**)&px,     g_x);
    cudaGetSymbolAddress((void**)&pproj,  g_proj);
    cudaGetSymbolAddress((void**)&pcf,    g_cf);
    cudaGetSymbolAddress((void**)&pcv,    g_cv);
    cudaGetSymbolAddress((void**)&pxh,    g_xh);
    cudaGetSymbolAddress((void**)&pqkvh,  g_qkvh);
    cudaGetSymbolAddress((void**)&path,   g_ath);
    cudaGetSymbolAddress((void**)&pffh,   g_ffh);
    cudaGetSymbolAddress((void**)&pwqkvh, g_wqkvh);
    cudaGetSymbolAddress((void**)&pwoh,   g_woh);
    cudaGetSymbolAddress((void**)&pw1h,   g_w1h);
    cudaGetSymbolAddress((void**)&pw2h,   g_w2h);
    cudaGetSymbolAddress((void**)&ptnh,   g_tnh);
    cudaGetSymbolAddress((void**)&ptnl,   g_tnl);
    cudaGetSymbolAddress((void**)&pfnh,   g_fnh);
    cudaGetSymbolAddress((void**)&pvnh,   g_vnh);

    cudaFuncSetAttribute(mma_gemm<false>, cudaFuncAttributeMaxDynamicSharedMemorySize, SMEM1);
    cudaFuncSetAttribute(mma_gemm<true>,  cudaFuncAttributeMaxDynamicSharedMemorySize, SMEM2);

    // merged weight conversion (one launch)
    {
        const int n0 = NL * 3 * DM * DM / 2;
        const int n1 = NL * DM * DM / 2;
        const int n2 = NL * FFD * DM / 2;
        const int n3 = NL * DM * FFD / 2;
        const int pairs = (n0 + n1 + n2 + n3) / 2;
        cvt_weights<<<(pairs + 255) / 256, 256>>>(
            Wqkv, pwqkvh, n0, Wo, pwoh, n1, W1, pw1h, n2, W2, pw2h, n3);
    }

    build_x_split<<<(NROWS * DM / 4) / 256, 256>>>(fr, ex, px, pxh);

    for (int l = 0; l < NL; l++) {
        // QKV: [8192,512] x [1536,512]^T -> fp16 directly
        mma_gemm<false><<<dim3(3 * DM / 128, NROWS / 128), 512, SMEM1>>>(
            pxh, nullptr, pwqkvh + (size_t)l * 3 * DM * DM / 2,
            bqkv + (size_t)l * 3 * DM, nullptr, pqkvh,
            NROWS, 3 * DM, DM, 0);
        // attention per (batch, head), fp16 in/out
        attn_h<<<dim3(NB, NH), dim3(32, 32)>>>(pqkvh, path);
        // O projection -> fp32
        mma_gemm<false><<<dim3(DM / 128, NROWS / 128), 512, SMEM1>>>(
            path, nullptr, pwoh + (size_t)l * DM * DM / 2,
            bo + (size_t)l * DM, pproj, nullptr,
            NROWS, DM, DM, 0);
        add_ln_warp<<<NROWS / 32, 1024>>>(px, pproj, ln1w + (size_t)l * DM,
                                          ln1b + (size_t)l * DM, pxh);
        // FF1 (+ReLU), writes fp16 output directly
        mma_gemm<false><<<dim3(FFD / 128, NROWS / 128), 512, SMEM1>>>(
            pxh, nullptr, pw1h + (size_t)l * FFD * DM / 2,
            b1 + (size_t)l * FFD, nullptr, pffh,
            NROWS, FFD, DM, 1);
        // FF2 -> fp32
        mma_gemm<false><<<dim3(DM / 128, NROWS / 128), 512, SMEM1>>>(
            pffh, nullptr, pw2h + (size_t)l * DM * FFD / 2,
            b2 + (size_t)l * DM, pproj, nullptr,
            NROWS, DM, FFD, 0);
        add_ln_warp<<<NROWS / 32, 1024>>>(px, pproj, ln2w + (size_t)l * DM,
                                          ln2b + (size_t)l * DM, pxh);
    }

    // normalizations (text keeps hi/lo for MaxSim precision)
    l2norm_warp<<<NB / 32, 1024>>>(text, ptnh, ptnl);
    l2norm_warp<<<NFR / 32, 1024>>>(fr, pfnh, nullptr);
    l2norm_warp<<<NROWS / 32, 1024>>>(px, pvnh, nullptr);

    // similarity dot-product GEMMs -> fp32 (text hi/lo, 2-MMA path)
    mma_gemm<true><<<dim3(NFR / 128, NB / 128), 512, SMEM2>>>(
        ptnh, ptnl, pfnh, nullptr, pcf, nullptr, NB, NFR, DM, 0);
    mma_gemm<true><<<dim3(NROWS / 128, NB / 128), 512, SMEM2>>>(
        ptnh, ptnl, pvnh, nullptr, pcv, nullptr, NB, NROWS, DM, 0);

    // MaxSim + write three output matrices
    sim_out_kernel<<<(NB * NB) / 256, 256>>>(pcf, pcv, out);
}

// round 13
// speedup vs baseline: 5.0165x; 1.0001x over previous
#include <cuda_runtime.h>
#include <cuda_fp16.h>
#include <math.h>
#include <stdint.h>

// Problem constants
#define NL 4
#define DM 512
#define NH 8
#define DH 64
#define FFD 2048
#define NB 256
#define NF 30
#define NS 32
#define NROWS (NB*NS)      // 8192
#define NFR   (NB*NF)      // 7680

// GEMM config: CTA tile 128x128, BK=32, 512 threads (16 warps, 4x4),
// warp tile 32x32, 4-stage cp.async pipeline, fp16.
#define SSTAGES 4
#define MATB 8192                 // bytes per matrix per stage (128 rows x 64B)

// ------------------------- scratch (device globals, no allocs) -------------
__device__ __align__(16) float g_x[NROWS*DM];      // residual stream fp32
__device__ __align__(16) float g_proj[NROWS*DM];   // o-proj / ff2 output fp32
__device__ __align__(16) float g_cf[NB*NFR];       // text x frames dots
__device__ __align__(16) float g_cv[NB*NROWS];     // text x video dots

// packed fp16 operand buffers (each unsigned = 2 fp16 along K)
__device__ __align__(16) unsigned g_xh  [NROWS*DM/2];
__device__ __align__(16) unsigned g_qkvh[NROWS*3*DM/2];
__device__ __align__(16) unsigned g_ath [NROWS*DM/2];
__device__ __align__(16) unsigned g_ffh [NROWS*FFD/2];
__device__ __align__(16) unsigned g_wqkvh[NL*3*DM*DM/2];
__device__ __align__(16) unsigned g_woh [NL*DM*DM/2];
__device__ __align__(16) unsigned g_w1h [NL*FFD*DM/2];
__device__ __align__(16) unsigned g_w2h [NL*DM*FFD/2];
__device__ __align__(16) unsigned g_tnh[NB*DM/2],   g_tnl[NB*DM/2];
__device__ __align__(16) unsigned g_fnh[NFR*DM/2];
__device__ __align__(16) unsigned g_vnh[NROWS*DM/2];

// ------------------------- fp16 helpers ------------------------------------
__device__ __forceinline__ void split2h(float f0, float f1, unsigned &h, unsigned &l) {
    __half2 hv = __floats2half2_rn(f0, f1);
    h = reinterpret_cast<unsigned&>(hv);
    float r0 = f0 - __half2float(__low2half(hv));
    float r1 = f1 - __half2float(__high2half(hv));
    __half2 lv = __floats2half2_rn(r0, r1);
    l = reinterpret_cast<unsigned&>(lv);
}

__device__ __forceinline__ unsigned cvt2h(float f0, float f1) {
    __half2 hv = __floats2half2_rn(f0, f1);
    return reinterpret_cast<unsigned&>(hv);
}

__device__ __forceinline__ float2 h2f(unsigned u) {
    __half2 h = reinterpret_cast<__half2&>(u);
    return __half22float2(h);
}

__device__ __forceinline__ uint32_t smem_u32(const void* p) {
    uint32_t a;
    asm("{ .reg .u64 t; cvta.to.shared.u64 t, %1; cvt.u32.u64 %0, t; }"
        : "=r"(a) : "l"(p));
    return a;
}

#define MMA_F16(d, a, b0, b1) \
    asm volatile("mma.sync.aligned.m16n8k16.row.col.f32.f16.f16.f32 " \
                 "{%0,%1,%2,%3}, {%4,%5,%6,%7}, {%8,%9}, {%0,%1,%2,%3};" \
                 : "+f"(d[0]), "+f"(d[1]), "+f"(d[2]), "+f"(d[3]) \
                 : "r"(a[0]), "r"(a[1]), "r"(a[2]), "r"(a[3]), \
                   "r"(b0), "r"(b1))

#define LDSM4(r, addr) \
    asm volatile("ldmatrix.sync.aligned.m8n8.x4.shared.b16 {%0,%1,%2,%3}, [%4];" \
                 : "=r"((r)[0]), "=r"((r)[1]), "=r"((r)[2]), "=r"((r)[3]) \
                 : "r"(addr))

#define CP_ASYNC16(dst, src) \
    asm volatile("cp.async.cg.shared.global [%0], [%1], 16;" \
                 :: "r"(dst), "l"(src) : "memory")

#define CP_COMMIT() asm volatile("cp.async.commit_group;" ::: "memory")
#define CP_WAIT2()  asm volatile("cp.async.wait_group 2;" ::: "memory")

// ------------------------- fp16 mma.sync GEMM ------------------------------
// C[M,N] = A[M,K]*B[N,K]^T (+bias)(relu). B single fp16.
// USE_LO=false: A single fp16 (1 MMA/tile). USE_LO=true: A hi/lo (2 MMA/tile).
template<bool USE_LO>
__global__ __launch_bounds__(512) void mma_gemm(
    const unsigned* __restrict__ Ah, const unsigned* __restrict__ Al,
    const unsigned* __restrict__ Bh,
    const float* __restrict__ bias, float* __restrict__ C,
    unsigned* __restrict__ Ch,
    int M, int N, int K, int relu)
{
    constexpr int NMAT = USE_LO ? 3 : 2;
    constexpr int STAGEB = NMAT * MATB;

    extern __shared__ __align__(16) char dsm[];
    const uint32_t sbase = smem_u32(dsm);

    const int tid  = threadIdx.x;
    const int warp = tid >> 5;
    const int lane = tid & 31;
    const int g = lane >> 2;        // 0..7
    const int t = lane & 3;         // 0..3
    const int wm = (warp & 3) * 32;
    const int wn = (warp >> 2) * 32;
    const int bm = blockIdx.y * 128;
    const int bn = blockIdx.x * 128;

    // ---- cp.async mapping: each thread loads one 16B chunk per matrix -----
    const int lrow = tid >> 2;      // 0..127
    const int lc   = tid & 3;       // 16B chunk within 64B row
    const int Kc16 = K >> 3;        // 16B chunks per global row
    const uint32_t swoff = lrow * 64 + ((lc ^ ((lrow >> 1) & 3)) << 4);

    const char* gAh = (const char*)Ah + ((size_t)(bm + lrow) * Kc16 + lc) * 16;
    const char* gAl = USE_LO ? (const char*)Al + ((size_t)(bm + lrow) * Kc16 + lc) * 16 : nullptr;
    const char* gBh = (const char*)Bh + ((size_t)(bn + lrow) * Kc16 + lc) * 16;

    auto load_stage = [&](int chunk, int stage) {
        const size_t go = (size_t)chunk * 64;
        const uint32_t d = sbase + stage * STAGEB + swoff;
        CP_ASYNC16(d, gAh + go);
        if (USE_LO) CP_ASYNC16(d + MATB, gAl + go);
        CP_ASYNC16(d + (NMAT - 1) * MATB, gBh + go);
    };

    // ---- ldmatrix base addresses (stage 0, k-step 0) ----------------------
    const int mat  = lane >> 3;     // 0..3
    const int mrow = lane & 7;      // 0..7
    uint32_t aB[2][2], bB[2];       // [term][mt] / [pair]
#pragma unroll
    for (int mt = 0; mt < 2; mt++) {
        const int r = wm + mt * 16 + (mat & 1) * 8 + mrow;
        const uint32_t off = r * 64 + ((((unsigned)mat >> 1) ^ ((r >> 1) & 3)) << 4);
        aB[0][mt] = sbase + off;                       // Ah
        if (USE_LO) aB[1][mt] = sbase + MATB + off;    // Al
    }
#pragma unroll
    for (int p = 0; p < 2; p++) {
        const int r = wn + p * 16 + (mat >> 1) * 8 + mrow;
        const uint32_t off = r * 64 + ((((unsigned)mat & 1) ^ ((r >> 1) & 3)) << 4);
        bB[p] = sbase + (NMAT - 1) * MATB + off;       // Bh
    }

    float acc[2][4][4];
#pragma unroll
    for (int mt = 0; mt < 2; mt++)
#pragma unroll
        for (int nt = 0; nt < 4; nt++)
#pragma unroll
            for (int i = 0; i < 4; i++) acc[mt][nt][i] = 0.f;

    auto compute = [&](int stage) {
        const uint32_t so = stage * STAGEB;
#pragma unroll
        for (int s = 0; s < 2; s++) {
            const uint32_t sx = (uint32_t)(s << 5);   // k-step toggles bit5
            unsigned ah[2][4], al[2][4], bh[2][4];
#pragma unroll
            for (int mt = 0; mt < 2; mt++) {
                LDSM4(ah[mt], (aB[0][mt] + so) ^ sx);
                if (USE_LO) LDSM4(al[mt], (aB[1][mt] + so) ^ sx);
            }
#pragma unroll
            for (int p = 0; p < 2; p++) {
                LDSM4(bh[p], (bB[p] + so) ^ sx);
            }
#pragma unroll
            for (int mt = 0; mt < 2; mt++)
#pragma unroll
                for (int nt = 0; nt < 4; nt++) {
                    const int p = nt >> 1, u = (nt & 1) * 2;
                    MMA_F16(acc[mt][nt], ah[mt], bh[p][u], bh[p][u+1]);
                    if (USE_LO)
                        MMA_F16(acc[mt][nt], al[mt], bh[p][u], bh[p][u+1]);
                }
        }
    };

    const int NC = K >> 5;          // K/32 chunks

    load_stage(0, 0); CP_COMMIT();
    load_stage(1, 1); CP_COMMIT();
    load_stage(2, 2); CP_COMMIT();

    for (int c = 0; c < NC; c++) {
        CP_WAIT2();
        __syncthreads();
        if (c + 3 < NC) load_stage(c + 3, (c + 3) & 3);
        CP_COMMIT();
        compute(c & 3);
    }

    // ---- epilogue ---------------------------------------------------------
#pragma unroll
    for (int mt = 0; mt < 2; mt++) {
        const int r0 = bm + wm + mt * 16 + g;
#pragma unroll
        for (int nt = 0; nt < 4; nt++) {
            const int c = bn + wn + nt * 8 + 2 * t;
            float b0 = 0.f, b1 = 0.f;
            if (bias) { b0 = __ldg(bias + c); b1 = __ldg(bias + c + 1); }
            float v00 = acc[mt][nt][0] + b0;
            float v01 = acc[mt][nt][1] + b1;
            float v10 = acc[mt][nt][2] + b0;
            float v11 = acc[mt][nt][3] + b1;
            if (relu) {
                v00 = fmaxf(v00, 0.f); v01 = fmaxf(v01, 0.f);
                v10 = fmaxf(v10, 0.f); v11 = fmaxf(v11, 0.f);
            }
            if (Ch) {
                Ch[((size_t)r0 * N + c) >> 1]       = cvt2h(v00, v01);
                Ch[((size_t)(r0 + 8) * N + c) >> 1] = cvt2h(v10, v11);
            } else {
                *reinterpret_cast<float2*>(C + (size_t)r0 * N + c) = make_float2(v00, v01);
                *reinterpret_cast<float2*>(C + (size_t)(r0 + 8) * N + c) = make_float2(v10, v11);
            }
        }
    }
}

// ------------------------- merged weight conversion ------------------------
// Converts 4 weight regions fp32 -> fp16 pairs, one launch, float4 per thread.
__global__ void cvt_weights(const float* __restrict__ s0, unsigned* __restrict__ d0, int n0,
                            const float* __restrict__ s1, unsigned* __restrict__ d1, int n1,
                            const float* __restrict__ s2, unsigned* __restrict__ d2, int n2,
                            const float* __restrict__ s3, unsigned* __restrict__ d3, int n3) {
    int i = blockIdx.x * 256 + threadIdx.x;   // pair-of-words index (4 floats)
    int lw = i * 2;                            // word offset in concatenated space
    const float* s; unsigned* d;
    if (lw < n0) { s = s0; d = d0; }
    else { lw -= n0;
        if (lw < n1) { s = s1; d = d1; }
        else { lw -= n1;
            if (lw < n2) { s = s2; d = d2; }
            else { lw -= n2; if (lw >= n3) return; s = s3; d = d3; }
        }
    }
    float4 v = *reinterpret_cast<const float4*>(s + (size_t)lw * 2);
    d[lw]     = cvt2h(v.x, v.y);
    d[lw + 1] = cvt2h(v.z, v.w);
}

// ------------------------- build x = [frames; expansion] (+cvt) ------------
__global__ void build_x_split(const float* __restrict__ fr,
                              const float* __restrict__ ex,
                              float* __restrict__ x,
                              unsigned* __restrict__ xh) {
    int i = blockIdx.x * 256 + threadIdx.x;   // over NROWS*128 float4 units
    int c4 = i & 127;
    int row = i >> 7;
    int b = row >> 5;
    int s = row & 31;
    float4 v = (s < NF)
        ? *reinterpret_cast<const float4*>(fr + ((size_t)(b * NF + s) * DM + c4 * 4))
        : *reinterpret_cast<const float4*>(ex + ((size_t)(s - NF) * DM + c4 * 4));
    *reinterpret_cast<float4*>(x + (size_t)row * DM + c4 * 4) = v;
    uint2 u = make_uint2(cvt2h(v.x, v.y), cvt2h(v.z, v.w));
    *reinterpret_cast<uint2*>(xh + (size_t)row * 256 + c4 * 2) = u;
}

// ------------------------- attention (fp16 qkv in, fp16 out) ---------------
__global__ __launch_bounds__(1024) void attn_h(const unsigned* __restrict__ qkvh,
                                               unsigned* __restrict__ oh) {
    const int b = blockIdx.x;
    const int hh = blockIdx.y;
    __shared__ float sq[32][65];
    __shared__ float sk[32][65];
    __shared__ float sv[32][65];
    __shared__ float sp[32][33];
    const int tx = threadIdx.x;   // 0..31
    const int ty = threadIdx.y;   // 0..31

    const size_t wbase = (size_t)(b * NS + ty) * 768 + hh * 32 + tx;
    float2 q2 = h2f(qkvh[wbase]);
    float2 k2 = h2f(qkvh[wbase + 256]);
    float2 v2 = h2f(qkvh[wbase + 512]);
    sq[ty][2 * tx] = q2.x; sq[ty][2 * tx + 1] = q2.y;
    sk[ty][2 * tx] = k2.x; sk[ty][2 * tx + 1] = k2.y;
    sv[ty][2 * tx] = v2.x; sv[ty][2 * tx + 1] = v2.y;
    __syncthreads();

    float acc = 0.f;
#pragma unroll
    for (int d = 0; d < DH; d++) acc += sq[ty][d] * sk[tx][d];
    acc *= 0.125f; // 1/sqrt(64)

    float m = acc;
#pragma unroll
    for (int o = 16; o; o >>= 1) m = fmaxf(m, __shfl_xor_sync(0xffffffffu, m, o));
    float e = __expf(acc - m);
    float s = e;
#pragma unroll
    for (int o = 16; o; o >>= 1) s += __shfl_xor_sync(0xffffffffu, s, o);
    sp[ty][tx] = e / s;
    __syncthreads();

    float o0 = 0.f, o1 = 0.f;
#pragma unroll
    for (int k = 0; k < NS; k++) {
        float p = sp[ty][k];
        o0 += p * sv[k][2 * tx];
        o1 += p * sv[k][2 * tx + 1];
    }
    oh[(size_t)(b * NS + ty) * 256 + hh * 32 + tx] = cvt2h(o0, o1);
}

// ------------------------- warp-per-row LayerNorm (+cvt) -------------------
// x = LayerNorm(x + o)*g + b, writes fp32 x and fp16 xh. 32 rows per block.
__global__ __launch_bounds__(1024) void add_ln_warp(float* __restrict__ x,
                                                    const float* __restrict__ o,
                                                    const float* __restrict__ g,
                                                    const float* __restrict__ bt,
                                                    unsigned* __restrict__ xh) {
    const int w = threadIdx.x >> 5;
    const int lane = threadIdx.x & 31;
    const int row = blockIdx.x * 32 + w;
    float* xr = x + (size_t)row * DM;
    const float* orr = o + (size_t)row * DM;

    float4 v[4];
    float s = 0.f, s2 = 0.f;
#pragma unroll
    for (int i = 0; i < 4; i++) {
        const int e = (lane + 32 * i) * 4;
        float4 a = *reinterpret_cast<const float4*>(xr + e);
        float4 b = *reinterpret_cast<const float4*>(orr + e);
        a.x += b.x; a.y += b.y; a.z += b.z; a.w += b.w;
        v[i] = a;
        s  += a.x + a.y + a.z + a.w;
        s2 += a.x * a.x + a.y * a.y + a.z * a.z + a.w * a.w;
    }
#pragma unroll
    for (int off = 16; off; off >>= 1) {
        s  += __shfl_xor_sync(0xffffffffu, s, off);
        s2 += __shfl_xor_sync(0xffffffffu, s2, off);
    }
    const float mean = s * (1.f / DM);
    const float var = fmaxf(s2 * (1.f / DM) - mean * mean, 0.f);
    const float rs = rsqrtf(var + 1e-5f);

#pragma unroll
    for (int i = 0; i < 4; i++) {
        const int e = (lane + 32 * i) * 4;
        float4 gg = *reinterpret_cast<const float4*>(g + e);
        float4 bb = *reinterpret_cast<const float4*>(bt + e);
        float4 r;
        r.x = (v[i].x - mean) * rs * gg.x + bb.x;
        r.y = (v[i].y - mean) * rs * gg.y + bb.y;
        r.z = (v[i].z - mean) * rs * gg.z + bb.z;
        r.w = (v[i].w - mean) * rs * gg.w + bb.w;
        *reinterpret_cast<float4*>(xr + e) = r;
        uint2 u = make_uint2(cvt2h(r.x, r.y), cvt2h(r.z, r.w));
        *reinterpret_cast<uint2*>(xh + (size_t)row * 256 + e / 2) = u;
    }
}

// ------------------------- warp-per-row l2 normalize (+cvt/split) ----------
__global__ __launch_bounds__(1024) void l2norm_warp(const float* __restrict__ in,
                                                    unsigned* __restrict__ oh,
                                                    unsigned* __restrict__ ol) {
    const int w = threadIdx.x >> 5;
    const int lane = threadIdx.x & 31;
    const int row = blockIdx.x * 32 + w;
    const float* r = in + (size_t)row * DM;

    float4 v[4];
    float ss = 0.f;
#pragma unroll
    for (int i = 0; i < 4; i++) {
        v[i] = *reinterpret_cast<const float4*>(r + (lane + 32 * i) * 4);
        ss += v[i].x * v[i].x + v[i].y * v[i].y + v[i].z * v[i].z + v[i].w * v[i].w;
    }
#pragma unroll
    for (int off = 16; off; off >>= 1)
        ss += __shfl_xor_sync(0xffffffffu, ss, off);
    const float inv = 1.f / fmaxf(sqrtf(ss), 1e-12f);

#pragma unroll
    for (int i = 0; i < 4; i++) {
        const int e = (lane + 32 * i) * 4;
        float f0 = v[i].x * inv, f1 = v[i].y * inv;
        float f2 = v[i].z * inv, f3 = v[i].w * inv;
        if (ol) {
            unsigned h0, l0, h1, l1;
            split2h(f0, f1, h0, l0);
            split2h(f2, f3, h1, l1);
            *reinterpret_cast<uint2*>(oh + (size_t)row * 256 + e / 2) = make_uint2(h0, h1);
            *reinterpret_cast<uint2*>(ol + (size_t)row * 256 + e / 2) = make_uint2(l0, l1);
        } else {
            uint2 u = make_uint2(cvt2h(f0, f1), cvt2h(f2, f3));
            *reinterpret_cast<uint2*>(oh + (size_t)row * 256 + e / 2) = u;
        }
    }
}

// ------------------------- MaxSim reduce + output --------------------------
__global__ void sim_out_kernel(const float* __restrict__ cf,
                               const float* __restrict__ cv,
                               float* __restrict__ out) {
    int p = blockIdx.x * 256 + threadIdx.x;  // 65536 pairs
    int i = p >> 8;
    int j = p & 255;
    const float* pf = cf + (size_t)i * NFR + j * NF;
    float mf = -1e30f;
#pragma unroll
    for (int f = 0; f < NF; f++) mf = fmaxf(mf, pf[f]);
    const float* pv = cv + (size_t)i * NROWS + j * NS;
    float mv = -1e30f;
#pragma unroll
    for (int v = 0; v < NS; v++) mv = fmaxf(mv, pv[v]);
    out[p]               = mf + mv;
    out[NB * NB + p]     = mf;
    out[2 * NB * NB + p] = mv;
}

// ------------------------- launcher ----------------------------------------
#define SMEM1 (SSTAGES * 2 * MATB)   // 65536 (USE_LO=false)
#define SMEM2 (SSTAGES * 3 * MATB)   // 98304 (USE_LO=true)

extern "C" void kernel_launch(void* const* d_in, const int* in_sizes, int n_in,
                              void* d_out, int out_size) {
    const float* text  = (const float*)d_in[0];
    const float* fr    = (const float*)d_in[1];
    const float* ex    = (const float*)d_in[2];
    const float* Wqkv  = (const float*)d_in[3];
    const float* bqkv  = (const float*)d_in[4];
    const float* Wo    = (const float*)d_in[5];
    const float* bo    = (const float*)d_in[6];
    const float* ln1w  = (const float*)d_in[7];
    const float* ln1b  = (const float*)d_in[8];
    const float* W1    = (const float*)d_in[9];
    const float* b1    = (const float*)d_in[10];
    const float* W2    = (const float*)d_in[11];
    const float* b2    = (const float*)d_in[12];
    const float* ln2w  = (const float*)d_in[13];
    const float* ln2b  = (const float*)d_in[14];
    float* out = (float*)d_out;

    float *px, *pproj, *pcf, *pcv;
    unsigned *pxh, *pqkvh, *path, *pffh;
    unsigned *pwqkvh, *pwoh, *pw1h, *pw2h;
    unsigned *ptnh, *ptnl, *pfnh, *pvnh;
    cudaGetSymbolAddress((void**)&px,     g_x);
    cudaGetSymbolAddress((void**)&pproj,  g_proj);
    cudaGetSymbolAddress((void**)&pcf,    g_cf);
    cudaGetSymbolAddress((void**)&pcv,    g_cv);
    cudaGetSymbolAddress((void**)&pxh,    g_xh);
    cudaGetSymbolAddress((void**)&pqkvh,  g_qkvh);
    cudaGetSymbolAddress((void**)&path,   g_ath);
    cudaGetSymbolAddress((void**)&pffh,   g_ffh);
    cudaGetSymbolAddress((void**)&pwqkvh, g_wqkvh);
    cudaGetSymbolAddress((void**)&pwoh,   g_woh);
    cudaGetSymbolAddress((void**)&pw1h,   g_w1h);
    cudaGetSymbolAddress((void**)&pw2h,   g_w2h);
    cudaGetSymbolAddress((void**)&ptnh,   g_tnh);
    cudaGetSymbolAddress((void**)&ptnl,   g_tnl);
    cudaGetSymbolAddress((void**)&pfnh,   g_fnh);
    cudaGetSymbolAddress((void**)&pvnh,   g_vnh);

    cudaFuncSetAttribute(mma_gemm<false>, cudaFuncAttributeMaxDynamicSharedMemorySize, SMEM1);
    cudaFuncSetAttribute(mma_gemm<true>,  cudaFuncAttributeMaxDynamicSharedMemorySize, SMEM2);

    // merged weight conversion (one launch)
    {
        const int n0 = NL * 3 * DM * DM / 2;
        const int n1 = NL * DM * DM / 2;
        const int n2 = NL * FFD * DM / 2;
        const int n3 = NL * DM * FFD / 2;
        const int pairs = (n0 + n1 + n2 + n3) / 2;
        cvt_weights<<<(pairs + 255) / 256, 256>>>(
            Wqkv, pwqkvh, n0, Wo, pwoh, n1, W1, pw1h, n2, W2, pw2h, n3);
    }

    build_x_split<<<(NROWS * DM / 4) / 256, 256>>>(fr, ex, px, pxh);

    for (int l = 0; l < NL; l++) {
        // QKV: [8192,512] x [1536,512]^T -> fp16 directly
        mma_gemm<false><<<dim3(3 * DM / 128, NROWS / 128), 512, SMEM1>>>(
            pxh, nullptr, pwqkvh + (size_t)l * 3 * DM * DM / 2,
            bqkv + (size_t)l * 3 * DM, nullptr, pqkvh,
            NROWS, 3 * DM, DM, 0);
        // attention per (batch, head), fp16 in/out
        attn_h<<<dim3(NB, NH), dim3(32, 32)>>>(pqkvh, path);
        // O projection -> fp32
        mma_gemm<false><<<dim3(DM / 128, NROWS / 128), 512, SMEM1>>>(
            path, nullptr, pwoh + (size_t)l * DM * DM / 2,
            bo + (size_t)l * DM, pproj, nullptr,
            NROWS, DM, DM, 0);
        add_ln_warp<<<NROWS / 32, 1024>>>(px, pproj, ln1w + (size_t)l * DM,
                                          ln1b + (size_t)l * DM, pxh);
        // FF1 (+ReLU), writes fp16 output directly
        mma_gemm<false><<<dim3(FFD / 128, NROWS / 128), 512, SMEM1>>>(
            pxh, nullptr, pw1h + (size_t)l * FFD * DM / 2,
            b1 + (size_t)l * FFD, nullptr, pffh,
            NROWS, FFD, DM, 1);
        // FF2 -> fp32
        mma_gemm<false><<<dim3(DM / 128, NROWS / 128), 512, SMEM1>>>(
            pffh, nullptr, pw2h + (size_t)l * DM * FFD / 2,
            b2 + (size_t)l * DM, pproj, nullptr,
            NROWS, DM, FFD, 0);
        add_ln_warp<<<NROWS / 32, 1024>>>(px, pproj, ln2w + (size_t)l * DM,
                                          ln2b + (size_t)l * DM, pxh);
    }

    // normalizations (text keeps hi/lo for MaxSim precision)
    l2norm_warp<<<NB / 32, 1024>>>(text, ptnh, ptnl);
    l2norm_warp<<<NFR / 32, 1024>>>(fr, pfnh, nullptr);
    l2norm_warp<<<NROWS / 32, 1024>>>(px, pvnh, nullptr);

    // similarity dot-product GEMMs -> fp32 (text hi/lo, 2-MMA path)
    mma_gemm<true><<<dim3(NFR / 128, NB / 128), 512, SMEM2>>>(
        ptnh, ptnl, pfnh, nullptr, pcf, nullptr, NB, NFR, DM, 0);
    mma_gemm<true><<<dim3(NROWS / 128, NB / 128), 512, SMEM2>>>(
        ptnh, ptnl, pvnh, nullptr, pcv, nullptr, NB, NROWS, DM, 0);

    // MaxSim + write three output matrices
    sim_out_kernel<<<(NB * NB) / 256, 256>>>(pcf, pcv, out);
}